// round 1
// baseline (speedup 1.0000x reference)
#include <cuda_runtime.h>
#include <cstdint>

// Problem constants (fixed shapes)
#define ND 20000
#define NP 40000
#define EMAX 300000
#define HIDW 256
#define OUTC 64
#define NEG 0.2f

// ---------------- static device scratch (allocation-free rule) ----------------
__device__ float g_xd[2][ND * HIDW];            // drug features ping-pong
__device__ float g_xp[2][NP * HIDW];            // protein features ping-pong
__device__ float g_h[NP * HIDW];                // h_src = x_src @ W scratch (max 40000x256)
__device__ float g_alpha[EMAX * 4];             // per-edge attention (up to 4 heads)
__device__ float g_als[NP * 4];                 // per-node src attention logits
__device__ float g_ald[NP * 4];                 // per-node dst attention logits
__device__ float g_V[HIDW * 4 * 2];             // Vs [256,H] then Vd [256,H]
__device__ int   g_rowptr[3][NP + 1];           // CSR row pointers per edge type
__device__ int   g_srcp[3][EMAX];               // CSR-permuted src indices
__device__ int   g_cnt[NP];                     // counts / scatter offsets

// ---------------- CSR build ----------------
__global__ void k_zero(int* __restrict__ p, int n) {
    int i = blockIdx.x * blockDim.x + threadIdx.x;
    if (i < n) p[i] = 0;
}

__global__ void k_count(const int* __restrict__ dst, int E, int* __restrict__ cnt) {
    int i = blockIdx.x * blockDim.x + threadIdx.x;
    if (i < E) atomicAdd(&cnt[dst[i]], 1);
}

// single-block exclusive scan (n up to 40000)
__global__ void k_scan(const int* __restrict__ cnt, int* __restrict__ rowptr, int n) {
    __shared__ int buf[1024];
    __shared__ int carry_s;
    int t = threadIdx.x;
    if (t == 0) { carry_s = 0; rowptr[0] = 0; }
    __syncthreads();
    for (int base = 0; base < n; base += 1024) {
        int i = base + t;
        int v = (i < n) ? cnt[i] : 0;
        buf[t] = v;
        __syncthreads();
        for (int off = 1; off < 1024; off <<= 1) {
            int x = (t >= off) ? buf[t - off] : 0;
            __syncthreads();
            buf[t] += x;
            __syncthreads();
        }
        int incl = buf[t] + carry_s;
        if (i < n) rowptr[i + 1] = incl;
        __syncthreads();
        if (t == 1023) carry_s = incl;
        __syncthreads();
    }
}

__global__ void k_scatter(const int* __restrict__ src, const int* __restrict__ dst, int E,
                          const int* __restrict__ rowptr, int* __restrict__ off,
                          int* __restrict__ srcp) {
    int i = blockIdx.x * blockDim.x + threadIdx.x;
    if (i < E) {
        int d = dst[i];
        int p = rowptr[d] + atomicAdd(&off[d], 1);
        srcp[p] = src[i];
    }
}

// ---------------- GEMM: C[M,N] = A[M,K] @ B[K,N] (+bias)(+relu) ----------------
// BM=128, BK=16, 256 threads, 8xTN micro-tile. BN/TN: (128,8) or (64,4).
template <int BN, int TN>
__global__ void __launch_bounds__(256) k_gemm(const float* __restrict__ A,
                                              const float* __restrict__ B,
                                              const float* __restrict__ bias,
                                              float* __restrict__ C,
                                              int M, int N, int K, int act) {
    const int BM = 128, BK = 16;
    __shared__ float As[BK][BM + 4];
    __shared__ float Bs[BK][BN];
    int tid = threadIdx.x;
    int bm = blockIdx.x * BM, bn = blockIdx.y * BN;
    int tx = tid & 15, ty = tid >> 4;

    float acc[8][TN];
#pragma unroll
    for (int i = 0; i < 8; i++)
#pragma unroll
        for (int j = 0; j < TN; j++) acc[i][j] = 0.f;

    for (int k0 = 0; k0 < K; k0 += BK) {
#pragma unroll
        for (int r = 0; r < 2; r++) {   // A tile: 128x16 = 512 float4
            int q = tid + r * 256;
            int row = q >> 2, cf4 = q & 3;
            int grow = bm + row;
            float4 v = make_float4(0.f, 0.f, 0.f, 0.f);
            if (grow < M) v = *(const float4*)(A + (size_t)grow * K + k0 + cf4 * 4);
            As[cf4 * 4 + 0][row] = v.x;
            As[cf4 * 4 + 1][row] = v.y;
            As[cf4 * 4 + 2][row] = v.z;
            As[cf4 * 4 + 3][row] = v.w;
        }
#pragma unroll
        for (int r = 0; r < BN / 64; r++) {  // B tile: 16xBN
            int q = tid + r * 256;
            int row = q / (BN / 4), cf4 = q % (BN / 4);
            *(float4*)&Bs[row][cf4 * 4] =
                *(const float4*)(B + (size_t)(k0 + row) * N + bn + cf4 * 4);
        }
        __syncthreads();
#pragma unroll
        for (int k = 0; k < BK; k++) {
            float ra[8], rb[TN];
#pragma unroll
            for (int i = 0; i < 8; i += 4) *(float4*)&ra[i] = *(float4*)&As[k][ty * 8 + i];
#pragma unroll
            for (int j = 0; j < TN; j += 4) *(float4*)&rb[j] = *(float4*)&Bs[k][tx * TN + j];
#pragma unroll
            for (int i = 0; i < 8; i++)
#pragma unroll
                for (int j = 0; j < TN; j++) acc[i][j] = fmaf(ra[i], rb[j], acc[i][j]);
        }
        __syncthreads();
    }
#pragma unroll
    for (int i = 0; i < 8; i++) {
        int grow = bm + ty * 8 + i;
        if (grow >= M) continue;
#pragma unroll
        for (int j = 0; j < TN; j++) {
            int gcol = bn + tx * TN + j;
            float v = acc[i][j];
            if (bias) v += bias[gcol];
            if (act) v = fmaxf(v, 0.f);
            C[(size_t)grow * N + gcol] = v;
        }
    }
}

// ---------------- V[k,h] = sum_c W[k, h*C+c] * a[h*C+c] ----------------
__global__ void k_makeV(const float* __restrict__ W, const float* __restrict__ a,
                        float* __restrict__ V, int H, int C) {
    int k = threadIdx.x;  // 256 threads, K=256
    int N = H * C;
    for (int h = 0; h < H; h++) {
        float s = 0.f;
        for (int c = 0; c < C; c++) s = fmaf(W[(size_t)k * N + h * C + c], a[h * C + c], s);
        V[k * H + h] = s;
    }
}

// ---------------- al[n,h] = x[n,:] @ V[:,h]  (K=256 fixed) ----------------
template <int H>
__global__ void k_al(const float* __restrict__ X, const float* __restrict__ V,
                     float* __restrict__ al, int Nrows) {
    __shared__ float Vs[256 * H];
    for (int i = threadIdx.x; i < 256 * H; i += blockDim.x) Vs[i] = V[i];
    __syncthreads();
    int w = (blockIdx.x * blockDim.x + threadIdx.x) >> 5;
    int lane = threadIdx.x & 31;
    if (w >= Nrows) return;
    float p[H];
#pragma unroll
    for (int h = 0; h < H; h++) p[h] = 0.f;
    const float* xr = X + (size_t)w * 256;
#pragma unroll
    for (int t = 0; t < 8; t++) {
        int k = lane + t * 32;
        float x = xr[k];
#pragma unroll
        for (int h = 0; h < H; h++) p[h] = fmaf(x, Vs[k * H + h], p[h]);
    }
#pragma unroll
    for (int h = 0; h < H; h++) {
#pragma unroll
        for (int o = 16; o; o >>= 1) p[h] += __shfl_xor_sync(0xffffffffu, p[h], o);
    }
    if (lane == 0) {
#pragma unroll
        for (int h = 0; h < H; h++) al[(size_t)w * H + h] = p[h];
    }
}

// ---------------- segment softmax per destination node (warp per dst) ----------------
template <int H>
__global__ void k_softmax(const int* __restrict__ rowptr, const int* __restrict__ srcp,
                          const float* __restrict__ als, const float* __restrict__ ald,
                          float* __restrict__ alpha, int Nd) {
    int w = (blockIdx.x * blockDim.x + threadIdx.x) >> 5;
    int lane = threadIdx.x & 31;
    if (w >= Nd) return;
    int s0 = rowptr[w], s1 = rowptr[w + 1];
    if (s0 == s1) return;
    float ad[H], mx[H];
#pragma unroll
    for (int h = 0; h < H; h++) {
        ad[h] = ald[(size_t)w * H + h];
        mx[h] = __int_as_float(0xff800000u);  // -inf
    }
    for (int j = s0 + lane; j < s1; j += 32) {
        int s = srcp[j];
#pragma unroll
        for (int h = 0; h < H; h++) {
            float e = als[(size_t)s * H + h] + ad[h];
            e = e > 0.f ? e : NEG * e;
            alpha[(size_t)j * H + h] = e;
            mx[h] = fmaxf(mx[h], e);
        }
    }
#pragma unroll
    for (int h = 0; h < H; h++)
#pragma unroll
        for (int o = 16; o; o >>= 1) mx[h] = fmaxf(mx[h], __shfl_xor_sync(0xffffffffu, mx[h], o));
    float sm[H];
#pragma unroll
    for (int h = 0; h < H; h++) sm[h] = 0.f;
    for (int j = s0 + lane; j < s1; j += 32) {
#pragma unroll
        for (int h = 0; h < H; h++) {
            float ex = __expf(alpha[(size_t)j * H + h] - mx[h]);
            alpha[(size_t)j * H + h] = ex;
            sm[h] += ex;
        }
    }
#pragma unroll
    for (int h = 0; h < H; h++) {
#pragma unroll
        for (int o = 16; o; o >>= 1) sm[h] += __shfl_xor_sync(0xffffffffu, sm[h], o);
        sm[h] = 1.f / (sm[h] + 1e-16f);
    }
    for (int j = s0 + lane; j < s1; j += 32) {
#pragma unroll
        for (int h = 0; h < H; h++) alpha[(size_t)j * H + h] *= sm[h];
    }
}

// ---------------- aggregation H=4,C=64 (warp per dst, 256-wide rows) ----------------
__global__ void k_agg4(const int* __restrict__ rowptr, const int* __restrict__ srcp,
                       const float* __restrict__ alpha, const float* __restrict__ hsrc,
                       const float* __restrict__ b1, const float* __restrict__ b2,
                       float* __restrict__ out, int Nd, int accum) {
    int w = (blockIdx.x * blockDim.x + threadIdx.x) >> 5;
    int lane = threadIdx.x & 31;
    if (w >= Nd) return;
    int s0 = rowptr[w], s1 = rowptr[w + 1];
    if (accum && s0 == s1) return;
    int c0 = lane, c1 = lane + 32;  // float4 indices within 64-float4 row
    int hsel = lane >> 4;           // head for c0 is hsel, for c1 is hsel+2
    float4 a0 = make_float4(0.f, 0.f, 0.f, 0.f), a1 = a0;
    for (int j = s0; j < s1; j++) {
        int s = srcp[j];
        float4 al = *(const float4*)(alpha + (size_t)j * 4);
        const float4* hr = (const float4*)(hsrc + (size_t)s * 256);
        float4 v0 = hr[c0], v1 = hr[c1];
        float w0 = hsel ? al.y : al.x;
        float w1 = hsel ? al.w : al.z;
        a0.x = fmaf(v0.x, w0, a0.x); a0.y = fmaf(v0.y, w0, a0.y);
        a0.z = fmaf(v0.z, w0, a0.z); a0.w = fmaf(v0.w, w0, a0.w);
        a1.x = fmaf(v1.x, w1, a1.x); a1.y = fmaf(v1.y, w1, a1.y);
        a1.z = fmaf(v1.z, w1, a1.z); a1.w = fmaf(v1.w, w1, a1.w);
    }
    float4* orow = (float4*)(out + (size_t)w * 256);
    if (accum) {
        float4 o0 = orow[c0], o1 = orow[c1];
        o0.x += a0.x; o0.y += a0.y; o0.z += a0.z; o0.w += a0.w;
        o1.x += a1.x; o1.y += a1.y; o1.z += a1.z; o1.w += a1.w;
        orow[c0] = o0; orow[c1] = o1;
    } else {
        const float4* B1 = (const float4*)b1;
        float4 bb0 = B1[c0], bb1 = B1[c1];
        if (b2) {
            const float4* B2 = (const float4*)b2;
            float4 t0 = B2[c0], t1 = B2[c1];
            bb0.x += t0.x; bb0.y += t0.y; bb0.z += t0.z; bb0.w += t0.w;
            bb1.x += t1.x; bb1.y += t1.y; bb1.z += t1.z; bb1.w += t1.w;
        }
        orow[c0] = make_float4(a0.x + bb0.x, a0.y + bb0.y, a0.z + bb0.z, a0.w + bb0.w);
        orow[c1] = make_float4(a1.x + bb1.x, a1.y + bb1.y, a1.z + bb1.z, a1.w + bb1.w);
    }
}

// ---------------- aggregation H=1,OUT=64 (warp per dst) ----------------
__global__ void k_agg1(const int* __restrict__ rowptr, const int* __restrict__ srcp,
                       const float* __restrict__ alpha, const float* __restrict__ hsrc,
                       const float* __restrict__ b1, const float* __restrict__ b2,
                       float* __restrict__ out, int Nd, int accum) {
    int w = (blockIdx.x * blockDim.x + threadIdx.x) >> 5;
    int lane = threadIdx.x & 31;
    if (w >= Nd) return;
    int s0 = rowptr[w], s1 = rowptr[w + 1];
    if (accum && s0 == s1) return;
    float a0 = 0.f, a1 = 0.f;
    for (int j = s0; j < s1; j++) {
        int s = srcp[j];
        float al = alpha[j];
        const float* hr = hsrc + (size_t)s * 64;
        a0 = fmaf(hr[lane], al, a0);
        a1 = fmaf(hr[lane + 32], al, a1);
    }
    float* orow = out + (size_t)w * 64;
    if (accum) {
        orow[lane] += a0;
        orow[lane + 32] += a1;
    } else {
        float bb0 = b1[lane], bb1 = b1[lane + 32];
        if (b2) { bb0 += b2[lane]; bb1 += b2[lane + 32]; }
        orow[lane] = a0 + bb0;
        orow[lane + 32] = a1 + bb1;
    }
}

// ---------------- elementwise elu ----------------
__global__ void k_elu(float* __restrict__ x, size_t n) {
    size_t i = (size_t)blockIdx.x * blockDim.x + threadIdx.x;
    if (i < n) {
        float v = x[i];
        x[i] = v > 0.f ? v : expm1f(v);
    }
}

// =====================================================================
extern "C" void kernel_launch(void* const* d_in, const int* in_sizes, int n_in,
                              void* d_out, int out_size) {
    const float* x_drug = (const float*)d_in[0];
    const float* x_prot = (const float*)d_in[1];
    const int* srcA[3] = {(const int*)d_in[2], (const int*)d_in[4], (const int*)d_in[6]};
    const int* dstA[3] = {(const int*)d_in[3], (const int*)d_in[5], (const int*)d_in[7]};
    const float* linW_d = (const float*)d_in[8];
    const float* linb_d = (const float*)d_in[9];
    const float* linW_p = (const float*)d_in[10];
    const float* linb_p = (const float*)d_in[11];
    const float* W_hid = (const float*)d_in[12];
    const float* as_hid = (const float*)d_in[13];
    const float* ad_hid = (const float*)d_in[14];
    const float* b_hid = (const float*)d_in[15];
    const float* W_out = (const float*)d_in[16];
    const float* as_out = (const float*)d_in[17];
    const float* ad_out = (const float*)d_in[18];
    const float* b_out = (const float*)d_in[19];
    float* outp = (float*)d_out;

    int E[3] = {in_sizes[2], in_sizes[4], in_sizes[6]};
    int NdT[3] = {NP, ND, NP};

    // scratch pointers
    float *xdb, *xpb, *hb, *alpha, *als, *ald, *V;
    int *rp_base, *sp_base, *cnt;
    cudaGetSymbolAddress((void**)&xdb, g_xd);
    cudaGetSymbolAddress((void**)&xpb, g_xp);
    cudaGetSymbolAddress((void**)&hb, g_h);
    cudaGetSymbolAddress((void**)&alpha, g_alpha);
    cudaGetSymbolAddress((void**)&als, g_als);
    cudaGetSymbolAddress((void**)&ald, g_ald);
    cudaGetSymbolAddress((void**)&V, g_V);
    cudaGetSymbolAddress((void**)&rp_base, g_rowptr);
    cudaGetSymbolAddress((void**)&sp_base, g_srcp);
    cudaGetSymbolAddress((void**)&cnt, g_cnt);

    float* xd[2] = {xdb, xdb + (size_t)ND * HIDW};
    float* xp[2] = {xpb, xpb + (size_t)NP * HIDW};
    int* rowptr[3] = {rp_base, rp_base + (NP + 1), rp_base + 2 * (NP + 1)};
    int* srcp[3] = {sp_base, sp_base + EMAX, sp_base + 2 * EMAX};
    float* Vd = V + HIDW * 4;

    // ---- build CSR per edge type (reused by all layers) ----
    for (int t = 0; t < 3; t++) {
        int nb = (NdT[t] + 255) / 256, eb = (E[t] + 255) / 256;
        k_zero<<<nb, 256>>>(cnt, NdT[t]);
        k_count<<<eb, 256>>>(dstA[t], E[t], cnt);
        k_scan<<<1, 1024>>>(cnt, rowptr[t], NdT[t]);
        k_zero<<<nb, 256>>>(cnt, NdT[t]);
        k_scatter<<<eb, 256>>>(srcA[t], dstA[t], E[t], rowptr[t], cnt, srcp[t]);
    }

    // ---- input projections + relu ----
    {
        dim3 gd((ND + 127) / 128, 2);
        k_gemm<128, 8><<<gd, 256>>>(x_drug, linW_d, linb_d, xd[0], ND, 256, 128, 1);
        dim3 gp((NP + 127) / 128, 2);
        k_gemm<128, 8><<<gp, 256>>>(x_prot, linW_p, linb_p, xp[0], NP, 256, 256, 1);
    }

    int cur = 0, nxt = 1;

    // ---- hidden layers (H=4, C=64) ----
    for (int l = 0; l < 2; l++) {
        // helper macro-ish lambda
        auto run_gat4 = [&](int et, const float* xsrc, int Ns, const float* xdst, int Ndst,
                            int csr, const float* b1, const float* b2, float* ob, int accum) {
            const float* W = W_hid + (size_t)(l * 3 + et) * HIDW * HIDW;
            const float* asr = as_hid + (size_t)(l * 3 + et) * HIDW;
            const float* adr = ad_hid + (size_t)(l * 3 + et) * HIDW;
            k_makeV<<<1, 256>>>(W, asr, V, 4, 64);
            k_makeV<<<1, 256>>>(W, adr, Vd, 4, 64);
            dim3 gg((Ns + 127) / 128, 2);
            k_gemm<128, 8><<<gg, 256>>>(xsrc, W, nullptr, hb, Ns, 256, 256, 0);
            k_al<4><<<(Ns + 7) / 8, 256>>>(xsrc, V, als, Ns);
            k_al<4><<<(Ndst + 7) / 8, 256>>>(xdst, Vd, ald, Ndst);
            k_softmax<4><<<(Ndst + 7) / 8, 256>>>(rowptr[csr], srcp[csr], als, ald, alpha, Ndst);
            k_agg4<<<(Ndst + 7) / 8, 256>>>(rowptr[csr], srcp[csr], alpha, hb, b1, b2, ob, Ndst,
                                            accum);
        };
        const float* b0 = b_hid + (size_t)(l * 3 + 0) * HIDW;
        const float* b1_ = b_hid + (size_t)(l * 3 + 1) * HIDW;
        const float* b2 = b_hid + (size_t)(l * 3 + 2) * HIDW;
        // drug->protein (init protein out with b0+b2)
        run_gat4(0, xd[cur], ND, xp[cur], NP, 0, b0, b2, xp[nxt], 0);
        // protein->protein (accumulate)
        run_gat4(2, xp[cur], NP, xp[cur], NP, 2, nullptr, nullptr, xp[nxt], 1);
        // protein->drug (init drug out with b1)
        run_gat4(1, xp[cur], NP, xd[cur], ND, 1, b1_, nullptr, xd[nxt], 0);
        // elu
        k_elu<<<(unsigned)(((size_t)ND * HIDW + 255) / 256), 256>>>(xd[nxt], (size_t)ND * HIDW);
        k_elu<<<(unsigned)(((size_t)NP * HIDW + 255) / 256), 256>>>(xp[nxt], (size_t)NP * HIDW);
        cur = nxt;
        nxt = 1 - nxt;
    }

    // ---- output layer (H=1, OUT=64) ----
    float* od = outp;                       // [ND, 64]
    float* op = outp + (size_t)ND * OUTC;   // [NP, 64]
    auto run_gat1 = [&](int et, const float* xsrc, int Ns, const float* xdst, int Ndst, int csr,
                        const float* b1, const float* b2, float* ob, int accum) {
        const float* W = W_out + (size_t)et * HIDW * OUTC;
        const float* asr = as_out + (size_t)et * OUTC;
        const float* adr = ad_out + (size_t)et * OUTC;
        k_makeV<<<1, 256>>>(W, asr, V, 1, 64);
        k_makeV<<<1, 256>>>(W, adr, Vd, 1, 64);
        dim3 gg((Ns + 127) / 128, 1);
        k_gemm<64, 4><<<gg, 256>>>(xsrc, W, nullptr, hb, Ns, 64, 256, 0);
        k_al<1><<<(Ns + 7) / 8, 256>>>(xsrc, V, als, Ns);
        k_al<1><<<(Ndst + 7) / 8, 256>>>(xdst, Vd, ald, Ndst);
        k_softmax<1><<<(Ndst + 7) / 8, 256>>>(rowptr[csr], srcp[csr], als, ald, alpha, Ndst);
        k_agg1<<<(Ndst + 7) / 8, 256>>>(rowptr[csr], srcp[csr], alpha, hb, b1, b2, ob, Ndst,
                                        accum);
    };
    // drug->protein: init op with b_out[0]+b_out[2]
    run_gat1(0, xd[cur], ND, xp[cur], NP, 0, b_out + 0 * OUTC, b_out + 2 * OUTC, op, 0);
    // protein->protein: accumulate into op
    run_gat1(2, xp[cur], NP, xp[cur], NP, 2, nullptr, nullptr, op, 1);
    // protein->drug: init od with b_out[1]
    run_gat1(1, xp[cur], NP, xd[cur], ND, 1, b_out + 1 * OUTC, nullptr, od, 0);

    (void)n_in;
    (void)out_size;
}

// round 4
// speedup vs baseline: 1.6569x; 1.6569x over previous
#include <cuda_runtime.h>
#include <cuda_bf16.h>
#include <cstdint>

// Problem constants (fixed shapes)
#define ND 20000
#define NP 40000
#define EMAX 300000
#define HIDW 256
#define OUTC 64
#define NEG 0.2f

// ---------------- static device scratch (allocation-free rule) ----------------
__device__ float g_xd[2][ND * HIDW];
__device__ float g_xp[2][NP * HIDW];
__device__ float g_h[NP * HIDW];
__device__ float g_alpha[EMAX * 4];
__device__ float g_als[NP * 4];
__device__ float g_ald[NP * 4];
__device__ float g_V[HIDW * 4];
__device__ int   g_rowptr[3][NP + 1];
__device__ int   g_srcp[3][EMAX];
__device__ int   g_cnt[NP];
#define WTOT 540672
__device__ __nv_bfloat16 g_whi[WTOT];
__device__ __nv_bfloat16 g_wlo[WTOT];

// ======================= helpers =======================
__device__ __forceinline__ uint32_t smem_u32(const void* p) {
    uint32_t a;
    asm("{ .reg .u64 t; cvta.to.shared.u64 t, %1; cvt.u32.u64 %0, t; }" : "=r"(a) : "l"(p));
    return a;
}
__device__ __forceinline__ void cp_async8(uint32_t dst, const void* src) {
    asm volatile("cp.async.ca.shared.global [%0], [%1], 8;" :: "r"(dst), "l"(src));
}
#define CP_COMMIT() asm volatile("cp.async.commit_group;" ::: "memory")
#define CP_WAIT0()  asm volatile("cp.async.wait_group 0;" ::: "memory")

__device__ __forceinline__ void mma16816(float* c, const uint32_t* a, const uint32_t* b) {
    asm volatile(
        "mma.sync.aligned.m16n8k16.row.col.f32.bf16.bf16.f32 "
        "{%0,%1,%2,%3}, {%4,%5,%6,%7}, {%8,%9}, {%0,%1,%2,%3};"
        : "+f"(c[0]), "+f"(c[1]), "+f"(c[2]), "+f"(c[3])
        : "r"(a[0]), "r"(a[1]), "r"(a[2]), "r"(a[3]), "r"(b[0]), "r"(b[1]));
}

__device__ __forceinline__ uint32_t pack_bf2(float x, float y) {
    __nv_bfloat162 t = __floats2bfloat162_rn(x, y);
    return *reinterpret_cast<uint32_t*>(&t);
}

// ---------------- weight pre-transpose + bf16 split: Bt[n][k] = W[k][n] ----------------
__global__ void k_splitW(const float* __restrict__ W, __nv_bfloat16* __restrict__ hi,
                         __nv_bfloat16* __restrict__ lo, int K, int N) {
    int i = blockIdx.x * 256 + threadIdx.x;
    if (i >= N * K) return;
    int n = i / K, k = i % K;
    float v = W[(size_t)k * N + n];
    __nv_bfloat16 h = __float2bfloat16(v);
    hi[i] = h;
    lo[i] = __float2bfloat16(v - __bfloat162float(h));
}

// ============ mma.sync GEMM: C[M,NT] = A[M,K] @ Bt^T, 3-pass bf16 split ============
// A fp32 row-major [M,K]; Bt pre-split bf16 [NT,K] (K-major). BK=32, BM=128.
// BN: block N tile (128 or 64). 256 threads, warp grid 4(m) x 2(n), warp tile 32 x BN/2.
// HALS: 0 none; 4: als[row,h]=sum_n C*asrc (h=n/64, single writer -> store);
//       1: atomicAdd into pre-zeroed als.
template <int BN, bool BIAS, bool RELU, int HALS>
__global__ void __launch_bounds__(256) k_mma(
    const float* __restrict__ A, const __nv_bfloat16* __restrict__ Bthi,
    const __nv_bfloat16* __restrict__ Btlo, const float* __restrict__ bias,
    const float* __restrict__ asrc, float* __restrict__ C, float* __restrict__ als,
    int M, int K, int NT) {
    extern __shared__ char smem[];
    constexpr int WN = BN / 2;        // warp n width
    constexpr int NTILES = WN / 8;    // n8 tiles per warp
    constexpr int ABUF = 128 * 40 * 2;  // bytes per A half-buffer (hi or lo)
    constexpr int BBUF = BN * 40 * 2;
    constexpr int S_A = 1024;
    constexpr int S_B = S_A + 4 * ABUF;
    // smem: [0,512) bias, [512,1024) asrc, A bufs, B bufs
    float* sBias = (float*)(smem);
    float* sAsrc = (float*)(smem + 512);

    int tid = threadIdx.x;
    int wid = tid >> 5, lane = tid & 31;
    int g = lane >> 2, tg = lane & 3;
    int warp_m = wid & 3, warp_n = wid >> 2;
    int bm = blockIdx.x * 128, bn = blockIdx.y * BN;

    if (BIAS)
        for (int i = tid; i < BN; i += 256) sBias[i] = bias[bn + i];
    if (HALS)
        for (int i = tid; i < BN; i += 256) sAsrc[i] = asrc[bn + i];

    // A global-load mapping: thread -> (row, 16-k-chunk)
    int arow = tid >> 1;
    int akq = (tid & 1) * 16;
    bool aval_base = (bm + arow) < M;

    // B cp.async mapping: 8B chunks (4 bf16)
    constexpr int CH = BN * 8 / 256;  // chunks per thread per half (4 or 2)

    float acc[2][NTILES][4];
#pragma unroll
    for (int mi = 0; mi < 2; mi++)
#pragma unroll
        for (int nt = 0; nt < NTILES; nt++)
#pragma unroll
            for (int q = 0; q < 4; q++) acc[mi][nt][q] = 0.f;

    uint32_t sbase = smem_u32(smem);

    auto loadA = [&](int k0, float4* ar) {
        const float* src = A + (size_t)(bm + arow) * K + k0 + akq;
#pragma unroll
        for (int i = 0; i < 4; i++)
            ar[i] = aval_base ? ((const float4*)src)[i] : make_float4(0.f, 0.f, 0.f, 0.f);
    };
    auto storeA = [&](const float4* ar, int buf) {
        char* dh = smem + S_A + buf * 2 * ABUF;
        char* dl = dh + ABUF;
#pragma unroll
        for (int i = 0; i < 4; i++) {
            float4 f = ar[i];
            __nv_bfloat16 hx = __float2bfloat16(f.x), hy = __float2bfloat16(f.y);
            __nv_bfloat16 hz = __float2bfloat16(f.z), hw = __float2bfloat16(f.w);
            __nv_bfloat162 H01(hx, hy), H23(hz, hw);
            uint32_t h01 = *(uint32_t*)&H01, h23 = *(uint32_t*)&H23;
            uint32_t l01 = pack_bf2(f.x - __bfloat162float(hx), f.y - __bfloat162float(hy));
            uint32_t l23 = pack_bf2(f.z - __bfloat162float(hz), f.w - __bfloat162float(hw));
            int off = (arow * 40 + akq + i * 4) * 2;
            *(uint2*)(dh + off) = make_uint2(h01, h23);
            *(uint2*)(dl + off) = make_uint2(l01, l23);
        }
    };
    auto loadB = [&](int k0, int buf) {
        uint32_t dh = sbase + S_B + buf * 2 * BBUF;
        uint32_t dl = dh + BBUF;
#pragma unroll
        for (int i = 0; i < CH; i++) {
            int c = tid + i * 256;
            int row = c >> 3, kc = c & 7;
            size_t go = (size_t)(bn + row) * K + k0 + kc * 4;
            uint32_t so = row * 80 + kc * 8;
            cp_async8(dh + so, Bthi + go);
            cp_async8(dl + so, Btlo + go);
        }
        CP_COMMIT();
    };
    auto compute = [&](int buf) {
        const char* Ah = smem + S_A + buf * 2 * ABUF;
        const char* Al = Ah + ABUF;
        const char* Bh = smem + S_B + buf * 2 * BBUF;
        const char* Bl = Bh + BBUF;
#pragma unroll
        for (int kk = 0; kk < 32; kk += 16) {
            uint32_t ah[2][4], al[2][4];
#pragma unroll
            for (int mi = 0; mi < 2; mi++) {
                int r0 = warp_m * 32 + mi * 16 + g;
                int kb = kk + tg * 2;
                ah[mi][0] = *(const uint32_t*)(Ah + (r0 * 40 + kb) * 2);
                ah[mi][1] = *(const uint32_t*)(Ah + ((r0 + 8) * 40 + kb) * 2);
                ah[mi][2] = *(const uint32_t*)(Ah + (r0 * 40 + kb + 8) * 2);
                ah[mi][3] = *(const uint32_t*)(Ah + ((r0 + 8) * 40 + kb + 8) * 2);
                al[mi][0] = *(const uint32_t*)(Al + (r0 * 40 + kb) * 2);
                al[mi][1] = *(const uint32_t*)(Al + ((r0 + 8) * 40 + kb) * 2);
                al[mi][2] = *(const uint32_t*)(Al + (r0 * 40 + kb + 8) * 2);
                al[mi][3] = *(const uint32_t*)(Al + ((r0 + 8) * 40 + kb + 8) * 2);
            }
#pragma unroll
            for (int nt = 0; nt < NTILES; nt++) {
                int nr = warp_n * WN + nt * 8 + g;
                int kb = kk + tg * 2;
                uint32_t bh[2], bl[2];
                bh[0] = *(const uint32_t*)(Bh + (nr * 40 + kb) * 2);
                bh[1] = *(const uint32_t*)(Bh + (nr * 40 + kb + 8) * 2);
                bl[0] = *(const uint32_t*)(Bl + (nr * 40 + kb) * 2);
                bl[1] = *(const uint32_t*)(Bl + (nr * 40 + kb + 8) * 2);
#pragma unroll
                for (int mi = 0; mi < 2; mi++) {
                    mma16816(acc[mi][nt], ah[mi], bh);
                    mma16816(acc[mi][nt], ah[mi], bl);
                    mma16816(acc[mi][nt], al[mi], bh);
                }
            }
        }
    };

    // ---- pipeline ----
    int nstages = K / 32;
    float4 ar[4];
    loadA(0, ar);
    loadB(0, 0);
    storeA(ar, 0);
    CP_WAIT0();
    __syncthreads();
    for (int s = 0; s < nstages; s++) {
        int cur = s & 1, nxt = cur ^ 1;
        bool more = (s + 1) < nstages;
        if (more) {
            loadA((s + 1) * 32, ar);
            loadB((s + 1) * 32, nxt);
        }
        compute(cur);
        if (more) storeA(ar, nxt);
        CP_WAIT0();
        __syncthreads();
    }

    // ---- epilogue ----
    float sals[2][2];
    sals[0][0] = sals[0][1] = sals[1][0] = sals[1][1] = 0.f;
#pragma unroll
    for (int mi = 0; mi < 2; mi++) {
        int r0 = bm + warp_m * 32 + mi * 16 + g;
        int r1 = r0 + 8;
#pragma unroll
        for (int nt = 0; nt < NTILES; nt++) {
            int nloc = warp_n * WN + nt * 8 + tg * 2;
            int n0 = bn + nloc;
            float* cc = acc[mi][nt];
            float v00 = cc[0], v01 = cc[1], v10 = cc[2], v11 = cc[3];
            if (BIAS) {
                v00 += sBias[nloc]; v01 += sBias[nloc + 1];
                v10 += sBias[nloc]; v11 += sBias[nloc + 1];
            }
            if (RELU) {
                v00 = fmaxf(v00, 0.f); v01 = fmaxf(v01, 0.f);
                v10 = fmaxf(v10, 0.f); v11 = fmaxf(v11, 0.f);
            }
            if (r0 < M) *(float2*)(C + (size_t)r0 * NT + n0) = make_float2(v00, v01);
            if (r1 < M) *(float2*)(C + (size_t)r1 * NT + n0) = make_float2(v10, v11);
            if (HALS) {
                float a0 = sAsrc[nloc], a1 = sAsrc[nloc + 1];
                sals[mi][0] += v00 * a0 + v01 * a1;
                sals[mi][1] += v10 * a0 + v11 * a1;
            }
        }
    }
    if (HALS) {
#pragma unroll
        for (int mi = 0; mi < 2; mi++)
#pragma unroll
            for (int hf = 0; hf < 2; hf++) {
                float s = sals[mi][hf];
                s += __shfl_xor_sync(0xffffffffu, s, 1);
                s += __shfl_xor_sync(0xffffffffu, s, 2);
                if (tg == 0) {
                    int r = bm + warp_m * 32 + mi * 16 + g + hf * 8;
                    if (r < M) {
                        if (HALS == 4) {
                            int h = blockIdx.y * 2 + warp_n;
                            als[(size_t)r * 4 + h] = s;
                        } else {
                            atomicAdd(&als[r], s);
                        }
                    }
                }
            }
    }
}

// ---------------- CSR build ----------------
__global__ void k_zero(int* __restrict__ p, int n) {
    int i = blockIdx.x * blockDim.x + threadIdx.x;
    if (i < n) p[i] = 0;
}
__global__ void k_count(const int* __restrict__ dst, int E, int* __restrict__ cnt) {
    int i = blockIdx.x * blockDim.x + threadIdx.x;
    if (i < E) atomicAdd(&cnt[dst[i]], 1);
}
__global__ void k_scan(const int* __restrict__ cnt, int* __restrict__ rowptr, int n) {
    __shared__ int buf[1024];
    __shared__ int carry_s;
    int t = threadIdx.x;
    if (t == 0) { carry_s = 0; rowptr[0] = 0; }
    __syncthreads();
    for (int base = 0; base < n; base += 1024) {
        int i = base + t;
        int v = (i < n) ? cnt[i] : 0;
        buf[t] = v;
        __syncthreads();
        for (int off = 1; off < 1024; off <<= 1) {
            int x = (t >= off) ? buf[t - off] : 0;
            __syncthreads();
            buf[t] += x;
            __syncthreads();
        }
        int incl = buf[t] + carry_s;
        if (i < n) rowptr[i + 1] = incl;
        __syncthreads();
        if (t == 1023) carry_s = incl;
        __syncthreads();
    }
}
__global__ void k_scatter(const int* __restrict__ src, const int* __restrict__ dst, int E,
                          const int* __restrict__ rowptr, int* __restrict__ off,
                          int* __restrict__ srcp) {
    int i = blockIdx.x * blockDim.x + threadIdx.x;
    if (i < E) {
        int d = dst[i];
        int p = rowptr[d] + atomicAdd(&off[d], 1);
        srcp[p] = src[i];
    }
}

// ---------------- V[k,h] = sum_c W[k, h*C+c] * a[h*C+c] ----------------
__global__ void k_makeV(const float* __restrict__ W, const float* __restrict__ a,
                        float* __restrict__ V, int H, int C) {
    int k = threadIdx.x;
    int N = H * C;
    for (int h = 0; h < H; h++) {
        float s = 0.f;
        for (int c = 0; c < C; c++) s = fmaf(W[(size_t)k * N + h * C + c], a[h * C + c], s);
        V[k * H + h] = s;
    }
}

// ---------------- al[n,h] = x[n,:] @ V[:,h] (K=256 fixed) ----------------
template <int H>
__global__ void k_al(const float* __restrict__ X, const float* __restrict__ V,
                     float* __restrict__ al, int Nrows) {
    __shared__ float Vs[256 * H];
    for (int i = threadIdx.x; i < 256 * H; i += blockDim.x) Vs[i] = V[i];
    __syncthreads();
    int w = (blockIdx.x * blockDim.x + threadIdx.x) >> 5;
    int lane = threadIdx.x & 31;
    if (w >= Nrows) return;
    float p[H];
#pragma unroll
    for (int h = 0; h < H; h++) p[h] = 0.f;
    const float* xr = X + (size_t)w * 256;
#pragma unroll
    for (int t = 0; t < 8; t++) {
        int k = lane + t * 32;
        float x = xr[k];
#pragma unroll
        for (int h = 0; h < H; h++) p[h] = fmaf(x, Vs[k * H + h], p[h]);
    }
#pragma unroll
    for (int h = 0; h < H; h++) {
#pragma unroll
        for (int o = 16; o; o >>= 1) p[h] += __shfl_xor_sync(0xffffffffu, p[h], o);
    }
    if (lane == 0) {
#pragma unroll
        for (int h = 0; h < H; h++) al[(size_t)w * H + h] = p[h];
    }
}

// ---------------- segment softmax per destination node (warp per dst) ----------------
template <int H>
__global__ void k_softmax(const int* __restrict__ rowptr, const int* __restrict__ srcp,
                          const float* __restrict__ als, const float* __restrict__ ald,
                          float* __restrict__ alpha, int Nd) {
    int w = (blockIdx.x * blockDim.x + threadIdx.x) >> 5;
    int lane = threadIdx.x & 31;
    if (w >= Nd) return;
    int s0 = rowptr[w], s1 = rowptr[w + 1];
    if (s0 == s1) return;
    float ad[H], mx[H];
#pragma unroll
    for (int h = 0; h < H; h++) {
        ad[h] = ald[(size_t)w * H + h];
        mx[h] = __int_as_float(0xff800000u);
    }
    for (int j = s0 + lane; j < s1; j += 32) {
        int s = srcp[j];
#pragma unroll
        for (int h = 0; h < H; h++) {
            float e = als[(size_t)s * H + h] + ad[h];
            e = e > 0.f ? e : NEG * e;
            alpha[(size_t)j * H + h] = e;
            mx[h] = fmaxf(mx[h], e);
        }
    }
#pragma unroll
    for (int h = 0; h < H; h++)
#pragma unroll
        for (int o = 16; o; o >>= 1) mx[h] = fmaxf(mx[h], __shfl_xor_sync(0xffffffffu, mx[h], o));
    float sm[H];
#pragma unroll
    for (int h = 0; h < H; h++) sm[h] = 0.f;
    for (int j = s0 + lane; j < s1; j += 32) {
#pragma unroll
        for (int h = 0; h < H; h++) {
            float ex = __expf(alpha[(size_t)j * H + h] - mx[h]);
            alpha[(size_t)j * H + h] = ex;
            sm[h] += ex;
        }
    }
#pragma unroll
    for (int h = 0; h < H; h++) {
#pragma unroll
        for (int o = 16; o; o >>= 1) sm[h] += __shfl_xor_sync(0xffffffffu, sm[h], o);
        sm[h] = 1.f / (sm[h] + 1e-16f);
    }
    for (int j = s0 + lane; j < s1; j += 32) {
#pragma unroll
        for (int h = 0; h < H; h++) alpha[(size_t)j * H + h] *= sm[h];
    }
}

// ---------------- aggregation H=4,C=64 ----------------
__global__ void k_agg4(const int* __restrict__ rowptr, const int* __restrict__ srcp,
                       const float* __restrict__ alpha, const float* __restrict__ hsrc,
                       const float* __restrict__ b1, const float* __restrict__ b2,
                       float* __restrict__ out, int Nd, int accum) {
    int w = (blockIdx.x * blockDim.x + threadIdx.x) >> 5;
    int lane = threadIdx.x & 31;
    if (w >= Nd) return;
    int s0 = rowptr[w], s1 = rowptr[w + 1];
    if (accum && s0 == s1) return;
    int c0 = lane, c1 = lane + 32;
    int hsel = lane >> 4;
    float4 a0 = make_float4(0.f, 0.f, 0.f, 0.f), a1 = a0;
    for (int j = s0; j < s1; j++) {
        int s = srcp[j];
        float4 al = *(const float4*)(alpha + (size_t)j * 4);
        const float4* hr = (const float4*)(hsrc + (size_t)s * 256);
        float4 v0 = hr[c0], v1 = hr[c1];
        float w0 = hsel ? al.y : al.x;
        float w1 = hsel ? al.w : al.z;
        a0.x = fmaf(v0.x, w0, a0.x); a0.y = fmaf(v0.y, w0, a0.y);
        a0.z = fmaf(v0.z, w0, a0.z); a0.w = fmaf(v0.w, w0, a0.w);
        a1.x = fmaf(v1.x, w1, a1.x); a1.y = fmaf(v1.y, w1, a1.y);
        a1.z = fmaf(v1.z, w1, a1.z); a1.w = fmaf(v1.w, w1, a1.w);
    }
    float4* orow = (float4*)(out + (size_t)w * 256);
    if (accum) {
        float4 o0 = orow[c0], o1 = orow[c1];
        o0.x += a0.x; o0.y += a0.y; o0.z += a0.z; o0.w += a0.w;
        o1.x += a1.x; o1.y += a1.y; o1.z += a1.z; o1.w += a1.w;
        orow[c0] = o0; orow[c1] = o1;
    } else {
        const float4* B1 = (const float4*)b1;
        float4 bb0 = B1[c0], bb1 = B1[c1];
        if (b2) {
            const float4* B2 = (const float4*)b2;
            float4 t0 = B2[c0], t1 = B2[c1];
            bb0.x += t0.x; bb0.y += t0.y; bb0.z += t0.z; bb0.w += t0.w;
            bb1.x += t1.x; bb1.y += t1.y; bb1.z += t1.z; bb1.w += t1.w;
        }
        orow[c0] = make_float4(a0.x + bb0.x, a0.y + bb0.y, a0.z + bb0.z, a0.w + bb0.w);
        orow[c1] = make_float4(a1.x + bb1.x, a1.y + bb1.y, a1.z + bb1.z, a1.w + bb1.w);
    }
}

// ---------------- aggregation H=1,OUT=64 ----------------
__global__ void k_agg1(const int* __restrict__ rowptr, const int* __restrict__ srcp,
                       const float* __restrict__ alpha, const float* __restrict__ hsrc,
                       const float* __restrict__ b1, const float* __restrict__ b2,
                       float* __restrict__ out, int Nd, int accum) {
    int w = (blockIdx.x * blockDim.x + threadIdx.x) >> 5;
    int lane = threadIdx.x & 31;
    if (w >= Nd) return;
    int s0 = rowptr[w], s1 = rowptr[w + 1];
    if (accum && s0 == s1) return;
    float a0 = 0.f, a1 = 0.f;
    for (int j = s0; j < s1; j++) {
        int s = srcp[j];
        float al = alpha[j];
        const float* hr = hsrc + (size_t)s * 64;
        a0 = fmaf(hr[lane], al, a0);
        a1 = fmaf(hr[lane + 32], al, a1);
    }
    float* orow = out + (size_t)w * 64;
    if (accum) {
        orow[lane] += a0;
        orow[lane + 32] += a1;
    } else {
        float bb0 = b1[lane], bb1 = b1[lane + 32];
        if (b2) { bb0 += b2[lane]; bb1 += b2[lane + 32]; }
        orow[lane] = a0 + bb0;
        orow[lane + 32] = a1 + bb1;
    }
}

__global__ void k_elu(float* __restrict__ x, size_t n) {
    size_t i = (size_t)blockIdx.x * blockDim.x + threadIdx.x;
    if (i < n) {
        float v = x[i];
        x[i] = v > 0.f ? v : expm1f(v);
    }
}

// =====================================================================
extern "C" void kernel_launch(void* const* d_in, const int* in_sizes, int n_in,
                              void* d_out, int out_size) {
    const float* x_drug = (const float*)d_in[0];
    const float* x_prot = (const float*)d_in[1];
    const int* srcA[3] = {(const int*)d_in[2], (const int*)d_in[4], (const int*)d_in[6]};
    const int* dstA[3] = {(const int*)d_in[3], (const int*)d_in[5], (const int*)d_in[7]};
    const float* linW_d = (const float*)d_in[8];
    const float* linb_d = (const float*)d_in[9];
    const float* linW_p = (const float*)d_in[10];
    const float* linb_p = (const float*)d_in[11];
    const float* W_hid = (const float*)d_in[12];
    const float* as_hid = (const float*)d_in[13];
    const float* ad_hid = (const float*)d_in[14];
    const float* b_hid = (const float*)d_in[15];
    const float* W_out = (const float*)d_in[16];
    const float* as_out = (const float*)d_in[17];
    const float* ad_out = (const float*)d_in[18];
    const float* b_out = (const float*)d_in[19];
    float* outp = (float*)d_out;

    int E[3] = {in_sizes[2], in_sizes[4], in_sizes[6]};
    int NdT[3] = {NP, ND, NP};

    float *xdb, *xpb, *hb, *alpha, *als, *ald, *V;
    int *rp_base, *sp_base, *cnt;
    __nv_bfloat16 *whi, *wlo;
    cudaGetSymbolAddress((void**)&xdb, g_xd);
    cudaGetSymbolAddress((void**)&xpb, g_xp);
    cudaGetSymbolAddress((void**)&hb, g_h);
    cudaGetSymbolAddress((void**)&alpha, g_alpha);
    cudaGetSymbolAddress((void**)&als, g_als);
    cudaGetSymbolAddress((void**)&ald, g_ald);
    cudaGetSymbolAddress((void**)&V, g_V);
    cudaGetSymbolAddress((void**)&rp_base, g_rowptr);
    cudaGetSymbolAddress((void**)&sp_base, g_srcp);
    cudaGetSymbolAddress((void**)&cnt, g_cnt);
    cudaGetSymbolAddress((void**)&whi, g_whi);
    cudaGetSymbolAddress((void**)&wlo, g_wlo);

    float* xd[2] = {xdb, xdb + (size_t)ND * HIDW};
    float* xp[2] = {xpb, xpb + (size_t)NP * HIDW};
    int* rowptr[3] = {rp_base, rp_base + (NP + 1), rp_base + 2 * (NP + 1)};
    int* srcp[3] = {sp_base, sp_base + EMAX, sp_base + 2 * EMAX};

    // dynamic smem: 1024 + 4*ABUF + 4*BBUF
    const int SM128 = 1024 + 4 * (128 * 40 * 2) + 4 * (128 * 40 * 2);  // 82944
    const int SM64 = 1024 + 4 * (128 * 40 * 2) + 4 * (64 * 40 * 2);    // 62464
    cudaFuncSetAttribute(k_mma<128, true, true, 0>,
                         cudaFuncAttributeMaxDynamicSharedMemorySize, SM128);
    cudaFuncSetAttribute(k_mma<128, false, false, 4>,
                         cudaFuncAttributeMaxDynamicSharedMemorySize, SM128);
    cudaFuncSetAttribute(k_mma<64, false, false, 1>,
                         cudaFuncAttributeMaxDynamicSharedMemorySize, SM64);

    // weight scratch offsets (elements in [N*K] layout)
    size_t o_lind = 0;
    size_t o_linp = o_lind + 256 * 128;
    size_t o_hid0 = o_linp + 256 * 256;
    size_t o_out0 = o_hid0 + 6 * 65536;

    // ---- pre-transpose + split weights ----
    k_splitW<<<(256 * 128 + 255) / 256, 256>>>(linW_d, whi + o_lind, wlo + o_lind, 128, 256);
    k_splitW<<<(256 * 256 + 255) / 256, 256>>>(linW_p, whi + o_linp, wlo + o_linp, 256, 256);
    for (int i = 0; i < 6; i++)
        k_splitW<<<(65536 + 255) / 256, 256>>>(W_hid + (size_t)i * 65536,
                                               whi + o_hid0 + (size_t)i * 65536,
                                               wlo + o_hid0 + (size_t)i * 65536, 256, 256);
    for (int i = 0; i < 3; i++)
        k_splitW<<<(16384 + 255) / 256, 256>>>(W_out + (size_t)i * 16384,
                                               whi + o_out0 + (size_t)i * 16384,
                                               wlo + o_out0 + (size_t)i * 16384, 256, 64);

    // ---- build CSR per edge type ----
    for (int t = 0; t < 3; t++) {
        int nb = (NdT[t] + 255) / 256, eb = (E[t] + 255) / 256;
        k_zero<<<nb, 256>>>(cnt, NdT[t]);
        k_count<<<eb, 256>>>(dstA[t], E[t], cnt);
        k_scan<<<1, 1024>>>(cnt, rowptr[t], NdT[t]);
        k_zero<<<nb, 256>>>(cnt, NdT[t]);
        k_scatter<<<eb, 256>>>(srcA[t], dstA[t], E[t], rowptr[t], cnt, srcp[t]);
    }

    // ---- input projections + relu ----
    {
        dim3 gd((ND + 127) / 128, 2);
        k_mma<128, true, true, 0><<<gd, 256, SM128>>>(x_drug, whi + o_lind, wlo + o_lind,
                                                      linb_d, nullptr, xd[0], nullptr, ND, 128,
                                                      256);
        dim3 gp((NP + 127) / 128, 2);
        k_mma<128, true, true, 0><<<gp, 256, SM128>>>(x_prot, whi + o_linp, wlo + o_linp,
                                                      linb_p, nullptr, xp[0], nullptr, NP, 256,
                                                      256);
    }

    int cur = 0, nxt = 1;

    // ---- hidden layers (H=4, C=64) ----
    for (int l = 0; l < 2; l++) {
        auto run_gat4 = [&](int et, const float* xsrc, int Ns, const float* xdst, int Ndst,
                            int csr, const float* b1, const float* b2, float* ob, int accum) {
            int idx = l * 3 + et;
            const float* W = W_hid + (size_t)idx * HIDW * HIDW;
            const float* asr = as_hid + (size_t)idx * HIDW;
            const float* adr = ad_hid + (size_t)idx * HIDW;
            const __nv_bfloat16* bh = whi + o_hid0 + (size_t)idx * 65536;
            const __nv_bfloat16* bl = wlo + o_hid0 + (size_t)idx * 65536;
            k_makeV<<<1, 256>>>(W, adr, V, 4, 64);
            dim3 gg((Ns + 127) / 128, 2);
            k_mma<128, false, false, 4><<<gg, 256, SM128>>>(xsrc, bh, bl, nullptr, asr, hb, als,
                                                            Ns, 256, 256);
            k_al<4><<<(Ndst + 7) / 8, 256>>>(xdst, V, ald, Ndst);
            k_softmax<4><<<(Ndst + 7) / 8, 256>>>(rowptr[csr], srcp[csr], als, ald, alpha, Ndst);
            k_agg4<<<(Ndst + 7) / 8, 256>>>(rowptr[csr], srcp[csr], alpha, hb, b1, b2, ob, Ndst,
                                            accum);
        };
        const float* b0 = b_hid + (size_t)(l * 3 + 0) * HIDW;
        const float* b1_ = b_hid + (size_t)(l * 3 + 1) * HIDW;
        const float* b2 = b_hid + (size_t)(l * 3 + 2) * HIDW;
        run_gat4(0, xd[cur], ND, xp[cur], NP, 0, b0, b2, xp[nxt], 0);
        run_gat4(2, xp[cur], NP, xp[cur], NP, 2, nullptr, nullptr, xp[nxt], 1);
        run_gat4(1, xp[cur], NP, xd[cur], ND, 1, b1_, nullptr, xd[nxt], 0);
        k_elu<<<(unsigned)(((size_t)ND * HIDW + 255) / 256), 256>>>(xd[nxt], (size_t)ND * HIDW);
        k_elu<<<(unsigned)(((size_t)NP * HIDW + 255) / 256), 256>>>(xp[nxt], (size_t)NP * HIDW);
        cur = nxt;
        nxt = 1 - nxt;
    }

    // ---- output layer (H=1, OUT=64) ----
    float* od = outp;
    float* op = outp + (size_t)ND * OUTC;
    auto run_gat1 = [&](int et, const float* xsrc, int Ns, const float* xdst, int Ndst, int csr,
                        const float* b1, const float* b2, float* ob, int accum) {
        const float* W = W_out + (size_t)et * HIDW * OUTC;
        const float* asr = as_out + (size_t)et * OUTC;
        const float* adr = ad_out + (size_t)et * OUTC;
        const __nv_bfloat16* bh = whi + o_out0 + (size_t)et * 16384;
        const __nv_bfloat16* bl = wlo + o_out0 + (size_t)et * 16384;
        k_makeV<<<1, 256>>>(W, adr, V, 1, 64);
        k_zero<<<(Ns + 255) / 256, 256>>>((int*)als, Ns);  // als zero for atomic accumulate
        dim3 gg((Ns + 127) / 128, 1);
        k_mma<64, false, false, 1><<<gg, 256, SM64>>>(xsrc, bh, bl, nullptr, asr, hb, als, Ns,
                                                      256, 64);
        k_al<1><<<(Ndst + 7) / 8, 256>>>(xdst, V, ald, Ndst);
        k_softmax<1><<<(Ndst + 7) / 8, 256>>>(rowptr[csr], srcp[csr], als, ald, alpha, Ndst);
        k_agg1<<<(Ndst + 7) / 8, 256>>>(rowptr[csr], srcp[csr], alpha, hb, b1, b2, ob, Ndst,
                                        accum);
    };
    run_gat1(0, xd[cur], ND, xp[cur], NP, 0, b_out + 0 * OUTC, b_out + 2 * OUTC, op, 0);
    run_gat1(2, xp[cur], NP, xp[cur], NP, 2, nullptr, nullptr, op, 1);
    run_gat1(1, xp[cur], NP, xd[cur], ND, 1, b_out + 1 * OUTC, nullptr, od, 0);

    (void)n_in;
    (void)out_size;
}

// round 7
// speedup vs baseline: 2.2841x; 1.3785x over previous
#include <cuda_runtime.h>
#include <cuda_bf16.h>
#include <cstdint>

// Problem constants (fixed shapes)
#define ND 20000
#define NP 40000
#define EMAX 300000
#define HIDW 256
#define OUTC 64
#define NEG 0.2f

// ---------------- static device scratch (allocation-free rule) ----------------
__device__ float g_xd[2][ND * HIDW];
__device__ float g_xp[2][NP * HIDW];
__device__ float g_h[NP * HIDW];
__device__ float g_alpha[EMAX * 4];
__device__ float g_als[NP * 4];
__device__ float g_ald[NP * 4];
__device__ float g_V[9 * 1024];
__device__ int   g_rowptr[3 * (NP + 1)];
__device__ int   g_srcp[3 * EMAX];
__device__ int   g_cnt[3 * NP];
#define WTOT 540672
__device__ __nv_bfloat16 g_whi[WTOT];
__device__ __nv_bfloat16 g_wlo[WTOT];

// ======================= helpers =======================
__device__ __forceinline__ uint32_t smem_u32(const void* p) {
    uint32_t a;
    asm("{ .reg .u64 t; cvta.to.shared.u64 t, %1; cvt.u32.u64 %0, t; }" : "=r"(a) : "l"(p));
    return a;
}
__device__ __forceinline__ void cp_async8(uint32_t dst, const void* src) {
    asm volatile("cp.async.ca.shared.global [%0], [%1], 8;" :: "r"(dst), "l"(src));
}
#define CP_COMMIT() asm volatile("cp.async.commit_group;" ::: "memory")
#define CP_WAIT0()  asm volatile("cp.async.wait_group 0;" ::: "memory")

__device__ __forceinline__ void mma16816(float* c, const uint32_t* a, const uint32_t* b) {
    asm volatile(
        "mma.sync.aligned.m16n8k16.row.col.f32.bf16.bf16.f32 "
        "{%0,%1,%2,%3}, {%4,%5,%6,%7}, {%8,%9}, {%0,%1,%2,%3};"
        : "+f"(c[0]), "+f"(c[1]), "+f"(c[2]), "+f"(c[3])
        : "r"(a[0]), "r"(a[1]), "r"(a[2]), "r"(a[3]), "r"(b[0]), "r"(b[1]));
}

__device__ __forceinline__ uint32_t pack_bf2(float x, float y) {
    __nv_bfloat162 t = __floats2bfloat162_rn(x, y);
    return *reinterpret_cast<uint32_t*>(&t);
}
__device__ __forceinline__ float eluf(float v) { return v > 0.f ? v : expm1f(v); }

// ---------------- weight pre-transpose + bf16 split: Bt[n][k] = W[k][n] ----------------
__global__ void k_splitW(const float* __restrict__ W, __nv_bfloat16* __restrict__ hi,
                         __nv_bfloat16* __restrict__ lo, int K, int N) {
    int i = blockIdx.x * 256 + threadIdx.x;
    if (i >= N * K) return;
    int n = i / K, k = i % K;
    float v = W[(size_t)k * N + n];
    __nv_bfloat16 h = __float2bfloat16(v);
    hi[i] = h;
    lo[i] = __float2bfloat16(v - __bfloat162float(h));
}

// ============ mma.sync GEMM: C[M,NT] = A[M,K] @ Bt^T, 3-pass bf16 split ============
// HALS: 0 none; 4: als[row,h] = sum C*asrc (store); 1: atomicAdd into pre-zeroed als.
// Runtime dual (adst != nullptr): also compute ald with adst.
template <int BN, bool BIAS, bool RELU, int HALS>
__global__ void __launch_bounds__(256) k_mma(
    const float* __restrict__ A, const __nv_bfloat16* __restrict__ Bthi,
    const __nv_bfloat16* __restrict__ Btlo, const float* __restrict__ bias,
    const float* __restrict__ asrc, const float* __restrict__ adst,
    float* __restrict__ C, float* __restrict__ als, float* __restrict__ ald,
    int M, int K, int NT) {
    extern __shared__ char smem[];
    constexpr int WN = BN / 2;
    constexpr int NTILES = WN / 8;
    constexpr int ABUF = 128 * 40 * 2;
    constexpr int BBUF = BN * 40 * 2;
    constexpr int S_A = 2048;
    constexpr int S_B = S_A + 4 * ABUF;
    float* sBias = (float*)(smem);
    float* sAsrc = (float*)(smem + 512);
    float* sAdst = (float*)(smem + 1024);

    const bool dual = (HALS != 0) && (adst != nullptr);

    int tid = threadIdx.x;
    int wid = tid >> 5, lane = tid & 31;
    int g = lane >> 2, tg = lane & 3;
    int warp_m = wid & 3, warp_n = wid >> 2;
    int bm = blockIdx.x * 128, bn = blockIdx.y * BN;

    if (BIAS)
        for (int i = tid; i < BN; i += 256) sBias[i] = bias[bn + i];
    if (HALS) {
        for (int i = tid; i < BN; i += 256) sAsrc[i] = asrc[bn + i];
        if (dual)
            for (int i = tid; i < BN; i += 256) sAdst[i] = adst[bn + i];
    }

    int arow = tid >> 1;
    int akq = (tid & 1) * 16;
    bool aval_base = (bm + arow) < M;
    constexpr int CH = BN * 8 / 256;

    float acc[2][NTILES][4];
#pragma unroll
    for (int mi = 0; mi < 2; mi++)
#pragma unroll
        for (int nt = 0; nt < NTILES; nt++)
#pragma unroll
            for (int q = 0; q < 4; q++) acc[mi][nt][q] = 0.f;

    uint32_t sbase = smem_u32(smem);

    auto loadA = [&](int k0, float4* ar) {
        const float* src = A + (size_t)(bm + arow) * K + k0 + akq;
#pragma unroll
        for (int i = 0; i < 4; i++)
            ar[i] = aval_base ? ((const float4*)src)[i] : make_float4(0.f, 0.f, 0.f, 0.f);
    };
    auto storeA = [&](const float4* ar, int buf) {
        char* dh = smem + S_A + buf * 2 * ABUF;
        char* dl = dh + ABUF;
#pragma unroll
        for (int i = 0; i < 4; i++) {
            float4 f = ar[i];
            __nv_bfloat16 hx = __float2bfloat16(f.x), hy = __float2bfloat16(f.y);
            __nv_bfloat16 hz = __float2bfloat16(f.z), hw = __float2bfloat16(f.w);
            __nv_bfloat162 H01(hx, hy), H23(hz, hw);
            uint32_t h01 = *(uint32_t*)&H01, h23 = *(uint32_t*)&H23;
            uint32_t l01 = pack_bf2(f.x - __bfloat162float(hx), f.y - __bfloat162float(hy));
            uint32_t l23 = pack_bf2(f.z - __bfloat162float(hz), f.w - __bfloat162float(hw));
            int off = (arow * 40 + akq + i * 4) * 2;
            *(uint2*)(dh + off) = make_uint2(h01, h23);
            *(uint2*)(dl + off) = make_uint2(l01, l23);
        }
    };
    auto loadB = [&](int k0, int buf) {
        uint32_t dh = sbase + S_B + buf * 2 * BBUF;
        uint32_t dl = dh + BBUF;
#pragma unroll
        for (int i = 0; i < CH; i++) {
            int c = tid + i * 256;
            int row = c >> 3, kc = c & 7;
            size_t go = (size_t)(bn + row) * K + k0 + kc * 4;
            uint32_t so = row * 80 + kc * 8;
            cp_async8(dh + so, Bthi + go);
            cp_async8(dl + so, Btlo + go);
        }
        CP_COMMIT();
    };
    auto compute = [&](int buf) {
        const char* Ah = smem + S_A + buf * 2 * ABUF;
        const char* Al = Ah + ABUF;
        const char* Bh = smem + S_B + buf * 2 * BBUF;
        const char* Bl = Bh + BBUF;
#pragma unroll
        for (int kk = 0; kk < 32; kk += 16) {
            uint32_t ah[2][4], al[2][4];
#pragma unroll
            for (int mi = 0; mi < 2; mi++) {
                int r0 = warp_m * 32 + mi * 16 + g;
                int kb = kk + tg * 2;
                ah[mi][0] = *(const uint32_t*)(Ah + (r0 * 40 + kb) * 2);
                ah[mi][1] = *(const uint32_t*)(Ah + ((r0 + 8) * 40 + kb) * 2);
                ah[mi][2] = *(const uint32_t*)(Ah + (r0 * 40 + kb + 8) * 2);
                ah[mi][3] = *(const uint32_t*)(Ah + ((r0 + 8) * 40 + kb + 8) * 2);
                al[mi][0] = *(const uint32_t*)(Al + (r0 * 40 + kb) * 2);
                al[mi][1] = *(const uint32_t*)(Al + ((r0 + 8) * 40 + kb) * 2);
                al[mi][2] = *(const uint32_t*)(Al + (r0 * 40 + kb + 8) * 2);
                al[mi][3] = *(const uint32_t*)(Al + ((r0 + 8) * 40 + kb + 8) * 2);
            }
#pragma unroll
            for (int nt = 0; nt < NTILES; nt++) {
                int nr = warp_n * WN + nt * 8 + g;
                int kb = kk + tg * 2;
                uint32_t bh[2], bl[2];
                bh[0] = *(const uint32_t*)(Bh + (nr * 40 + kb) * 2);
                bh[1] = *(const uint32_t*)(Bh + (nr * 40 + kb + 8) * 2);
                bl[0] = *(const uint32_t*)(Bl + (nr * 40 + kb) * 2);
                bl[1] = *(const uint32_t*)(Bl + (nr * 40 + kb + 8) * 2);
#pragma unroll
                for (int mi = 0; mi < 2; mi++) {
                    mma16816(acc[mi][nt], ah[mi], bh);
                    mma16816(acc[mi][nt], ah[mi], bl);
                    mma16816(acc[mi][nt], al[mi], bh);
                }
            }
        }
    };

    int nstages = K / 32;
    float4 ar[4];
    loadA(0, ar);
    loadB(0, 0);
    storeA(ar, 0);
    CP_WAIT0();
    __syncthreads();
    for (int s = 0; s < nstages; s++) {
        int cur = s & 1, nxt = cur ^ 1;
        bool more = (s + 1) < nstages;
        if (more) {
            loadA((s + 1) * 32, ar);
            loadB((s + 1) * 32, nxt);
        }
        compute(cur);
        if (more) storeA(ar, nxt);
        CP_WAIT0();
        __syncthreads();
    }

    // ---- epilogue ----
    float sals[2][2], sald[2][2];
    sals[0][0] = sals[0][1] = sals[1][0] = sals[1][1] = 0.f;
    sald[0][0] = sald[0][1] = sald[1][0] = sald[1][1] = 0.f;
#pragma unroll
    for (int mi = 0; mi < 2; mi++) {
        int r0 = bm + warp_m * 32 + mi * 16 + g;
        int r1 = r0 + 8;
#pragma unroll
        for (int nt = 0; nt < NTILES; nt++) {
            int nloc = warp_n * WN + nt * 8 + tg * 2;
            int n0 = bn + nloc;
            float* cc = acc[mi][nt];
            float v00 = cc[0], v01 = cc[1], v10 = cc[2], v11 = cc[3];
            if (BIAS) {
                v00 += sBias[nloc]; v01 += sBias[nloc + 1];
                v10 += sBias[nloc]; v11 += sBias[nloc + 1];
            }
            if (RELU) {
                v00 = fmaxf(v00, 0.f); v01 = fmaxf(v01, 0.f);
                v10 = fmaxf(v10, 0.f); v11 = fmaxf(v11, 0.f);
            }
            if (r0 < M) *(float2*)(C + (size_t)r0 * NT + n0) = make_float2(v00, v01);
            if (r1 < M) *(float2*)(C + (size_t)r1 * NT + n0) = make_float2(v10, v11);
            if (HALS) {
                float a0 = sAsrc[nloc], a1 = sAsrc[nloc + 1];
                sals[mi][0] += v00 * a0 + v01 * a1;
                sals[mi][1] += v10 * a0 + v11 * a1;
                if (dual) {
                    float d0 = sAdst[nloc], d1 = sAdst[nloc + 1];
                    sald[mi][0] += v00 * d0 + v01 * d1;
                    sald[mi][1] += v10 * d0 + v11 * d1;
                }
            }
        }
    }
    if (HALS) {
#pragma unroll
        for (int mi = 0; mi < 2; mi++)
#pragma unroll
            for (int hf = 0; hf < 2; hf++) {
                float s = sals[mi][hf];
                s += __shfl_xor_sync(0xffffffffu, s, 1);
                s += __shfl_xor_sync(0xffffffffu, s, 2);
                float s2 = sald[mi][hf];
                s2 += __shfl_xor_sync(0xffffffffu, s2, 1);
                s2 += __shfl_xor_sync(0xffffffffu, s2, 2);
                if (tg == 0) {
                    int r = bm + warp_m * 32 + mi * 16 + g + hf * 8;
                    if (r < M) {
                        if (HALS == 4) {
                            int h = blockIdx.y * 2 + warp_n;
                            als[(size_t)r * 4 + h] = s;
                            if (dual) ald[(size_t)r * 4 + h] = s2;
                        } else {
                            atomicAdd(&als[r], s);
                            if (dual) atomicAdd(&ald[r], s2);
                        }
                    }
                }
            }
    }
}

// ---------------- CSR build (batched over 3 edge types) ----------------
__global__ void k_zero(int* __restrict__ p, int n) {
    int i = blockIdx.x * blockDim.x + threadIdx.x;
    if (i < n) p[i] = 0;
}
__global__ void k_count3(const int* __restrict__ d0, const int* __restrict__ d1,
                         const int* __restrict__ d2, int E0, int E1, int E2,
                         int* __restrict__ cnt) {
    int t = blockIdx.y;
    const int* dst = (t == 0) ? d0 : (t == 1) ? d1 : d2;
    int E = (t == 0) ? E0 : (t == 1) ? E1 : E2;
    int i = blockIdx.x * 256 + threadIdx.x;
    if (i < E) atomicAdd(&cnt[t * NP + dst[i]], 1);
}
// 3 blocks, 1024 threads: warp-shuffle scan
__global__ void __launch_bounds__(1024) k_scan3(const int* __restrict__ cnt,
                                                int* __restrict__ rp, int n0, int n1, int n2) {
    int t = blockIdx.x;
    int n = (t == 0) ? n0 : (t == 1) ? n1 : n2;
    const int* c = cnt + t * NP;
    int* rowptr = rp + t * (NP + 1);
    __shared__ int wsum[32];
    __shared__ int carry;
    int tid = threadIdx.x, lane = tid & 31, wid = tid >> 5;
    if (tid == 0) { carry = 0; rowptr[0] = 0; }
    __syncthreads();
    for (int base = 0; base < n; base += 1024) {
        int i = base + tid;
        int x = (i < n) ? c[i] : 0;
#pragma unroll
        for (int o = 1; o < 32; o <<= 1) {
            int y = __shfl_up_sync(0xffffffffu, x, o);
            if (lane >= o) x += y;
        }
        if (lane == 31) wsum[wid] = x;
        __syncthreads();
        if (wid == 0) {
            int s = wsum[lane];
#pragma unroll
            for (int o = 1; o < 32; o <<= 1) {
                int y = __shfl_up_sync(0xffffffffu, s, o);
                if (lane >= o) s += y;
            }
            wsum[lane] = s;
        }
        __syncthreads();
        int incl = x + (wid ? wsum[wid - 1] : 0) + carry;
        if (i < n) rowptr[i + 1] = incl;
        __syncthreads();
        if (tid == 1023) carry = incl;
        __syncthreads();
    }
}
__global__ void k_scatter3(const int* __restrict__ s0p, const int* __restrict__ s1p,
                           const int* __restrict__ s2p, const int* __restrict__ d0,
                           const int* __restrict__ d1, const int* __restrict__ d2,
                           int E0, int E1, int E2, const int* __restrict__ rp,
                           int* __restrict__ off, int* __restrict__ srcp) {
    int t = blockIdx.y;
    const int* src = (t == 0) ? s0p : (t == 1) ? s1p : s2p;
    const int* dst = (t == 0) ? d0 : (t == 1) ? d1 : d2;
    int E = (t == 0) ? E0 : (t == 1) ? E1 : E2;
    int i = blockIdx.x * 256 + threadIdx.x;
    if (i < E) {
        int d = dst[i];
        int p = rp[t * (NP + 1) + d] + atomicAdd(&off[t * NP + d], 1);
        srcp[t * EMAX + p] = src[i];
    }
}

// ---------------- all 9 Vd vectors in one launch ----------------
__global__ void k_makeV_all(const float* __restrict__ W_hid, const float* __restrict__ ad_hid,
                            const float* __restrict__ W_out, const float* __restrict__ ad_out,
                            float* __restrict__ V) {
    int b = blockIdx.x;
    int k = threadIdx.x;
    if (b < 6) {
        const float* W = W_hid + (size_t)b * 65536;
        const float* a = ad_hid + (size_t)b * 256;
        for (int h = 0; h < 4; h++) {
            float s = 0.f;
            for (int c = 0; c < 64; c++) s = fmaf(W[k * 256 + h * 64 + c], a[h * 64 + c], s);
            V[b * 1024 + k * 4 + h] = s;
        }
    } else {
        const float* W = W_out + (size_t)(b - 6) * 16384;
        const float* a = ad_out + (size_t)(b - 6) * 64;
        float s = 0.f;
        for (int c = 0; c < 64; c++) s = fmaf(W[k * 64 + c], a[c], s);
        V[b * 1024 + k] = s;
    }
}

// ---------------- al[n,h] = x[n,:] @ V[:,h] (K=256 fixed) ----------------
template <int H>
__global__ void k_al(const float* __restrict__ X, const float* __restrict__ V,
                     float* __restrict__ al, int Nrows) {
    __shared__ float Vs[256 * H];
    for (int i = threadIdx.x; i < 256 * H; i += blockDim.x) Vs[i] = V[i];
    __syncthreads();
    int w = (blockIdx.x * blockDim.x + threadIdx.x) >> 5;
    int lane = threadIdx.x & 31;
    if (w >= Nrows) return;
    float p[H];
#pragma unroll
    for (int h = 0; h < H; h++) p[h] = 0.f;
    const float* xr = X + (size_t)w * 256;
#pragma unroll
    for (int t = 0; t < 8; t++) {
        int k = lane + t * 32;
        float x = xr[k];
#pragma unroll
        for (int h = 0; h < H; h++) p[h] = fmaf(x, Vs[k * H + h], p[h]);
    }
#pragma unroll
    for (int h = 0; h < H; h++) {
#pragma unroll
        for (int o = 16; o; o >>= 1) p[h] += __shfl_xor_sync(0xffffffffu, p[h], o);
    }
    if (lane == 0) {
#pragma unroll
        for (int h = 0; h < H; h++) al[(size_t)w * H + h] = p[h];
    }
}

// ---------------- fused segment softmax + aggregation, H=4 ----------------
__global__ void k_smagg4(const int* __restrict__ rowptr, const int* __restrict__ srcp,
                         const float* __restrict__ als, const float* __restrict__ ald,
                         float* __restrict__ alpha, const float* __restrict__ hsrc,
                         const float* __restrict__ b1, const float* __restrict__ b2,
                         float* __restrict__ out, int Nd, int accum, int act) {
    int w = (blockIdx.x * blockDim.x + threadIdx.x) >> 5;
    int lane = threadIdx.x & 31;
    if (w >= Nd) return;
    int s0 = rowptr[w], s1 = rowptr[w + 1];

    float ad[4], mx[4], sm[4], inv[4];
#pragma unroll
    for (int h = 0; h < 4; h++) {
        ad[h] = ald[(size_t)w * 4 + h];
        mx[h] = __int_as_float(0xff800000u);
        sm[h] = 0.f;
    }
    for (int j = s0 + lane; j < s1; j += 32) {
        int s = srcp[j];
#pragma unroll
        for (int h = 0; h < 4; h++) {
            float e = als[(size_t)s * 4 + h] + ad[h];
            e = e > 0.f ? e : NEG * e;
            alpha[(size_t)j * 4 + h] = e;
            mx[h] = fmaxf(mx[h], e);
        }
    }
#pragma unroll
    for (int h = 0; h < 4; h++)
#pragma unroll
        for (int o = 16; o; o >>= 1) mx[h] = fmaxf(mx[h], __shfl_xor_sync(0xffffffffu, mx[h], o));
    for (int j = s0 + lane; j < s1; j += 32) {
#pragma unroll
        for (int h = 0; h < 4; h++) {
            float ex = __expf(alpha[(size_t)j * 4 + h] - mx[h]);
            alpha[(size_t)j * 4 + h] = ex;
            sm[h] += ex;
        }
    }
#pragma unroll
    for (int h = 0; h < 4; h++) {
#pragma unroll
        for (int o = 16; o; o >>= 1) sm[h] += __shfl_xor_sync(0xffffffffu, sm[h], o);
        inv[h] = 1.f / (sm[h] + 1e-16f);
    }
    int c0 = lane, c1 = lane + 32;
    int hsel = lane >> 4;
    float inv0 = inv[hsel], inv1 = inv[hsel + 2];
    float4 a0 = make_float4(0.f, 0.f, 0.f, 0.f), a1 = a0;
    for (int j = s0; j < s1; j++) {
        int s = srcp[j];
        float4 al = *(const float4*)(alpha + (size_t)j * 4);
        const float4* hr = (const float4*)(hsrc + (size_t)s * 256);
        float4 v0 = hr[c0], v1 = hr[c1];
        float w0 = (hsel ? al.y : al.x) * inv0;
        float w1 = (hsel ? al.w : al.z) * inv1;
        a0.x = fmaf(v0.x, w0, a0.x); a0.y = fmaf(v0.y, w0, a0.y);
        a0.z = fmaf(v0.z, w0, a0.z); a0.w = fmaf(v0.w, w0, a0.w);
        a1.x = fmaf(v1.x, w1, a1.x); a1.y = fmaf(v1.y, w1, a1.y);
        a1.z = fmaf(v1.z, w1, a1.z); a1.w = fmaf(v1.w, w1, a1.w);
    }
    float4* orow = (float4*)(out + (size_t)w * 256);
    float4 o0, o1;
    if (accum) {
        o0 = orow[c0]; o1 = orow[c1];
        o0.x += a0.x; o0.y += a0.y; o0.z += a0.z; o0.w += a0.w;
        o1.x += a1.x; o1.y += a1.y; o1.z += a1.z; o1.w += a1.w;
    } else {
        const float4* B1 = (const float4*)b1;
        float4 bb0 = B1[c0], bb1 = B1[c1];
        if (b2) {
            const float4* B2 = (const float4*)b2;
            float4 t0 = B2[c0], t1 = B2[c1];
            bb0.x += t0.x; bb0.y += t0.y; bb0.z += t0.z; bb0.w += t0.w;
            bb1.x += t1.x; bb1.y += t1.y; bb1.z += t1.z; bb1.w += t1.w;
        }
        o0 = make_float4(a0.x + bb0.x, a0.y + bb0.y, a0.z + bb0.z, a0.w + bb0.w);
        o1 = make_float4(a1.x + bb1.x, a1.y + bb1.y, a1.z + bb1.z, a1.w + bb1.w);
    }
    if (act) {
        o0.x = eluf(o0.x); o0.y = eluf(o0.y); o0.z = eluf(o0.z); o0.w = eluf(o0.w);
        o1.x = eluf(o1.x); o1.y = eluf(o1.y); o1.z = eluf(o1.z); o1.w = eluf(o1.w);
    }
    orow[c0] = o0;
    orow[c1] = o1;
}

// ---------------- fused segment softmax + aggregation, H=1, 64 cols ----------------
__global__ void k_smagg1(const int* __restrict__ rowptr, const int* __restrict__ srcp,
                         const float* __restrict__ als, const float* __restrict__ ald,
                         float* __restrict__ alpha, const float* __restrict__ hsrc,
                         const float* __restrict__ b1, const float* __restrict__ b2,
                         float* __restrict__ out, int Nd, int accum) {
    int w = (blockIdx.x * blockDim.x + threadIdx.x) >> 5;
    int lane = threadIdx.x & 31;
    if (w >= Nd) return;
    int s0 = rowptr[w], s1 = rowptr[w + 1];
    float ad = ald[w];
    float mx = __int_as_float(0xff800000u), sm = 0.f;
    for (int j = s0 + lane; j < s1; j += 32) {
        int s = srcp[j];
        float e = als[s] + ad;
        e = e > 0.f ? e : NEG * e;
        alpha[j] = e;
        mx = fmaxf(mx, e);
    }
#pragma unroll
    for (int o = 16; o; o >>= 1) mx = fmaxf(mx, __shfl_xor_sync(0xffffffffu, mx, o));
    for (int j = s0 + lane; j < s1; j += 32) {
        float ex = __expf(alpha[j] - mx);
        alpha[j] = ex;
        sm += ex;
    }
#pragma unroll
    for (int o = 16; o; o >>= 1) sm += __shfl_xor_sync(0xffffffffu, sm, o);
    float inv = 1.f / (sm + 1e-16f);
    float a0 = 0.f, a1 = 0.f;
    for (int j = s0; j < s1; j++) {
        int s = srcp[j];
        float al = alpha[j] * inv;
        const float* hr = hsrc + (size_t)s * 64;
        a0 = fmaf(hr[lane], al, a0);
        a1 = fmaf(hr[lane + 32], al, a1);
    }
    float* orow = out + (size_t)w * 64;
    if (accum) {
        orow[lane] += a0;
        orow[lane + 32] += a1;
    } else {
        float bb0 = b1[lane], bb1 = b1[lane + 32];
        if (b2) { bb0 += b2[lane]; bb1 += b2[lane + 32]; }
        orow[lane] = a0 + bb0;
        orow[lane + 32] = a1 + bb1;
    }
}

// =====================================================================
extern "C" void kernel_launch(void* const* d_in, const int* in_sizes, int n_in,
                              void* d_out, int out_size) {
    const float* x_drug = (const float*)d_in[0];
    const float* x_prot = (const float*)d_in[1];
    const int* srcA[3] = {(const int*)d_in[2], (const int*)d_in[4], (const int*)d_in[6]};
    const int* dstA[3] = {(const int*)d_in[3], (const int*)d_in[5], (const int*)d_in[7]};
    const float* linW_d = (const float*)d_in[8];
    const float* linb_d = (const float*)d_in[9];
    const float* linW_p = (const float*)d_in[10];
    const float* linb_p = (const float*)d_in[11];
    const float* W_hid = (const float*)d_in[12];
    const float* as_hid = (const float*)d_in[13];
    const float* ad_hid = (const float*)d_in[14];
    const float* b_hid = (const float*)d_in[15];
    const float* W_out = (const float*)d_in[16];
    const float* as_out = (const float*)d_in[17];
    const float* ad_out = (const float*)d_in[18];
    const float* b_out = (const float*)d_in[19];
    float* outp = (float*)d_out;

    int E[3] = {in_sizes[2], in_sizes[4], in_sizes[6]};
    int maxE = E[0] > E[1] ? E[0] : E[1];
    if (E[2] > maxE) maxE = E[2];

    float *xdb, *xpb, *hb, *alpha, *als, *ald, *V;
    int *rp, *sp, *cnt;
    __nv_bfloat16 *whi, *wlo;
    cudaGetSymbolAddress((void**)&xdb, g_xd);
    cudaGetSymbolAddress((void**)&xpb, g_xp);
    cudaGetSymbolAddress((void**)&hb, g_h);
    cudaGetSymbolAddress((void**)&alpha, g_alpha);
    cudaGetSymbolAddress((void**)&als, g_als);
    cudaGetSymbolAddress((void**)&ald, g_ald);
    cudaGetSymbolAddress((void**)&V, g_V);
    cudaGetSymbolAddress((void**)&rp, g_rowptr);
    cudaGetSymbolAddress((void**)&sp, g_srcp);
    cudaGetSymbolAddress((void**)&cnt, g_cnt);
    cudaGetSymbolAddress((void**)&whi, g_whi);
    cudaGetSymbolAddress((void**)&wlo, g_wlo);

    float* xd[2] = {xdb, xdb + (size_t)ND * HIDW};
    float* xp[2] = {xpb, xpb + (size_t)NP * HIDW};
    int* rowptr[3] = {rp, rp + (NP + 1), rp + 2 * (NP + 1)};
    int* srcp[3] = {sp, sp + EMAX, sp + 2 * EMAX};

    const int SM128 = 2048 + 4 * (128 * 40 * 2) + 4 * (128 * 40 * 2);  // 83968
    const int SM64 = 2048 + 4 * (128 * 40 * 2) + 4 * (64 * 40 * 2);    // 63488
    cudaFuncSetAttribute(k_mma<128, true, true, 0>,
                         cudaFuncAttributeMaxDynamicSharedMemorySize, SM128);
    cudaFuncSetAttribute(k_mma<128, false, false, 4>,
                         cudaFuncAttributeMaxDynamicSharedMemorySize, SM128);
    cudaFuncSetAttribute(k_mma<64, false, false, 1>,
                         cudaFuncAttributeMaxDynamicSharedMemorySize, SM64);

    size_t o_lind = 0;
    size_t o_linp = o_lind + 256 * 128;
    size_t o_hid0 = o_linp + 256 * 256;
    size_t o_out0 = o_hid0 + 6 * 65536;

    int ebx = (maxE + 255) / 256;

    // ---- L0: splitW protein proj (needed by L5) ----
    k_splitW<<<(256 * 256 + 255) / 256, 256>>>(linW_p, whi + o_linp, wlo + o_linp, 256, 256);
    // ---- L1-4: CSR count+scan ----
    k_zero<<<(3 * NP + 255) / 256, 256>>>(cnt, 3 * NP);
    {
        dim3 gc(ebx, 3);
        k_count3<<<gc, 256>>>(dstA[0], dstA[1], dstA[2], E[0], E[1], E[2], cnt);
    }
    k_scan3<<<3, 1024>>>(cnt, rp, NP, ND, NP);
    k_zero<<<(3 * NP + 255) / 256, 256>>>(cnt, 3 * NP);
    // ---- L5: protein input projection (ncu -s 5 captures this) ----
    {
        dim3 gp((NP + 127) / 128, 2);
        k_mma<128, true, true, 0><<<gp, 256, SM128>>>(
            x_prot, whi + o_linp, wlo + o_linp, linb_p, nullptr, nullptr, xp[0], nullptr,
            nullptr, NP, 256, 256);
    }
    // ---- L6: CSR scatter ----
    {
        dim3 gs(ebx, 3);
        k_scatter3<<<gs, 256>>>(srcA[0], srcA[1], srcA[2], dstA[0], dstA[1], dstA[2], E[0],
                                E[1], E[2], rp, cnt, sp);
    }
    // ---- remaining weight prep ----
    k_splitW<<<(256 * 128 + 255) / 256, 256>>>(linW_d, whi + o_lind, wlo + o_lind, 128, 256);
    {
        dim3 gd((ND + 127) / 128, 2);
        k_mma<128, true, true, 0><<<gd, 256, SM128>>>(
            x_drug, whi + o_lind, wlo + o_lind, linb_d, nullptr, nullptr, xd[0], nullptr,
            nullptr, ND, 128, 256);
    }
    for (int i = 0; i < 6; i++)
        k_splitW<<<(65536 + 255) / 256, 256>>>(W_hid + (size_t)i * 65536,
                                               whi + o_hid0 + (size_t)i * 65536,
                                               wlo + o_hid0 + (size_t)i * 65536, 256, 256);
    for (int i = 0; i < 3; i++)
        k_splitW<<<(16384 + 255) / 256, 256>>>(W_out + (size_t)i * 16384,
                                               whi + o_out0 + (size_t)i * 16384,
                                               wlo + o_out0 + (size_t)i * 16384, 256, 64);
    k_makeV_all<<<9, 256>>>(W_hid, ad_hid, W_out, ad_out, V);

    int cur = 0, nxt = 1;

    // ---- hidden layers ----
    for (int l = 0; l < 2; l++) {
        const float* b0 = b_hid + (size_t)(l * 3 + 0) * HIDW;
        const float* b1_ = b_hid + (size_t)(l * 3 + 1) * HIDW;
        const float* b2 = b_hid + (size_t)(l * 3 + 2) * HIDW;
        // drug->protein (et 0): GEMM(xd) fused als; k_al for ald on xp; init xp_out, no elu
        {
            int idx = l * 3 + 0;
            const __nv_bfloat16* bh = whi + o_hid0 + (size_t)idx * 65536;
            const __nv_bfloat16* bl = wlo + o_hid0 + (size_t)idx * 65536;
            dim3 gg((ND + 127) / 128, 2);
            k_mma<128, false, false, 4><<<gg, 256, SM128>>>(
                xd[cur], bh, bl, nullptr, as_hid + (size_t)idx * 256, nullptr, hb, als, nullptr,
                ND, 256, 256);
            k_al<4><<<(NP + 7) / 8, 256>>>(xp[cur], V + idx * 1024, ald, NP);
            k_smagg4<<<(NP + 7) / 8, 256>>>(rowptr[0], srcp[0], als, ald, alpha, hb, b0, b2,
                                            xp[nxt], NP, 0, 0);
        }
        // protein->protein (et 2): dual GEMM gives als+ald; accumulate + elu
        {
            int idx = l * 3 + 2;
            const __nv_bfloat16* bh = whi + o_hid0 + (size_t)idx * 65536;
            const __nv_bfloat16* bl = wlo + o_hid0 + (size_t)idx * 65536;
            dim3 gg((NP + 127) / 128, 2);
            k_mma<128, false, false, 4><<<gg, 256, SM128>>>(
                xp[cur], bh, bl, nullptr, as_hid + (size_t)idx * 256,
                ad_hid + (size_t)idx * 256, hb, als, ald, NP, 256, 256);
            k_smagg4<<<(NP + 7) / 8, 256>>>(rowptr[2], srcp[2], als, ald, alpha, hb, nullptr,
                                            nullptr, xp[nxt], NP, 1, 1);
        }
        // protein->drug (et 1): GEMM(xp); k_al on xd; init xd_out + elu
        {
            int idx = l * 3 + 1;
            const __nv_bfloat16* bh = whi + o_hid0 + (size_t)idx * 65536;
            const __nv_bfloat16* bl = wlo + o_hid0 + (size_t)idx * 65536;
            dim3 gg((NP + 127) / 128, 2);
            k_mma<128, false, false, 4><<<gg, 256, SM128>>>(
                xp[cur], bh, bl, nullptr, as_hid + (size_t)idx * 256, nullptr, hb, als, nullptr,
                NP, 256, 256);
            k_al<4><<<(ND + 7) / 8, 256>>>(xd[cur], V + idx * 1024, ald, ND);
            k_smagg4<<<(ND + 7) / 8, 256>>>(rowptr[1], srcp[1], als, ald, alpha, hb, b1_,
                                            nullptr, xd[nxt], ND, 0, 1);
        }
        cur = nxt;
        nxt = 1 - nxt;
    }

    // ---- output layer (H=1, OUT=64) ----
    float* od = outp;
    float* op = outp + (size_t)ND * OUTC;
    // et 0: drug->protein
    {
        const __nv_bfloat16* bh = whi + o_out0;
        const __nv_bfloat16* bl = wlo + o_out0;
        k_zero<<<(ND + 255) / 256, 256>>>((int*)als, ND);
        dim3 gg((ND + 127) / 128, 1);
        k_mma<64, false, false, 1><<<gg, 256, SM64>>>(
            xd[cur], bh, bl, nullptr, as_out, nullptr, hb, als, nullptr, ND, 256, 64);
        k_al<1><<<(NP + 7) / 8, 256>>>(xp[cur], V + 6 * 1024, ald, NP);
        k_smagg1<<<(NP + 7) / 8, 256>>>(rowptr[0], srcp[0], als, ald, alpha, hb,
                                        b_out + 0 * OUTC, b_out + 2 * OUTC, op, NP, 0);
    }
    // et 2: protein->protein (dual)
    {
        const __nv_bfloat16* bh = whi + o_out0 + 2 * 16384;
        const __nv_bfloat16* bl = wlo + o_out0 + 2 * 16384;
        k_zero<<<(NP + 255) / 256, 256>>>((int*)als, NP);
        k_zero<<<(NP + 255) / 256, 256>>>((int*)ald, NP);
        dim3 gg((NP + 127) / 128, 1);
        k_mma<64, false, false, 1><<<gg, 256, SM64>>>(
            xp[cur], bh, bl, nullptr, as_out + 2 * OUTC, ad_out + 2 * OUTC, hb, als, ald, NP,
            256, 64);
        k_smagg1<<<(NP + 7) / 8, 256>>>(rowptr[2], srcp[2], als, ald, alpha, hb, nullptr,
                                        nullptr, op, NP, 1);
    }
    // et 1: protein->drug
    {
        const __nv_bfloat16* bh = whi + o_out0 + 1 * 16384;
        const __nv_bfloat16* bl = wlo + o_out0 + 1 * 16384;
        k_zero<<<(NP + 255) / 256, 256>>>((int*)als, NP);
        dim3 gg((NP + 127) / 128, 1);
        k_mma<64, false, false, 1><<<gg, 256, SM64>>>(
            xp[cur], bh, bl, nullptr, as_out + 1 * OUTC, nullptr, hb, als, nullptr, NP, 256,
            64);
        k_al<1><<<(ND + 7) / 8, 256>>>(xd[cur], V + 7 * 1024, ald, ND);
        k_smagg1<<<(ND + 7) / 8, 256>>>(rowptr[1], srcp[1], als, ald, alpha, hb,
                                        b_out + 1 * OUTC, nullptr, od, ND, 0);
    }

    (void)n_in;
    (void)out_size;
}

// round 8
// speedup vs baseline: 2.4998x; 1.0944x over previous
#include <cuda_runtime.h>
#include <cuda_bf16.h>
#include <cstdint>

// Problem constants (fixed shapes)
#define ND 20000
#define NP 40000
#define EMAX 300000
#define HIDW 256
#define OUTC 64
#define NEG 0.2f

// ---------------- static device scratch (allocation-free rule) ----------------
__device__ float g_xd[2][ND * HIDW];
__device__ float g_xp[2][NP * HIDW];
__device__ float g_h[NP * HIDW];
__device__ float g_alpha[EMAX * 4];
__device__ float g_als[NP * 4];
__device__ float g_ald[NP * 4];
__device__ float g_V[9 * 1024];
__device__ int   g_rowptr[3 * (NP + 1)];
__device__ int   g_srcp[3 * EMAX];
__device__ int   g_cnt[3 * NP];
#define WTOT 540672
__device__ __nv_bfloat16 g_whi[WTOT];
__device__ __nv_bfloat16 g_wlo[WTOT];

// ======================= helpers =======================
__device__ __forceinline__ uint32_t smem_u32(const void* p) {
    uint32_t a;
    asm("{ .reg .u64 t; cvta.to.shared.u64 t, %1; cvt.u32.u64 %0, t; }" : "=r"(a) : "l"(p));
    return a;
}
__device__ __forceinline__ void cp_async8(uint32_t dst, const void* src) {
    asm volatile("cp.async.ca.shared.global [%0], [%1], 8;" :: "r"(dst), "l"(src));
}
#define CP_COMMIT() asm volatile("cp.async.commit_group;" ::: "memory")
#define CP_WAIT0()  asm volatile("cp.async.wait_group 0;" ::: "memory")

__device__ __forceinline__ void mma16816(float* c, const uint32_t* a, const uint32_t* b) {
    asm volatile(
        "mma.sync.aligned.m16n8k16.row.col.f32.bf16.bf16.f32 "
        "{%0,%1,%2,%3}, {%4,%5,%6,%7}, {%8,%9}, {%0,%1,%2,%3};"
        : "+f"(c[0]), "+f"(c[1]), "+f"(c[2]), "+f"(c[3])
        : "r"(a[0]), "r"(a[1]), "r"(a[2]), "r"(a[3]), "r"(b[0]), "r"(b[1]));
}

__device__ __forceinline__ uint32_t pack_bf2(float x, float y) {
    __nv_bfloat162 t = __floats2bfloat162_rn(x, y);
    return *reinterpret_cast<uint32_t*>(&t);
}
__device__ __forceinline__ float eluf(float v) { return v > 0.f ? v : expm1f(v); }

// ---------------- all-weights pre-transpose + bf16 split in ONE launch ----------------
// layout offsets: linW_d @0 (128x256->32768), linW_p @32768 (65536),
// W_hid[6] @98304 (6x65536), W_out[3] @491520 (3x16384)
__global__ void k_splitW_all(const float* __restrict__ linW_d, const float* __restrict__ linW_p,
                             const float* __restrict__ W_hid, const float* __restrict__ W_out,
                             __nv_bfloat16* __restrict__ hi, __nv_bfloat16* __restrict__ lo) {
    int id = blockIdx.y;
    int i = blockIdx.x * 256 + threadIdx.x;
    const float* W;
    size_t off;
    int K, N;
    if (id == 0) { W = linW_d; off = 0; K = 128; N = 256; }
    else if (id == 1) { W = linW_p; off = 32768; K = 256; N = 256; }
    else if (id < 8) {
        W = W_hid + (size_t)(id - 2) * 65536; off = 98304 + (size_t)(id - 2) * 65536;
        K = 256; N = 256;
    } else {
        W = W_out + (size_t)(id - 8) * 16384; off = 491520 + (size_t)(id - 8) * 16384;
        K = 256; N = 64;
    }
    if (i >= N * K) return;
    int n = i / K, k = i % K;
    float v = W[(size_t)k * N + n];
    __nv_bfloat16 h = __float2bfloat16(v);
    hi[off + i] = h;
    lo[off + i] = __float2bfloat16(v - __bfloat162float(h));
}

// ============ mma.sync GEMM: C[M,NT] = A[M,K] @ Bt^T, 3-pass bf16 split ============
// HALS: 0 none; 4: als[row,h]=sum C*asrc (store); 1: block smem-reduce then store.
// Runtime dual (adst != nullptr): also compute ald with adst.
template <int BN, bool BIAS, bool RELU, int HALS>
__global__ void __launch_bounds__(256) k_mma(
    const float* __restrict__ A, const __nv_bfloat16* __restrict__ Bthi,
    const __nv_bfloat16* __restrict__ Btlo, const float* __restrict__ bias,
    const float* __restrict__ asrc, const float* __restrict__ adst,
    float* __restrict__ C, float* __restrict__ als, float* __restrict__ ald,
    int M, int K, int NT) {
    extern __shared__ char smem[];
    constexpr int WN = BN / 2;
    constexpr int NTILES = WN / 8;
    constexpr int ABUF = 128 * 40 * 2;
    constexpr int BBUF = BN * 40 * 2;
    constexpr int S_A = 2048;
    constexpr int S_B = S_A + 4 * ABUF;
    float* sBias = (float*)(smem);
    float* sAsrc = (float*)(smem + 512);
    float* sAdst = (float*)(smem + 1024);
    __shared__ float sr1[128];
    __shared__ float sr2[128];

    const bool dual = (HALS != 0) && (adst != nullptr);

    int tid = threadIdx.x;
    int wid = tid >> 5, lane = tid & 31;
    int g = lane >> 2, tg = lane & 3;
    int warp_m = wid & 3, warp_n = wid >> 2;
    int bm = blockIdx.x * 128, bn = blockIdx.y * BN;

    if (BIAS)
        for (int i = tid; i < BN; i += 256) sBias[i] = bias[bn + i];
    if (HALS) {
        for (int i = tid; i < BN; i += 256) sAsrc[i] = asrc[bn + i];
        if (dual)
            for (int i = tid; i < BN; i += 256) sAdst[i] = adst[bn + i];
    }

    int arow = tid >> 1;
    int akq = (tid & 1) * 16;
    bool aval_base = (bm + arow) < M;
    constexpr int CH = BN * 8 / 256;

    float acc[2][NTILES][4];
#pragma unroll
    for (int mi = 0; mi < 2; mi++)
#pragma unroll
        for (int nt = 0; nt < NTILES; nt++)
#pragma unroll
            for (int q = 0; q < 4; q++) acc[mi][nt][q] = 0.f;

    uint32_t sbase = smem_u32(smem);

    auto loadA = [&](int k0, float4* ar) {
        const float* src = A + (size_t)(bm + arow) * K + k0 + akq;
#pragma unroll
        for (int i = 0; i < 4; i++)
            ar[i] = aval_base ? ((const float4*)src)[i] : make_float4(0.f, 0.f, 0.f, 0.f);
    };
    auto storeA = [&](const float4* ar, int buf) {
        char* dh = smem + S_A + buf * 2 * ABUF;
        char* dl = dh + ABUF;
#pragma unroll
        for (int i = 0; i < 4; i++) {
            float4 f = ar[i];
            __nv_bfloat16 hx = __float2bfloat16(f.x), hy = __float2bfloat16(f.y);
            __nv_bfloat16 hz = __float2bfloat16(f.z), hw = __float2bfloat16(f.w);
            __nv_bfloat162 H01(hx, hy), H23(hz, hw);
            uint32_t h01 = *(uint32_t*)&H01, h23 = *(uint32_t*)&H23;
            uint32_t l01 = pack_bf2(f.x - __bfloat162float(hx), f.y - __bfloat162float(hy));
            uint32_t l23 = pack_bf2(f.z - __bfloat162float(hz), f.w - __bfloat162float(hw));
            int off = (arow * 40 + akq + i * 4) * 2;
            *(uint2*)(dh + off) = make_uint2(h01, h23);
            *(uint2*)(dl + off) = make_uint2(l01, l23);
        }
    };
    auto loadB = [&](int k0, int buf) {
        uint32_t dh = sbase + S_B + buf * 2 * BBUF;
        uint32_t dl = dh + BBUF;
#pragma unroll
        for (int i = 0; i < CH; i++) {
            int c = tid + i * 256;
            int row = c >> 3, kc = c & 7;
            size_t go = (size_t)(bn + row) * K + k0 + kc * 4;
            uint32_t so = row * 80 + kc * 8;
            cp_async8(dh + so, Bthi + go);
            cp_async8(dl + so, Btlo + go);
        }
        CP_COMMIT();
    };
    auto compute = [&](int buf) {
        const char* Ah = smem + S_A + buf * 2 * ABUF;
        const char* Al = Ah + ABUF;
        const char* Bh = smem + S_B + buf * 2 * BBUF;
        const char* Bl = Bh + BBUF;
#pragma unroll
        for (int kk = 0; kk < 32; kk += 16) {
            uint32_t ah[2][4], al[2][4];
#pragma unroll
            for (int mi = 0; mi < 2; mi++) {
                int r0 = warp_m * 32 + mi * 16 + g;
                int kb = kk + tg * 2;
                ah[mi][0] = *(const uint32_t*)(Ah + (r0 * 40 + kb) * 2);
                ah[mi][1] = *(const uint32_t*)(Ah + ((r0 + 8) * 40 + kb) * 2);
                ah[mi][2] = *(const uint32_t*)(Ah + (r0 * 40 + kb + 8) * 2);
                ah[mi][3] = *(const uint32_t*)(Ah + ((r0 + 8) * 40 + kb + 8) * 2);
                al[mi][0] = *(const uint32_t*)(Al + (r0 * 40 + kb) * 2);
                al[mi][1] = *(const uint32_t*)(Al + ((r0 + 8) * 40 + kb) * 2);
                al[mi][2] = *(const uint32_t*)(Al + (r0 * 40 + kb + 8) * 2);
                al[mi][3] = *(const uint32_t*)(Al + ((r0 + 8) * 40 + kb + 8) * 2);
            }
#pragma unroll
            for (int nt = 0; nt < NTILES; nt++) {
                int nr = warp_n * WN + nt * 8 + g;
                int kb = kk + tg * 2;
                uint32_t bh[2], bl[2];
                bh[0] = *(const uint32_t*)(Bh + (nr * 40 + kb) * 2);
                bh[1] = *(const uint32_t*)(Bh + (nr * 40 + kb + 8) * 2);
                bl[0] = *(const uint32_t*)(Bl + (nr * 40 + kb) * 2);
                bl[1] = *(const uint32_t*)(Bl + (nr * 40 + kb + 8) * 2);
#pragma unroll
                for (int mi = 0; mi < 2; mi++) {
                    mma16816(acc[mi][nt], ah[mi], bh);
                    mma16816(acc[mi][nt], ah[mi], bl);
                    mma16816(acc[mi][nt], al[mi], bh);
                }
            }
        }
    };

    int nstages = K / 32;
    float4 ar[4];
    loadA(0, ar);
    loadB(0, 0);
    storeA(ar, 0);
    CP_WAIT0();
    __syncthreads();
    for (int s = 0; s < nstages; s++) {
        int cur = s & 1, nxt = cur ^ 1;
        bool more = (s + 1) < nstages;
        if (more) {
            loadA((s + 1) * 32, ar);
            loadB((s + 1) * 32, nxt);
        }
        compute(cur);
        if (more) storeA(ar, nxt);
        CP_WAIT0();
        __syncthreads();
    }

    // ---- epilogue ----
    float sals[2][2], sald[2][2];
    sals[0][0] = sals[0][1] = sals[1][0] = sals[1][1] = 0.f;
    sald[0][0] = sald[0][1] = sald[1][0] = sald[1][1] = 0.f;
#pragma unroll
    for (int mi = 0; mi < 2; mi++) {
        int r0 = bm + warp_m * 32 + mi * 16 + g;
        int r1 = r0 + 8;
#pragma unroll
        for (int nt = 0; nt < NTILES; nt++) {
            int nloc = warp_n * WN + nt * 8 + tg * 2;
            int n0 = bn + nloc;
            float* cc = acc[mi][nt];
            float v00 = cc[0], v01 = cc[1], v10 = cc[2], v11 = cc[3];
            if (BIAS) {
                v00 += sBias[nloc]; v01 += sBias[nloc + 1];
                v10 += sBias[nloc]; v11 += sBias[nloc + 1];
            }
            if (RELU) {
                v00 = fmaxf(v00, 0.f); v01 = fmaxf(v01, 0.f);
                v10 = fmaxf(v10, 0.f); v11 = fmaxf(v11, 0.f);
            }
            if (r0 < M) *(float2*)(C + (size_t)r0 * NT + n0) = make_float2(v00, v01);
            if (r1 < M) *(float2*)(C + (size_t)r1 * NT + n0) = make_float2(v10, v11);
            if (HALS) {
                float a0 = sAsrc[nloc], a1 = sAsrc[nloc + 1];
                sals[mi][0] += v00 * a0 + v01 * a1;
                sals[mi][1] += v10 * a0 + v11 * a1;
                if (dual) {
                    float d0 = sAdst[nloc], d1 = sAdst[nloc + 1];
                    sald[mi][0] += v00 * d0 + v01 * d1;
                    sald[mi][1] += v10 * d0 + v11 * d1;
                }
            }
        }
    }
    if (HALS) {
        if (HALS == 1) {
            for (int i = tid; i < 128; i += 256) { sr1[i] = 0.f; sr2[i] = 0.f; }
            __syncthreads();
        }
#pragma unroll
        for (int mi = 0; mi < 2; mi++)
#pragma unroll
            for (int hf = 0; hf < 2; hf++) {
                float s = sals[mi][hf];
                s += __shfl_xor_sync(0xffffffffu, s, 1);
                s += __shfl_xor_sync(0xffffffffu, s, 2);
                float s2 = sald[mi][hf];
                s2 += __shfl_xor_sync(0xffffffffu, s2, 1);
                s2 += __shfl_xor_sync(0xffffffffu, s2, 2);
                if (tg == 0) {
                    int rloc = warp_m * 32 + mi * 16 + g + hf * 8;
                    int r = bm + rloc;
                    if (HALS == 4) {
                        if (r < M) {
                            int h = blockIdx.y * 2 + warp_n;
                            als[(size_t)r * 4 + h] = s;
                            if (dual) ald[(size_t)r * 4 + h] = s2;
                        }
                    } else {
                        atomicAdd(&sr1[rloc], s);
                        if (dual) atomicAdd(&sr2[rloc], s2);
                    }
                }
            }
        if (HALS == 1) {
            __syncthreads();
            for (int i = tid; i < 128; i += 256) {
                int r = bm + i;
                if (r < M) {
                    als[r] = sr1[i];
                    if (dual) ald[r] = sr2[i];
                }
            }
        }
    }
}

// ---------------- CSR build (batched over 3 edge types) ----------------
__global__ void k_zero(int* __restrict__ p, int n) {
    int i = blockIdx.x * blockDim.x + threadIdx.x;
    if (i < n) p[i] = 0;
}
__global__ void k_count3(const int* __restrict__ d0, const int* __restrict__ d1,
                         const int* __restrict__ d2, int E0, int E1, int E2,
                         int* __restrict__ cnt) {
    int t = blockIdx.y;
    const int* dst = (t == 0) ? d0 : (t == 1) ? d1 : d2;
    int E = (t == 0) ? E0 : (t == 1) ? E1 : E2;
    int i = blockIdx.x * 256 + threadIdx.x;
    if (i < E) atomicAdd(&cnt[t * NP + dst[i]], 1);
}
// 3 blocks, 1024 threads, 4 elems/thread (4096/tile)
__global__ void __launch_bounds__(1024) k_scan3(const int* __restrict__ cnt,
                                                int* __restrict__ rp, int n0, int n1, int n2) {
    int t = blockIdx.x;
    int n = (t == 0) ? n0 : (t == 1) ? n1 : n2;
    const int* c = cnt + t * NP;
    int* rowptr = rp + t * (NP + 1);
    __shared__ int wsum[32];
    __shared__ int carry_s;
    int tid = threadIdx.x, lane = tid & 31, wid = tid >> 5;
    if (tid == 0) { carry_s = 0; rowptr[0] = 0; }
    __syncthreads();
    for (int base = 0; base < n; base += 4096) {
        int c0 = carry_s;
        int i0 = base + tid * 4;
        int v[4];
#pragma unroll
        for (int k = 0; k < 4; k++) v[k] = (i0 + k < n) ? c[i0 + k] : 0;
        int incl[4];
        incl[0] = v[0];
        incl[1] = incl[0] + v[1];
        incl[2] = incl[1] + v[2];
        incl[3] = incl[2] + v[3];
        int tot = incl[3];
        int x = tot;
#pragma unroll
        for (int o = 1; o < 32; o <<= 1) {
            int y = __shfl_up_sync(0xffffffffu, x, o);
            if (lane >= o) x += y;
        }
        if (lane == 31) wsum[wid] = x;
        __syncthreads();
        if (wid == 0) {
            int s = wsum[lane];
#pragma unroll
            for (int o = 1; o < 32; o <<= 1) {
                int y = __shfl_up_sync(0xffffffffu, s, o);
                if (lane >= o) s += y;
            }
            wsum[lane] = s;
        }
        __syncthreads();
        int excl = (x - tot) + (wid ? wsum[wid - 1] : 0) + c0;
#pragma unroll
        for (int k = 0; k < 4; k++) {
            int i = i0 + k;
            if (i < n) rowptr[i + 1] = excl + incl[k];
        }
        __syncthreads();
        if (tid == 0) carry_s = c0 + wsum[31];
        __syncthreads();
    }
}
__global__ void k_scatter3(const int* __restrict__ s0p, const int* __restrict__ s1p,
                           const int* __restrict__ s2p, const int* __restrict__ d0,
                           const int* __restrict__ d1, const int* __restrict__ d2,
                           int E0, int E1, int E2, const int* __restrict__ rp,
                           int* __restrict__ off, int* __restrict__ srcp) {
    int t = blockIdx.y;
    const int* src = (t == 0) ? s0p : (t == 1) ? s1p : s2p;
    const int* dst = (t == 0) ? d0 : (t == 1) ? d1 : d2;
    int E = (t == 0) ? E0 : (t == 1) ? E1 : E2;
    int i = blockIdx.x * 256 + threadIdx.x;
    if (i < E) {
        int d = dst[i];
        int p = rp[t * (NP + 1) + d] + atomicAdd(&off[t * NP + d], 1);
        srcp[t * EMAX + p] = src[i];
    }
}

// ---------------- all 9 Vd vectors in one launch ----------------
__global__ void k_makeV_all(const float* __restrict__ W_hid, const float* __restrict__ ad_hid,
                            const float* __restrict__ W_out, const float* __restrict__ ad_out,
                            float* __restrict__ V) {
    int b = blockIdx.x;
    int k = threadIdx.x;
    if (b < 6) {
        const float* W = W_hid + (size_t)b * 65536;
        const float* a = ad_hid + (size_t)b * 256;
        for (int h = 0; h < 4; h++) {
            float s = 0.f;
            for (int c = 0; c < 64; c++) s = fmaf(W[k * 256 + h * 64 + c], a[h * 64 + c], s);
            V[b * 1024 + k * 4 + h] = s;
        }
    } else {
        const float* W = W_out + (size_t)(b - 6) * 16384;
        const float* a = ad_out + (size_t)(b - 6) * 64;
        float s = 0.f;
        for (int c = 0; c < 64; c++) s = fmaf(W[k * 64 + c], a[c], s);
        V[b * 1024 + k] = s;
    }
}

// ---------------- fused ald + segment softmax + aggregation, H=4 ----------------
// Vd != nullptr: compute ald[w] = x_dst[w,:] @ V in-kernel; else read ald array.
__global__ void k_smagg4(const int* __restrict__ rowptr, const int* __restrict__ srcp,
                         const float* __restrict__ als, const float* __restrict__ ald,
                         const float* __restrict__ Vd, const float* __restrict__ xdst,
                         float* __restrict__ alpha, const float* __restrict__ hsrc,
                         const float* __restrict__ b1, const float* __restrict__ b2,
                         float* __restrict__ out, int Nd, int accum, int act) {
    __shared__ float Vs[1024];
    if (Vd) {
        for (int i = threadIdx.x; i < 1024; i += blockDim.x) Vs[i] = Vd[i];
        __syncthreads();
    }
    int w = (blockIdx.x * blockDim.x + threadIdx.x) >> 5;
    int lane = threadIdx.x & 31;
    if (w >= Nd) return;
    int s0 = rowptr[w], s1 = rowptr[w + 1];
    int deg = s1 - s0;
    const float NINF = __int_as_float(0xff800000u);

    float ad[4];
    if (Vd) {
        const float* xr = xdst + (size_t)w * 256;
        float p[4] = {0.f, 0.f, 0.f, 0.f};
#pragma unroll
        for (int tt = 0; tt < 8; tt++) {
            int k = lane + tt * 32;
            float x = xr[k];
#pragma unroll
            for (int h = 0; h < 4; h++) p[h] = fmaf(x, Vs[k * 4 + h], p[h]);
        }
#pragma unroll
        for (int h = 0; h < 4; h++) {
#pragma unroll
            for (int o = 16; o; o >>= 1) p[h] += __shfl_xor_sync(0xffffffffu, p[h], o);
            ad[h] = p[h];
        }
    } else {
#pragma unroll
        for (int h = 0; h < 4; h++) ad[h] = ald[(size_t)w * 4 + h];
    }

    int c0 = lane, c1 = lane + 32;
    int hsel = lane >> 4;
    float4 a0 = make_float4(0.f, 0.f, 0.f, 0.f), a1 = a0;

    if (deg <= 32) {
        // register-resident softmax (no alpha gmem traffic)
        int sreg = (lane < deg) ? srcp[s0 + lane] : 0;
        float ex[4];
#pragma unroll
        for (int h = 0; h < 4; h++) {
            float e = NINF;
            if (lane < deg) {
                e = als[(size_t)sreg * 4 + h] + ad[h];
                e = e > 0.f ? e : NEG * e;
            }
            ex[h] = e;
        }
        float inv[4];
#pragma unroll
        for (int h = 0; h < 4; h++) {
            float m = ex[h];
#pragma unroll
            for (int o = 16; o; o >>= 1) m = fmaxf(m, __shfl_xor_sync(0xffffffffu, m, o));
            float v = (lane < deg) ? __expf(ex[h] - m) : 0.f;
            ex[h] = v;
#pragma unroll
            for (int o = 16; o; o >>= 1) v += __shfl_xor_sync(0xffffffffu, v, o);
            inv[h] = 1.f / (v + 1e-16f);
        }
        float inv0 = hsel ? inv[1] : inv[0];
        float inv1 = hsel ? inv[3] : inv[2];
        for (int i = 0; i < deg; i++) {
            int s = __shfl_sync(0xffffffffu, sreg, i);
            float e0 = __shfl_sync(0xffffffffu, ex[0], i);
            float e1 = __shfl_sync(0xffffffffu, ex[1], i);
            float e2 = __shfl_sync(0xffffffffu, ex[2], i);
            float e3 = __shfl_sync(0xffffffffu, ex[3], i);
            float w0 = (hsel ? e1 : e0) * inv0;
            float w1 = (hsel ? e3 : e2) * inv1;
            const float4* hr = (const float4*)(hsrc + (size_t)s * 256);
            float4 v0 = hr[c0], v1 = hr[c1];
            a0.x = fmaf(v0.x, w0, a0.x); a0.y = fmaf(v0.y, w0, a0.y);
            a0.z = fmaf(v0.z, w0, a0.z); a0.w = fmaf(v0.w, w0, a0.w);
            a1.x = fmaf(v1.x, w1, a1.x); a1.y = fmaf(v1.y, w1, a1.y);
            a1.z = fmaf(v1.z, w1, a1.z); a1.w = fmaf(v1.w, w1, a1.w);
        }
    } else {
        // gmem fallback for high-degree nodes
        float mx[4], sm[4], inv[4];
#pragma unroll
        for (int h = 0; h < 4; h++) { mx[h] = NINF; sm[h] = 0.f; }
        for (int j = s0 + lane; j < s1; j += 32) {
            int s = srcp[j];
#pragma unroll
            for (int h = 0; h < 4; h++) {
                float e = als[(size_t)s * 4 + h] + ad[h];
                e = e > 0.f ? e : NEG * e;
                alpha[(size_t)j * 4 + h] = e;
                mx[h] = fmaxf(mx[h], e);
            }
        }
#pragma unroll
        for (int h = 0; h < 4; h++)
#pragma unroll
            for (int o = 16; o; o >>= 1)
                mx[h] = fmaxf(mx[h], __shfl_xor_sync(0xffffffffu, mx[h], o));
        for (int j = s0 + lane; j < s1; j += 32) {
#pragma unroll
            for (int h = 0; h < 4; h++) {
                float e2 = __expf(alpha[(size_t)j * 4 + h] - mx[h]);
                alpha[(size_t)j * 4 + h] = e2;
                sm[h] += e2;
            }
        }
#pragma unroll
        for (int h = 0; h < 4; h++) {
#pragma unroll
            for (int o = 16; o; o >>= 1) sm[h] += __shfl_xor_sync(0xffffffffu, sm[h], o);
            inv[h] = 1.f / (sm[h] + 1e-16f);
        }
        float inv0 = inv[hsel], inv1 = inv[hsel + 2];
        for (int j = s0; j < s1; j++) {
            int s = srcp[j];
            float4 al = *(const float4*)(alpha + (size_t)j * 4);
            const float4* hr = (const float4*)(hsrc + (size_t)s * 256);
            float4 v0 = hr[c0], v1 = hr[c1];
            float w0 = (hsel ? al.y : al.x) * inv0;
            float w1 = (hsel ? al.w : al.z) * inv1;
            a0.x = fmaf(v0.x, w0, a0.x); a0.y = fmaf(v0.y, w0, a0.y);
            a0.z = fmaf(v0.z, w0, a0.z); a0.w = fmaf(v0.w, w0, a0.w);
            a1.x = fmaf(v1.x, w1, a1.x); a1.y = fmaf(v1.y, w1, a1.y);
            a1.z = fmaf(v1.z, w1, a1.z); a1.w = fmaf(v1.w, w1, a1.w);
        }
    }

    float4* orow = (float4*)(out + (size_t)w * 256);
    float4 o0, o1;
    if (accum) {
        o0 = orow[c0]; o1 = orow[c1];
        o0.x += a0.x; o0.y += a0.y; o0.z += a0.z; o0.w += a0.w;
        o1.x += a1.x; o1.y += a1.y; o1.z += a1.z; o1.w += a1.w;
    } else {
        const float4* B1 = (const float4*)b1;
        float4 bb0 = B1[c0], bb1 = B1[c1];
        if (b2) {
            const float4* B2 = (const float4*)b2;
            float4 t0 = B2[c0], t1 = B2[c1];
            bb0.x += t0.x; bb0.y += t0.y; bb0.z += t0.z; bb0.w += t0.w;
            bb1.x += t1.x; bb1.y += t1.y; bb1.z += t1.z; bb1.w += t1.w;
        }
        o0 = make_float4(a0.x + bb0.x, a0.y + bb0.y, a0.z + bb0.z, a0.w + bb0.w);
        o1 = make_float4(a1.x + bb1.x, a1.y + bb1.y, a1.z + bb1.z, a1.w + bb1.w);
    }
    if (act) {
        o0.x = eluf(o0.x); o0.y = eluf(o0.y); o0.z = eluf(o0.z); o0.w = eluf(o0.w);
        o1.x = eluf(o1.x); o1.y = eluf(o1.y); o1.z = eluf(o1.z); o1.w = eluf(o1.w);
    }
    orow[c0] = o0;
    orow[c1] = o1;
}

// ---------------- fused ald + segment softmax + aggregation, H=1, 64 cols ----------------
__global__ void k_smagg1(const int* __restrict__ rowptr, const int* __restrict__ srcp,
                         const float* __restrict__ als, const float* __restrict__ ald,
                         const float* __restrict__ Vd, const float* __restrict__ xdst,
                         float* __restrict__ alpha, const float* __restrict__ hsrc,
                         const float* __restrict__ b1, const float* __restrict__ b2,
                         float* __restrict__ out, int Nd, int accum) {
    __shared__ float Vs[256];
    if (Vd) {
        for (int i = threadIdx.x; i < 256; i += blockDim.x) Vs[i] = Vd[i];
        __syncthreads();
    }
    int w = (blockIdx.x * blockDim.x + threadIdx.x) >> 5;
    int lane = threadIdx.x & 31;
    if (w >= Nd) return;
    int s0 = rowptr[w], s1 = rowptr[w + 1];
    int deg = s1 - s0;
    const float NINF = __int_as_float(0xff800000u);

    float ad;
    if (Vd) {
        const float* xr = xdst + (size_t)w * 256;
        float p = 0.f;
#pragma unroll
        for (int tt = 0; tt < 8; tt++) {
            int k = lane + tt * 32;
            p = fmaf(xr[k], Vs[k], p);
        }
#pragma unroll
        for (int o = 16; o; o >>= 1) p += __shfl_xor_sync(0xffffffffu, p, o);
        ad = p;
    } else {
        ad = ald[w];
    }

    float a0 = 0.f, a1 = 0.f;
    if (deg <= 32) {
        int sreg = (lane < deg) ? srcp[s0 + lane] : 0;
        float e = NINF;
        if (lane < deg) {
            e = als[sreg] + ad;
            e = e > 0.f ? e : NEG * e;
        }
        float m = e;
#pragma unroll
        for (int o = 16; o; o >>= 1) m = fmaxf(m, __shfl_xor_sync(0xffffffffu, m, o));
        float ex = (lane < deg) ? __expf(e - m) : 0.f;
        float sm = ex;
#pragma unroll
        for (int o = 16; o; o >>= 1) sm += __shfl_xor_sync(0xffffffffu, sm, o);
        float inv = 1.f / (sm + 1e-16f);
        for (int i = 0; i < deg; i++) {
            int s = __shfl_sync(0xffffffffu, sreg, i);
            float al = __shfl_sync(0xffffffffu, ex, i) * inv;
            const float* hr = hsrc + (size_t)s * 64;
            a0 = fmaf(hr[lane], al, a0);
            a1 = fmaf(hr[lane + 32], al, a1);
        }
    } else {
        float mx = NINF, sm = 0.f;
        for (int j = s0 + lane; j < s1; j += 32) {
            int s = srcp[j];
            float e = als[s] + ad;
            e = e > 0.f ? e : NEG * e;
            alpha[j] = e;
            mx = fmaxf(mx, e);
        }
#pragma unroll
        for (int o = 16; o; o >>= 1) mx = fmaxf(mx, __shfl_xor_sync(0xffffffffu, mx, o));
        for (int j = s0 + lane; j < s1; j += 32) {
            float ex = __expf(alpha[j] - mx);
            alpha[j] = ex;
            sm += ex;
        }
#pragma unroll
        for (int o = 16; o; o >>= 1) sm += __shfl_xor_sync(0xffffffffu, sm, o);
        float inv = 1.f / (sm + 1e-16f);
        for (int j = s0; j < s1; j++) {
            int s = srcp[j];
            float al = alpha[j] * inv;
            const float* hr = hsrc + (size_t)s * 64;
            a0 = fmaf(hr[lane], al, a0);
            a1 = fmaf(hr[lane + 32], al, a1);
        }
    }
    float* orow = out + (size_t)w * 64;
    if (accum) {
        orow[lane] += a0;
        orow[lane + 32] += a1;
    } else {
        float bb0 = b1[lane], bb1 = b1[lane + 32];
        if (b2) { bb0 += b2[lane]; bb1 += b2[lane + 32]; }
        orow[lane] = a0 + bb0;
        orow[lane + 32] = a1 + bb1;
    }
}

// =====================================================================
extern "C" void kernel_launch(void* const* d_in, const int* in_sizes, int n_in,
                              void* d_out, int out_size) {
    const float* x_drug = (const float*)d_in[0];
    const float* x_prot = (const float*)d_in[1];
    const int* srcA[3] = {(const int*)d_in[2], (const int*)d_in[4], (const int*)d_in[6]};
    const int* dstA[3] = {(const int*)d_in[3], (const int*)d_in[5], (const int*)d_in[7]};
    const float* linW_d = (const float*)d_in[8];
    const float* linb_d = (const float*)d_in[9];
    const float* linW_p = (const float*)d_in[10];
    const float* linb_p = (const float*)d_in[11];
    const float* W_hid = (const float*)d_in[12];
    const float* as_hid = (const float*)d_in[13];
    const float* ad_hid = (const float*)d_in[14];
    const float* b_hid = (const float*)d_in[15];
    const float* W_out = (const float*)d_in[16];
    const float* as_out = (const float*)d_in[17];
    const float* ad_out = (const float*)d_in[18];
    const float* b_out = (const float*)d_in[19];
    float* outp = (float*)d_out;

    int E[3] = {in_sizes[2], in_sizes[4], in_sizes[6]};
    int maxE = E[0] > E[1] ? E[0] : E[1];
    if (E[2] > maxE) maxE = E[2];

    float *xdb, *xpb, *hb, *alpha, *als, *ald, *V;
    int *rp, *sp, *cnt;
    __nv_bfloat16 *whi, *wlo;
    cudaGetSymbolAddress((void**)&xdb, g_xd);
    cudaGetSymbolAddress((void**)&xpb, g_xp);
    cudaGetSymbolAddress((void**)&hb, g_h);
    cudaGetSymbolAddress((void**)&alpha, g_alpha);
    cudaGetSymbolAddress((void**)&als, g_als);
    cudaGetSymbolAddress((void**)&ald, g_ald);
    cudaGetSymbolAddress((void**)&V, g_V);
    cudaGetSymbolAddress((void**)&rp, g_rowptr);
    cudaGetSymbolAddress((void**)&sp, g_srcp);
    cudaGetSymbolAddress((void**)&cnt, g_cnt);
    cudaGetSymbolAddress((void**)&whi, g_whi);
    cudaGetSymbolAddress((void**)&wlo, g_wlo);

    float* xd[2] = {xdb, xdb + (size_t)ND * HIDW};
    float* xp[2] = {xpb, xpb + (size_t)NP * HIDW};
    int* rowptr[3] = {rp, rp + (NP + 1), rp + 2 * (NP + 1)};
    int* srcp[3] = {sp, sp + EMAX, sp + 2 * EMAX};

    const int SM128 = 2048 + 4 * (128 * 40 * 2) + 4 * (128 * 40 * 2);  // 83968
    const int SM64 = 2048 + 4 * (128 * 40 * 2) + 4 * (64 * 40 * 2);    // 63488
    cudaFuncSetAttribute(k_mma<128, true, true, 0>,
                         cudaFuncAttributeMaxDynamicSharedMemorySize, SM128);
    cudaFuncSetAttribute(k_mma<128, false, false, 4>,
                         cudaFuncAttributeMaxDynamicSharedMemorySize, SM128);
    cudaFuncSetAttribute(k_mma<64, false, false, 1>,
                         cudaFuncAttributeMaxDynamicSharedMemorySize, SM64);

    size_t o_lind = 0;
    size_t o_linp = 32768;
    size_t o_hid0 = 98304;
    size_t o_out0 = 491520;

    int ebx = (maxE + 255) / 256;

    // ---- weight prep: single launch ----
    {
        dim3 gw(256, 11);
        k_splitW_all<<<gw, 256>>>(linW_d, linW_p, W_hid, W_out, whi, wlo);
    }
    // ---- CSR count+scan ----
    k_zero<<<(3 * NP + 255) / 256, 256>>>(cnt, 3 * NP);
    {
        dim3 gc(ebx, 3);
        k_count3<<<gc, 256>>>(dstA[0], dstA[1], dstA[2], E[0], E[1], E[2], cnt);
    }
    k_scan3<<<3, 1024>>>(cnt, rp, NP, ND, NP);
    k_zero<<<(3 * NP + 255) / 256, 256>>>(cnt, 3 * NP);
    // ---- protein input projection ----
    {
        dim3 gp((NP + 127) / 128, 2);
        k_mma<128, true, true, 0><<<gp, 256, SM128>>>(
            x_prot, whi + o_linp, wlo + o_linp, linb_p, nullptr, nullptr, xp[0], nullptr,
            nullptr, NP, 256, 256);
    }
    // ---- CSR scatter ----
    {
        dim3 gs(ebx, 3);
        k_scatter3<<<gs, 256>>>(srcA[0], srcA[1], srcA[2], dstA[0], dstA[1], dstA[2], E[0],
                                E[1], E[2], rp, cnt, sp);
    }
    // ---- drug input projection ----
    {
        dim3 gd((ND + 127) / 128, 2);
        k_mma<128, true, true, 0><<<gd, 256, SM128>>>(
            x_drug, whi + o_lind, wlo + o_lind, linb_d, nullptr, nullptr, xd[0], nullptr,
            nullptr, ND, 128, 256);
    }
    k_makeV_all<<<9, 256>>>(W_hid, ad_hid, W_out, ad_out, V);

    int cur = 0, nxt = 1;

    // ---- hidden layers ----
    for (int l = 0; l < 2; l++) {
        const float* b0 = b_hid + (size_t)(l * 3 + 0) * HIDW;
        const float* b1_ = b_hid + (size_t)(l * 3 + 1) * HIDW;
        const float* b2 = b_hid + (size_t)(l * 3 + 2) * HIDW;
        // drug->protein (et 0): GEMM(xd) fused als; smagg computes ald from xp & V
        {
            int idx = l * 3 + 0;
            const __nv_bfloat16* bh = whi + o_hid0 + (size_t)idx * 65536;
            const __nv_bfloat16* bl = wlo + o_hid0 + (size_t)idx * 65536;
            dim3 gg((ND + 127) / 128, 2);
            k_mma<128, false, false, 4><<<gg, 256, SM128>>>(
                xd[cur], bh, bl, nullptr, as_hid + (size_t)idx * 256, nullptr, hb, als, nullptr,
                ND, 256, 256);
            k_smagg4<<<(NP + 7) / 8, 256>>>(rowptr[0], srcp[0], als, nullptr, V + idx * 1024,
                                            xp[cur], alpha, hb, b0, b2, xp[nxt], NP, 0, 0);
        }
        // protein->protein (et 2): dual GEMM gives als+ald; accumulate + elu
        {
            int idx = l * 3 + 2;
            const __nv_bfloat16* bh = whi + o_hid0 + (size_t)idx * 65536;
            const __nv_bfloat16* bl = wlo + o_hid0 + (size_t)idx * 65536;
            dim3 gg((NP + 127) / 128, 2);
            k_mma<128, false, false, 4><<<gg, 256, SM128>>>(
                xp[cur], bh, bl, nullptr, as_hid + (size_t)idx * 256,
                ad_hid + (size_t)idx * 256, hb, als, ald, NP, 256, 256);
            k_smagg4<<<(NP + 7) / 8, 256>>>(rowptr[2], srcp[2], als, ald, nullptr, nullptr,
                                            alpha, hb, nullptr, nullptr, xp[nxt], NP, 1, 1);
        }
        // protein->drug (et 1): GEMM(xp); smagg computes ald from xd & V
        {
            int idx = l * 3 + 1;
            const __nv_bfloat16* bh = whi + o_hid0 + (size_t)idx * 65536;
            const __nv_bfloat16* bl = wlo + o_hid0 + (size_t)idx * 65536;
            dim3 gg((NP + 127) / 128, 2);
            k_mma<128, false, false, 4><<<gg, 256, SM128>>>(
                xp[cur], bh, bl, nullptr, as_hid + (size_t)idx * 256, nullptr, hb, als, nullptr,
                NP, 256, 256);
            k_smagg4<<<(ND + 7) / 8, 256>>>(rowptr[1], srcp[1], als, nullptr, V + idx * 1024,
                                            xd[cur], alpha, hb, b1_, nullptr, xd[nxt], ND, 0,
                                            1);
        }
        cur = nxt;
        nxt = 1 - nxt;
    }

    // ---- output layer (H=1, OUT=64) ----
    float* od = outp;
    float* op = outp + (size_t)ND * OUTC;
    // et 0: drug->protein
    {
        const __nv_bfloat16* bh = whi + o_out0;
        const __nv_bfloat16* bl = wlo + o_out0;
        dim3 gg((ND + 127) / 128, 1);
        k_mma<64, false, false, 1><<<gg, 256, SM64>>>(
            xd[cur], bh, bl, nullptr, as_out, nullptr, hb, als, nullptr, ND, 256, 64);
        k_smagg1<<<(NP + 7) / 8, 256>>>(rowptr[0], srcp[0], als, nullptr, V + 6 * 1024,
                                        xp[cur], alpha, hb, b_out + 0 * OUTC,
                                        b_out + 2 * OUTC, op, NP, 0);
    }
    // et 2: protein->protein (dual)
    {
        const __nv_bfloat16* bh = whi + o_out0 + 2 * 16384;
        const __nv_bfloat16* bl = wlo + o_out0 + 2 * 16384;
        dim3 gg((NP + 127) / 128, 1);
        k_mma<64, false, false, 1><<<gg, 256, SM64>>>(
            xp[cur], bh, bl, nullptr, as_out + 2 * OUTC, ad_out + 2 * OUTC, hb, als, ald, NP,
            256, 64);
        k_smagg1<<<(NP + 7) / 8, 256>>>(rowptr[2], srcp[2], als, ald, nullptr, nullptr, alpha,
                                        hb, nullptr, nullptr, op, NP, 1);
    }
    // et 1: protein->drug
    {
        const __nv_bfloat16* bh = whi + o_out0 + 1 * 16384;
        const __nv_bfloat16* bl = wlo + o_out0 + 1 * 16384;
        dim3 gg((NP + 127) / 128, 1);
        k_mma<64, false, false, 1><<<gg, 256, SM64>>>(
            xp[cur], bh, bl, nullptr, as_out + 1 * OUTC, nullptr, hb, als, nullptr, NP, 256,
            64);
        k_smagg1<<<(ND + 7) / 8, 256>>>(rowptr[1], srcp[1], als, nullptr, V + 7 * 1024,
                                        xd[cur], alpha, hb, b_out + 1 * OUTC, nullptr, od, ND,
                                        0);
    }

    (void)n_in;
    (void)out_size;
}

// round 10
// speedup vs baseline: 2.8339x; 1.1337x over previous
#include <cuda_runtime.h>
#include <cuda_bf16.h>
#include <cstdint>

// Problem constants (fixed shapes)
#define ND 20000
#define NP 40000
#define EMAX 300000
#define HIDW 256
#define OUTC 64
#define NEG 0.2f

// ---------------- static device scratch (allocation-free rule) ----------------
__device__ float g_xd[2][ND * HIDW];
__device__ float g_xp[2][NP * HIDW];
__device__ float g_h[3][NP * HIDW];            // per-edge-type h_src
__device__ float g_alpha[3 * EMAX * 4];        // per-edge-type softmax fallback
__device__ float g_als[3 * NP * 4];            // per-edge-type src logits
__device__ float g_ald[NP * 4];                // dual (et2) dst logits
__device__ float g_V[9 * 1024];
__device__ int   g_rowptr[3 * (NP + 1)];
__device__ int   g_srcp[3 * EMAX];
__device__ int   g_cnt[3 * NP];
#define WTOT 540672
__device__ __nv_bfloat16 g_whi[WTOT];
__device__ __nv_bfloat16 g_wlo[WTOT];

// ======================= helpers =======================
__device__ __forceinline__ uint32_t smem_u32(const void* p) {
    uint32_t a;
    asm("{ .reg .u64 t; cvta.to.shared.u64 t, %1; cvt.u32.u64 %0, t; }" : "=r"(a) : "l"(p));
    return a;
}
__device__ __forceinline__ void cp_async8(uint32_t dst, const void* src) {
    asm volatile("cp.async.ca.shared.global [%0], [%1], 8;" :: "r"(dst), "l"(src));
}
#define CP_COMMIT() asm volatile("cp.async.commit_group;" ::: "memory")
#define CP_WAIT0()  asm volatile("cp.async.wait_group 0;" ::: "memory")

__device__ __forceinline__ void mma16816(float* c, const uint32_t* a, const uint32_t* b) {
    asm volatile(
        "mma.sync.aligned.m16n8k16.row.col.f32.bf16.bf16.f32 "
        "{%0,%1,%2,%3}, {%4,%5,%6,%7}, {%8,%9}, {%0,%1,%2,%3};"
        : "+f"(c[0]), "+f"(c[1]), "+f"(c[2]), "+f"(c[3])
        : "r"(a[0]), "r"(a[1]), "r"(a[2]), "r"(a[3]), "r"(b[0]), "r"(b[1]));
}

__device__ __forceinline__ uint32_t pack_bf2(float x, float y) {
    __nv_bfloat162 t = __floats2bfloat162_rn(x, y);
    return *reinterpret_cast<uint32_t*>(&t);
}
__device__ __forceinline__ float eluf(float v) { return v > 0.f ? v : expm1f(v); }

// ---------------- all-weights pre-transpose + bf16 split in ONE launch ----------------
__global__ void k_splitW_all(const float* __restrict__ linW_d, const float* __restrict__ linW_p,
                             const float* __restrict__ W_hid, const float* __restrict__ W_out,
                             __nv_bfloat16* __restrict__ hi, __nv_bfloat16* __restrict__ lo) {
    int id = blockIdx.y;
    int i = blockIdx.x * 256 + threadIdx.x;
    const float* W;
    size_t off;
    int K, N;
    if (id == 0) { W = linW_d; off = 0; K = 128; N = 256; }
    else if (id == 1) { W = linW_p; off = 32768; K = 256; N = 256; }
    else if (id < 8) {
        W = W_hid + (size_t)(id - 2) * 65536; off = 98304 + (size_t)(id - 2) * 65536;
        K = 256; N = 256;
    } else {
        W = W_out + (size_t)(id - 8) * 16384; off = 491520 + (size_t)(id - 8) * 16384;
        K = 256; N = 64;
    }
    if (i >= N * K) return;
    int n = i / K, k = i % K;
    float v = W[(size_t)k * N + n];
    __nv_bfloat16 h = __float2bfloat16(v);
    hi[off + i] = h;
    lo[off + i] = __float2bfloat16(v - __bfloat162float(h));
}

// ============ batched mma.sync GEMM (cfg selected by blockIdx.z) ============
struct GemmCfg {
    const float* A;
    const __nv_bfloat16* Bhi;
    const __nv_bfloat16* Blo;
    const float* bias;
    const float* asrc;
    const float* adst;
    float* C;
    float* als;
    float* ald;
    int M;
    int K;
};
struct GemmCfg3 { GemmCfg c[3]; };

template <int BN, bool BIAS, bool RELU, int HALS>
__global__ void __launch_bounds__(256) k_mma(GemmCfg3 P) {
    GemmCfg cfg = P.c[blockIdx.z];
    const int M = cfg.M, K = cfg.K;
    if ((int)blockIdx.x * 128 >= M) return;

    extern __shared__ char smem[];
    constexpr int WN = BN / 2;
    constexpr int NTILES = WN / 8;
    constexpr int ABUF = 128 * 40 * 2;
    constexpr int BBUF = BN * 40 * 2;
    constexpr int S_A = 2048;
    constexpr int S_B = S_A + 4 * ABUF;
    float* sBias = (float*)(smem);
    float* sAsrc = (float*)(smem + 512);
    float* sAdst = (float*)(smem + 1024);
    __shared__ float sr1[128];
    __shared__ float sr2[128];

    const bool dual = (HALS != 0) && (cfg.adst != nullptr);

    int tid = threadIdx.x;
    int wid = tid >> 5, lane = tid & 31;
    int g = lane >> 2, tg = lane & 3;
    int warp_m = wid & 3, warp_n = wid >> 2;
    int bm = blockIdx.x * 128, bn = blockIdx.y * BN;

    if (BIAS)
        for (int i = tid; i < BN; i += 256) sBias[i] = cfg.bias[bn + i];
    if (HALS) {
        for (int i = tid; i < BN; i += 256) sAsrc[i] = cfg.asrc[bn + i];
        if (dual)
            for (int i = tid; i < BN; i += 256) sAdst[i] = cfg.adst[bn + i];
    }

    int arow = tid >> 1;
    int akq = (tid & 1) * 16;
    bool aval_base = (bm + arow) < M;
    constexpr int CH = BN * 8 / 256;

    float acc[2][NTILES][4];
#pragma unroll
    for (int mi = 0; mi < 2; mi++)
#pragma unroll
        for (int nt = 0; nt < NTILES; nt++)
#pragma unroll
            for (int q = 0; q < 4; q++) acc[mi][nt][q] = 0.f;

    uint32_t sbase = smem_u32(smem);
    const float* A = cfg.A;
    const __nv_bfloat16* Bthi = cfg.Bhi;
    const __nv_bfloat16* Btlo = cfg.Blo;

    auto loadA = [&](int k0, float4* ar) {
        const float* src = A + (size_t)(bm + arow) * K + k0 + akq;
#pragma unroll
        for (int i = 0; i < 4; i++)
            ar[i] = aval_base ? ((const float4*)src)[i] : make_float4(0.f, 0.f, 0.f, 0.f);
    };
    auto storeA = [&](const float4* ar, int buf) {
        char* dh = smem + S_A + buf * 2 * ABUF;
        char* dl = dh + ABUF;
#pragma unroll
        for (int i = 0; i < 4; i++) {
            float4 f = ar[i];
            __nv_bfloat16 hx = __float2bfloat16(f.x), hy = __float2bfloat16(f.y);
            __nv_bfloat16 hz = __float2bfloat16(f.z), hw = __float2bfloat16(f.w);
            __nv_bfloat162 H01(hx, hy), H23(hz, hw);
            uint32_t h01 = *(uint32_t*)&H01, h23 = *(uint32_t*)&H23;
            uint32_t l01 = pack_bf2(f.x - __bfloat162float(hx), f.y - __bfloat162float(hy));
            uint32_t l23 = pack_bf2(f.z - __bfloat162float(hz), f.w - __bfloat162float(hw));
            int off = (arow * 40 + akq + i * 4) * 2;
            *(uint2*)(dh + off) = make_uint2(h01, h23);
            *(uint2*)(dl + off) = make_uint2(l01, l23);
        }
    };
    auto loadB = [&](int k0, int buf) {
        uint32_t dh = sbase + S_B + buf * 2 * BBUF;
        uint32_t dl = dh + BBUF;
#pragma unroll
        for (int i = 0; i < CH; i++) {
            int c = tid + i * 256;
            int row = c >> 3, kc = c & 7;
            size_t go = (size_t)(bn + row) * K + k0 + kc * 4;
            uint32_t so = row * 80 + kc * 8;
            cp_async8(dh + so, Bthi + go);
            cp_async8(dl + so, Btlo + go);
        }
        CP_COMMIT();
    };
    auto compute = [&](int buf) {
        const char* Ah = smem + S_A + buf * 2 * ABUF;
        const char* Al = Ah + ABUF;
        const char* Bh = smem + S_B + buf * 2 * BBUF;
        const char* Bl = Bh + BBUF;
#pragma unroll
        for (int kk = 0; kk < 32; kk += 16) {
            uint32_t ah[2][4], al[2][4];
#pragma unroll
            for (int mi = 0; mi < 2; mi++) {
                int r0 = warp_m * 32 + mi * 16 + g;
                int kb = kk + tg * 2;
                ah[mi][0] = *(const uint32_t*)(Ah + (r0 * 40 + kb) * 2);
                ah[mi][1] = *(const uint32_t*)(Ah + ((r0 + 8) * 40 + kb) * 2);
                ah[mi][2] = *(const uint32_t*)(Ah + (r0 * 40 + kb + 8) * 2);
                ah[mi][3] = *(const uint32_t*)(Ah + ((r0 + 8) * 40 + kb + 8) * 2);
                al[mi][0] = *(const uint32_t*)(Al + (r0 * 40 + kb) * 2);
                al[mi][1] = *(const uint32_t*)(Al + ((r0 + 8) * 40 + kb) * 2);
                al[mi][2] = *(const uint32_t*)(Al + (r0 * 40 + kb + 8) * 2);
                al[mi][3] = *(const uint32_t*)(Al + ((r0 + 8) * 40 + kb + 8) * 2);
            }
#pragma unroll
            for (int nt = 0; nt < NTILES; nt++) {
                int nr = warp_n * WN + nt * 8 + g;
                int kb = kk + tg * 2;
                uint32_t bh[2], bl[2];
                bh[0] = *(const uint32_t*)(Bh + (nr * 40 + kb) * 2);
                bh[1] = *(const uint32_t*)(Bh + (nr * 40 + kb + 8) * 2);
                bl[0] = *(const uint32_t*)(Bl + (nr * 40 + kb) * 2);
                bl[1] = *(const uint32_t*)(Bl + (nr * 40 + kb + 8) * 2);
#pragma unroll
                for (int mi = 0; mi < 2; mi++) {
                    mma16816(acc[mi][nt], ah[mi], bh);
                    mma16816(acc[mi][nt], ah[mi], bl);
                    mma16816(acc[mi][nt], al[mi], bh);
                }
            }
        }
    };

    int nstages = K / 32;
    float4 ar[4];
    loadA(0, ar);
    loadB(0, 0);
    storeA(ar, 0);
    CP_WAIT0();
    __syncthreads();
    for (int s = 0; s < nstages; s++) {
        int cur = s & 1, nxt = cur ^ 1;
        bool more = (s + 1) < nstages;
        if (more) {
            loadA((s + 1) * 32, ar);
            loadB((s + 1) * 32, nxt);
        }
        compute(cur);
        if (more) storeA(ar, nxt);
        CP_WAIT0();
        __syncthreads();
    }

    // ---- epilogue ----
    const int NT = (BN == 128) ? 256 : 64;
    float sals[2][2], sald[2][2];
    sals[0][0] = sals[0][1] = sals[1][0] = sals[1][1] = 0.f;
    sald[0][0] = sald[0][1] = sald[1][0] = sald[1][1] = 0.f;
#pragma unroll
    for (int mi = 0; mi < 2; mi++) {
        int r0 = bm + warp_m * 32 + mi * 16 + g;
        int r1 = r0 + 8;
#pragma unroll
        for (int nt = 0; nt < NTILES; nt++) {
            int nloc = warp_n * WN + nt * 8 + tg * 2;
            int n0 = bn + nloc;
            float* cc = acc[mi][nt];
            float v00 = cc[0], v01 = cc[1], v10 = cc[2], v11 = cc[3];
            if (BIAS) {
                v00 += sBias[nloc]; v01 += sBias[nloc + 1];
                v10 += sBias[nloc]; v11 += sBias[nloc + 1];
            }
            if (RELU) {
                v00 = fmaxf(v00, 0.f); v01 = fmaxf(v01, 0.f);
                v10 = fmaxf(v10, 0.f); v11 = fmaxf(v11, 0.f);
            }
            if (r0 < M) *(float2*)(cfg.C + (size_t)r0 * NT + n0) = make_float2(v00, v01);
            if (r1 < M) *(float2*)(cfg.C + (size_t)r1 * NT + n0) = make_float2(v10, v11);
            if (HALS) {
                float a0 = sAsrc[nloc], a1 = sAsrc[nloc + 1];
                sals[mi][0] += v00 * a0 + v01 * a1;
                sals[mi][1] += v10 * a0 + v11 * a1;
                if (dual) {
                    float d0 = sAdst[nloc], d1 = sAdst[nloc + 1];
                    sald[mi][0] += v00 * d0 + v01 * d1;
                    sald[mi][1] += v10 * d0 + v11 * d1;
                }
            }
        }
    }
    if (HALS) {
        if (HALS == 1) {
            for (int i = tid; i < 128; i += 256) { sr1[i] = 0.f; sr2[i] = 0.f; }
            __syncthreads();
        }
#pragma unroll
        for (int mi = 0; mi < 2; mi++)
#pragma unroll
            for (int hf = 0; hf < 2; hf++) {
                float s = sals[mi][hf];
                s += __shfl_xor_sync(0xffffffffu, s, 1);
                s += __shfl_xor_sync(0xffffffffu, s, 2);
                float s2 = sald[mi][hf];
                s2 += __shfl_xor_sync(0xffffffffu, s2, 1);
                s2 += __shfl_xor_sync(0xffffffffu, s2, 2);
                if (tg == 0) {
                    int rloc = warp_m * 32 + mi * 16 + g + hf * 8;
                    int r = bm + rloc;
                    if (HALS == 4) {
                        if (r < M) {
                            int h = blockIdx.y * 2 + warp_n;
                            cfg.als[(size_t)r * 4 + h] = s;
                            if (dual) cfg.ald[(size_t)r * 4 + h] = s2;
                        }
                    } else {
                        atomicAdd(&sr1[rloc], s);
                        if (dual) atomicAdd(&sr2[rloc], s2);
                    }
                }
            }
        if (HALS == 1) {
            __syncthreads();
            for (int i = tid; i < 128; i += 256) {
                int r = bm + i;
                if (r < M) {
                    cfg.als[r] = sr1[i];
                    if (dual) cfg.ald[r] = sr2[i];
                }
            }
        }
    }
}

// ---------------- CSR build (batched over 3 edge types) ----------------
__global__ void k_zero(int* __restrict__ p, int n) {
    int i = blockIdx.x * blockDim.x + threadIdx.x;
    if (i < n) p[i] = 0;
}
__global__ void k_count3(const int* __restrict__ d0, const int* __restrict__ d1,
                         const int* __restrict__ d2, int E0, int E1, int E2,
                         int* __restrict__ cnt) {
    int t = blockIdx.y;
    const int* dst = (t == 0) ? d0 : (t == 1) ? d1 : d2;
    int E = (t == 0) ? E0 : (t == 1) ? E1 : E2;
    int i = blockIdx.x * 256 + threadIdx.x;
    if (i < E) atomicAdd(&cnt[t * NP + dst[i]], 1);
}
// 3 blocks, 1024 threads, 4 elems/thread; also re-zeroes cnt for the scatter pass
__global__ void __launch_bounds__(1024) k_scan3(int* __restrict__ cnt,
                                                int* __restrict__ rp, int n0, int n1, int n2) {
    int t = blockIdx.x;
    int n = (t == 0) ? n0 : (t == 1) ? n1 : n2;
    int* c = cnt + t * NP;
    int* rowptr = rp + t * (NP + 1);
    __shared__ int wsum[32];
    __shared__ int carry_s;
    int tid = threadIdx.x, lane = tid & 31, wid = tid >> 5;
    if (tid == 0) { carry_s = 0; rowptr[0] = 0; }
    __syncthreads();
    for (int base = 0; base < n; base += 4096) {
        int c0 = carry_s;
        int i0 = base + tid * 4;
        int v[4];
#pragma unroll
        for (int k = 0; k < 4; k++) {
            v[k] = (i0 + k < n) ? c[i0 + k] : 0;
            if (i0 + k < n) c[i0 + k] = 0;
        }
        int incl[4];
        incl[0] = v[0];
        incl[1] = incl[0] + v[1];
        incl[2] = incl[1] + v[2];
        incl[3] = incl[2] + v[3];
        int tot = incl[3];
        int x = tot;
#pragma unroll
        for (int o = 1; o < 32; o <<= 1) {
            int y = __shfl_up_sync(0xffffffffu, x, o);
            if (lane >= o) x += y;
        }
        if (lane == 31) wsum[wid] = x;
        __syncthreads();
        if (wid == 0) {
            int s = wsum[lane];
#pragma unroll
            for (int o = 1; o < 32; o <<= 1) {
                int y = __shfl_up_sync(0xffffffffu, s, o);
                if (lane >= o) s += y;
            }
            wsum[lane] = s;
        }
        __syncthreads();
        int excl = (x - tot) + (wid ? wsum[wid - 1] : 0) + c0;
#pragma unroll
        for (int k = 0; k < 4; k++) {
            int i = i0 + k;
            if (i < n) rowptr[i + 1] = excl + incl[k];
        }
        __syncthreads();
        if (tid == 0) carry_s = c0 + wsum[31];
        __syncthreads();
    }
}
__global__ void k_scatter3(const int* __restrict__ s0p, const int* __restrict__ s1p,
                           const int* __restrict__ s2p, const int* __restrict__ d0,
                           const int* __restrict__ d1, const int* __restrict__ d2,
                           int E0, int E1, int E2, const int* __restrict__ rp,
                           int* __restrict__ off, int* __restrict__ srcp) {
    int t = blockIdx.y;
    const int* src = (t == 0) ? s0p : (t == 1) ? s1p : s2p;
    const int* dst = (t == 0) ? d0 : (t == 1) ? d1 : d2;
    int E = (t == 0) ? E0 : (t == 1) ? E1 : E2;
    int i = blockIdx.x * 256 + threadIdx.x;
    if (i < E) {
        int d = dst[i];
        int p = rp[t * (NP + 1) + d] + atomicAdd(&off[t * NP + d], 1);
        srcp[t * EMAX + p] = src[i];
    }
}

// ---------------- all 9 Vd vectors in one launch ----------------
__global__ void k_makeV_all(const float* __restrict__ W_hid, const float* __restrict__ ad_hid,
                            const float* __restrict__ W_out, const float* __restrict__ ad_out,
                            float* __restrict__ V) {
    int b = blockIdx.x;
    int k = threadIdx.x;
    if (b < 6) {
        const float* W = W_hid + (size_t)b * 65536;
        const float* a = ad_hid + (size_t)b * 256;
        for (int h = 0; h < 4; h++) {
            float s = 0.f;
            for (int c = 0; c < 64; c++) s = fmaf(W[k * 256 + h * 64 + c], a[h * 64 + c], s);
            V[b * 1024 + k * 4 + h] = s;
        }
    } else {
        const float* W = W_out + (size_t)(b - 6) * 16384;
        const float* a = ad_out + (size_t)(b - 6) * 64;
        float s = 0.f;
        for (int c = 0; c < 64; c++) s = fmaf(W[k * 64 + c], a[c], s);
        V[b * 1024 + k] = s;
    }
}

// ---------------- per-segment softmax+gather accumulate, H=4 ----------------
__device__ __forceinline__ void edge4(const int* __restrict__ rowptr,
                                      const int* __restrict__ srcp,
                                      const float* __restrict__ als, const float* ad,
                                      const float* __restrict__ hsrc,
                                      float* __restrict__ alpha, int w, int lane, int c0,
                                      int c1, int hsel, float4& a0, float4& a1) {
    int s0 = rowptr[w], s1 = rowptr[w + 1];
    int deg = s1 - s0;
    if (deg <= 0) return;
    const float NINF = __int_as_float(0xff800000u);
    if (deg <= 32) {
        int sreg = (lane < deg) ? srcp[s0 + lane] : 0;
        float ex[4];
#pragma unroll
        for (int h = 0; h < 4; h++) {
            float e = NINF;
            if (lane < deg) {
                e = als[(size_t)sreg * 4 + h] + ad[h];
                e = e > 0.f ? e : NEG * e;
            }
            ex[h] = e;
        }
        float inv[4];
#pragma unroll
        for (int h = 0; h < 4; h++) {
            float m = ex[h];
#pragma unroll
            for (int o = 16; o; o >>= 1) m = fmaxf(m, __shfl_xor_sync(0xffffffffu, m, o));
            float v = (lane < deg) ? __expf(ex[h] - m) : 0.f;
            ex[h] = v;
#pragma unroll
            for (int o = 16; o; o >>= 1) v += __shfl_xor_sync(0xffffffffu, v, o);
            inv[h] = 1.f / (v + 1e-16f);
        }
        float inv0 = hsel ? inv[1] : inv[0];
        float inv1 = hsel ? inv[3] : inv[2];
        for (int i = 0; i < deg; i++) {
            int s = __shfl_sync(0xffffffffu, sreg, i);
            float e0 = __shfl_sync(0xffffffffu, ex[0], i);
            float e1 = __shfl_sync(0xffffffffu, ex[1], i);
            float e2 = __shfl_sync(0xffffffffu, ex[2], i);
            float e3 = __shfl_sync(0xffffffffu, ex[3], i);
            float w0 = (hsel ? e1 : e0) * inv0;
            float w1 = (hsel ? e3 : e2) * inv1;
            const float4* hr = (const float4*)(hsrc + (size_t)s * 256);
            float4 v0 = hr[c0], v1 = hr[c1];
            a0.x = fmaf(v0.x, w0, a0.x); a0.y = fmaf(v0.y, w0, a0.y);
            a0.z = fmaf(v0.z, w0, a0.z); a0.w = fmaf(v0.w, w0, a0.w);
            a1.x = fmaf(v1.x, w1, a1.x); a1.y = fmaf(v1.y, w1, a1.y);
            a1.z = fmaf(v1.z, w1, a1.z); a1.w = fmaf(v1.w, w1, a1.w);
        }
    } else {
        float mx[4], sm[4], inv[4];
#pragma unroll
        for (int h = 0; h < 4; h++) { mx[h] = NINF; sm[h] = 0.f; }
        for (int j = s0 + lane; j < s1; j += 32) {
            int s = srcp[j];
#pragma unroll
            for (int h = 0; h < 4; h++) {
                float e = als[(size_t)s * 4 + h] + ad[h];
                e = e > 0.f ? e : NEG * e;
                alpha[(size_t)j * 4 + h] = e;
                mx[h] = fmaxf(mx[h], e);
            }
        }
#pragma unroll
        for (int h = 0; h < 4; h++)
#pragma unroll
            for (int o = 16; o; o >>= 1)
                mx[h] = fmaxf(mx[h], __shfl_xor_sync(0xffffffffu, mx[h], o));
        for (int j = s0 + lane; j < s1; j += 32) {
#pragma unroll
            for (int h = 0; h < 4; h++) {
                float e2 = __expf(alpha[(size_t)j * 4 + h] - mx[h]);
                alpha[(size_t)j * 4 + h] = e2;
                sm[h] += e2;
            }
        }
#pragma unroll
        for (int h = 0; h < 4; h++) {
#pragma unroll
            for (int o = 16; o; o >>= 1) sm[h] += __shfl_xor_sync(0xffffffffu, sm[h], o);
            inv[h] = 1.f / (sm[h] + 1e-16f);
        }
        float inv0 = inv[hsel], inv1 = inv[hsel + 2];
        for (int j = s0; j < s1; j++) {
            int s = srcp[j];
            float4 al = *(const float4*)(alpha + (size_t)j * 4);
            const float4* hr = (const float4*)(hsrc + (size_t)s * 256);
            float4 v0 = hr[c0], v1 = hr[c1];
            float w0 = (hsel ? al.y : al.x) * inv0;
            float w1 = (hsel ? al.w : al.z) * inv1;
            a0.x = fmaf(v0.x, w0, a0.x); a0.y = fmaf(v0.y, w0, a0.y);
            a0.z = fmaf(v0.z, w0, a0.z); a0.w = fmaf(v0.w, w0, a0.w);
            a1.x = fmaf(v1.x, w1, a1.x); a1.y = fmaf(v1.y, w1, a1.y);
            a1.z = fmaf(v1.z, w1, a1.z); a1.w = fmaf(v1.w, w1, a1.w);
        }
    }
}

// ---------------- mega aggregation: one launch per hidden layer ----------------
__global__ void __launch_bounds__(256) k_lagg4(
    const int* __restrict__ rp0, const int* __restrict__ sp0, const int* __restrict__ rp1,
    const int* __restrict__ sp1, const int* __restrict__ rp2, const int* __restrict__ sp2,
    const float* __restrict__ h0, const float* __restrict__ h1, const float* __restrict__ h2,
    const float* __restrict__ als0, const float* __restrict__ als1,
    const float* __restrict__ als2, const float* __restrict__ ald2,
    const float* __restrict__ V0, const float* __restrict__ V1,
    const float* __restrict__ xp_in, const float* __restrict__ xd_in,
    const float* __restrict__ b0, const float* __restrict__ b1, const float* __restrict__ b2,
    float* __restrict__ alpha0, float* __restrict__ alpha1, float* __restrict__ alpha2,
    float* __restrict__ xp_out, float* __restrict__ xd_out, int act) {
    __shared__ float Vs0[1024];
    __shared__ float Vs1[1024];
    for (int i = threadIdx.x; i < 1024; i += 256) {
        Vs0[i] = V0[i];
        Vs1[i] = V1[i];
    }
    __syncthreads();
    int n = (blockIdx.x * 256 + threadIdx.x) >> 5;
    int lane = threadIdx.x & 31;
    if (n >= NP + ND) return;
    int c0 = lane, c1 = lane + 32, hsel = lane >> 4;
    float4 a0 = make_float4(0.f, 0.f, 0.f, 0.f), a1 = a0;
    float4 o0, o1;
    float4* orow;
    if (n < NP) {
        int w = n;
        const float* xr = xp_in + (size_t)w * 256;
        float p[4] = {0.f, 0.f, 0.f, 0.f};
#pragma unroll
        for (int tt = 0; tt < 8; tt++) {
            int k = lane + tt * 32;
            float x = xr[k];
#pragma unroll
            for (int h = 0; h < 4; h++) p[h] = fmaf(x, Vs0[k * 4 + h], p[h]);
        }
        float ad0[4];
#pragma unroll
        for (int h = 0; h < 4; h++) {
#pragma unroll
            for (int o = 16; o; o >>= 1) p[h] += __shfl_xor_sync(0xffffffffu, p[h], o);
            ad0[h] = p[h];
        }
        float ad2[4];
#pragma unroll
        for (int h = 0; h < 4; h++) ad2[h] = ald2[(size_t)w * 4 + h];
        edge4(rp0, sp0, als0, ad0, h0, alpha0, w, lane, c0, c1, hsel, a0, a1);
        edge4(rp2, sp2, als2, ad2, h2, alpha2, w, lane, c0, c1, hsel, a0, a1);
        const float4* B0 = (const float4*)b0;
        const float4* B2 = (const float4*)b2;
        float4 bb0 = B0[c0], bb1 = B0[c1];
        float4 t0 = B2[c0], t1 = B2[c1];
        bb0.x += t0.x; bb0.y += t0.y; bb0.z += t0.z; bb0.w += t0.w;
        bb1.x += t1.x; bb1.y += t1.y; bb1.z += t1.z; bb1.w += t1.w;
        o0 = make_float4(a0.x + bb0.x, a0.y + bb0.y, a0.z + bb0.z, a0.w + bb0.w);
        o1 = make_float4(a1.x + bb1.x, a1.y + bb1.y, a1.z + bb1.z, a1.w + bb1.w);
        orow = (float4*)(xp_out + (size_t)w * 256);
    } else {
        int w = n - NP;
        const float* xr = xd_in + (size_t)w * 256;
        float p[4] = {0.f, 0.f, 0.f, 0.f};
#pragma unroll
        for (int tt = 0; tt < 8; tt++) {
            int k = lane + tt * 32;
            float x = xr[k];
#pragma unroll
            for (int h = 0; h < 4; h++) p[h] = fmaf(x, Vs1[k * 4 + h], p[h]);
        }
        float ad1[4];
#pragma unroll
        for (int h = 0; h < 4; h++) {
#pragma unroll
            for (int o = 16; o; o >>= 1) p[h] += __shfl_xor_sync(0xffffffffu, p[h], o);
            ad1[h] = p[h];
        }
        edge4(rp1, sp1, als1, ad1, h1, alpha1, w, lane, c0, c1, hsel, a0, a1);
        const float4* B1 = (const float4*)b1;
        float4 bb0 = B1[c0], bb1 = B1[c1];
        o0 = make_float4(a0.x + bb0.x, a0.y + bb0.y, a0.z + bb0.z, a0.w + bb0.w);
        o1 = make_float4(a1.x + bb1.x, a1.y + bb1.y, a1.z + bb1.z, a1.w + bb1.w);
        orow = (float4*)(xd_out + (size_t)w * 256);
    }
    if (act) {
        o0.x = eluf(o0.x); o0.y = eluf(o0.y); o0.z = eluf(o0.z); o0.w = eluf(o0.w);
        o1.x = eluf(o1.x); o1.y = eluf(o1.y); o1.z = eluf(o1.z); o1.w = eluf(o1.w);
    }
    orow[c0] = o0;
    orow[c1] = o1;
}

// ---------------- per-segment softmax+gather, H=1, 64 cols ----------------
__device__ __forceinline__ void edge1(const int* __restrict__ rowptr,
                                      const int* __restrict__ srcp,
                                      const float* __restrict__ als, float ad,
                                      const float* __restrict__ hsrc,
                                      float* __restrict__ alpha, int w, int lane, float& a0,
                                      float& a1) {
    int s0 = rowptr[w], s1 = rowptr[w + 1];
    int deg = s1 - s0;
    if (deg <= 0) return;
    const float NINF = __int_as_float(0xff800000u);
    if (deg <= 32) {
        int sreg = (lane < deg) ? srcp[s0 + lane] : 0;
        float e = NINF;
        if (lane < deg) {
            e = als[sreg] + ad;
            e = e > 0.f ? e : NEG * e;
        }
        float m = e;
#pragma unroll
        for (int o = 16; o; o >>= 1) m = fmaxf(m, __shfl_xor_sync(0xffffffffu, m, o));
        float ex = (lane < deg) ? __expf(e - m) : 0.f;
        float sm = ex;
#pragma unroll
        for (int o = 16; o; o >>= 1) sm += __shfl_xor_sync(0xffffffffu, sm, o);
        float inv = 1.f / (sm + 1e-16f);
        for (int i = 0; i < deg; i++) {
            int s = __shfl_sync(0xffffffffu, sreg, i);
            float al = __shfl_sync(0xffffffffu, ex, i) * inv;
            const float* hr = hsrc + (size_t)s * 64;
            a0 = fmaf(hr[lane], al, a0);
            a1 = fmaf(hr[lane + 32], al, a1);
        }
    } else {
        float mx = NINF, sm = 0.f;
        for (int j = s0 + lane; j < s1; j += 32) {
            int s = srcp[j];
            float e = als[s] + ad;
            e = e > 0.f ? e : NEG * e;
            alpha[j] = e;
            mx = fmaxf(mx, e);
        }
#pragma unroll
        for (int o = 16; o; o >>= 1) mx = fmaxf(mx, __shfl_xor_sync(0xffffffffu, mx, o));
        for (int j = s0 + lane; j < s1; j += 32) {
            float ex = __expf(alpha[j] - mx);
            alpha[j] = ex;
            sm += ex;
        }
#pragma unroll
        for (int o = 16; o; o >>= 1) sm += __shfl_xor_sync(0xffffffffu, sm, o);
        float inv = 1.f / (sm + 1e-16f);
        for (int j = s0; j < s1; j++) {
            int s = srcp[j];
            float al = alpha[j] * inv;
            const float* hr = hsrc + (size_t)s * 64;
            a0 = fmaf(hr[lane], al, a0);
            a1 = fmaf(hr[lane + 32], al, a1);
        }
    }
}

// ---------------- mega aggregation for output layer ----------------
__global__ void __launch_bounds__(256) k_lagg1(
    const int* __restrict__ rp0, const int* __restrict__ sp0, const int* __restrict__ rp1,
    const int* __restrict__ sp1, const int* __restrict__ rp2, const int* __restrict__ sp2,
    const float* __restrict__ h0, const float* __restrict__ h1, const float* __restrict__ h2,
    const float* __restrict__ als0, const float* __restrict__ als1,
    const float* __restrict__ als2, const float* __restrict__ ald2,
    const float* __restrict__ V0, const float* __restrict__ V1,
    const float* __restrict__ xp_in, const float* __restrict__ xd_in,
    const float* __restrict__ b0, const float* __restrict__ b1, const float* __restrict__ b2,
    float* __restrict__ alpha0, float* __restrict__ alpha1, float* __restrict__ alpha2,
    float* __restrict__ op, float* __restrict__ od) {
    __shared__ float Vs0[256];
    __shared__ float Vs1[256];
    for (int i = threadIdx.x; i < 256; i += 256) {
        Vs0[i] = V0[i];
        Vs1[i] = V1[i];
    }
    __syncthreads();
    int n = (blockIdx.x * 256 + threadIdx.x) >> 5;
    int lane = threadIdx.x & 31;
    if (n >= NP + ND) return;
    float a0 = 0.f, a1 = 0.f;
    float* orow;
    float bb0, bb1;
    if (n < NP) {
        int w = n;
        const float* xr = xp_in + (size_t)w * 256;
        float p = 0.f;
#pragma unroll
        for (int tt = 0; tt < 8; tt++) {
            int k = lane + tt * 32;
            p = fmaf(xr[k], Vs0[k], p);
        }
#pragma unroll
        for (int o = 16; o; o >>= 1) p += __shfl_xor_sync(0xffffffffu, p, o);
        edge1(rp0, sp0, als0, p, h0, alpha0, w, lane, a0, a1);
        edge1(rp2, sp2, als2, ald2[w], h2, alpha2, w, lane, a0, a1);
        bb0 = b0[lane] + b2[lane];
        bb1 = b0[lane + 32] + b2[lane + 32];
        orow = op + (size_t)w * 64;
    } else {
        int w = n - NP;
        const float* xr = xd_in + (size_t)w * 256;
        float p = 0.f;
#pragma unroll
        for (int tt = 0; tt < 8; tt++) {
            int k = lane + tt * 32;
            p = fmaf(xr[k], Vs1[k], p);
        }
#pragma unroll
        for (int o = 16; o; o >>= 1) p += __shfl_xor_sync(0xffffffffu, p, o);
        edge1(rp1, sp1, als1, p, h1, alpha1, w, lane, a0, a1);
        bb0 = b1[lane];
        bb1 = b1[lane + 32];
        orow = od + (size_t)w * 64;
    }
    orow[lane] = a0 + bb0;
    orow[lane + 32] = a1 + bb1;
}

// =====================================================================
extern "C" void kernel_launch(void* const* d_in, const int* in_sizes, int n_in,
                              void* d_out, int out_size) {
    const float* x_drug = (const float*)d_in[0];
    const float* x_prot = (const float*)d_in[1];
    const int* srcA[3] = {(const int*)d_in[2], (const int*)d_in[4], (const int*)d_in[6]};
    const int* dstA[3] = {(const int*)d_in[3], (const int*)d_in[5], (const int*)d_in[7]};
    const float* linW_d = (const float*)d_in[8];
    const float* linb_d = (const float*)d_in[9];
    const float* linW_p = (const float*)d_in[10];
    const float* linb_p = (const float*)d_in[11];
    const float* W_hid = (const float*)d_in[12];
    const float* as_hid = (const float*)d_in[13];
    const float* ad_hid = (const float*)d_in[14];
    const float* b_hid = (const float*)d_in[15];
    const float* W_out = (const float*)d_in[16];
    const float* as_out = (const float*)d_in[17];
    const float* ad_out = (const float*)d_in[18];
    const float* b_out = (const float*)d_in[19];
    float* outp = (float*)d_out;

    int E[3] = {in_sizes[2], in_sizes[4], in_sizes[6]};
    int maxE = E[0] > E[1] ? E[0] : E[1];
    if (E[2] > maxE) maxE = E[2];

    float *xdb, *xpb, *hb, *alpha, *als, *ald, *V;
    int *rp, *sp, *cnt;
    __nv_bfloat16 *whi, *wlo;
    cudaGetSymbolAddress((void**)&xdb, g_xd);
    cudaGetSymbolAddress((void**)&xpb, g_xp);
    cudaGetSymbolAddress((void**)&hb, g_h);
    cudaGetSymbolAddress((void**)&alpha, g_alpha);
    cudaGetSymbolAddress((void**)&als, g_als);
    cudaGetSymbolAddress((void**)&ald, g_ald);
    cudaGetSymbolAddress((void**)&V, g_V);
    cudaGetSymbolAddress((void**)&rp, g_rowptr);
    cudaGetSymbolAddress((void**)&sp, g_srcp);
    cudaGetSymbolAddress((void**)&cnt, g_cnt);
    cudaGetSymbolAddress((void**)&whi, g_whi);
    cudaGetSymbolAddress((void**)&wlo, g_wlo);

    float* xd[2] = {xdb, xdb + (size_t)ND * HIDW};
    float* xp[2] = {xpb, xpb + (size_t)NP * HIDW};
    float* h0 = hb;
    float* h1 = hb + (size_t)NP * HIDW;
    float* h2 = hb + 2 * (size_t)NP * HIDW;
    int* rowptr[3] = {rp, rp + (NP + 1), rp + 2 * (NP + 1)};
    int* srcp[3] = {sp, sp + EMAX, sp + 2 * EMAX};
    float* als0 = als;
    float* als1 = als + (size_t)NP * 4;
    float* als2 = als + 2 * (size_t)NP * 4;
    float* alpha0 = alpha;
    float* alpha1 = alpha + (size_t)EMAX * 4;
    float* alpha2 = alpha + 2 * (size_t)EMAX * 4;

    const int SM128 = 2048 + 4 * (128 * 40 * 2) + 4 * (128 * 40 * 2);  // 83968
    const int SM64 = 2048 + 4 * (128 * 40 * 2) + 4 * (64 * 40 * 2);    // 63488
    cudaFuncSetAttribute(k_mma<128, true, true, 0>,
                         cudaFuncAttributeMaxDynamicSharedMemorySize, SM128);
    cudaFuncSetAttribute(k_mma<128, false, false, 4>,
                         cudaFuncAttributeMaxDynamicSharedMemorySize, SM128);
    cudaFuncSetAttribute(k_mma<64, false, false, 1>,
                         cudaFuncAttributeMaxDynamicSharedMemorySize, SM64);

    size_t o_lind = 0;
    size_t o_linp = 32768;
    size_t o_hid0 = 98304;
    size_t o_out0 = 491520;

    int ebx = (maxE + 255) / 256;
    int gx128 = (NP + 127) / 128;  // 313, covers both ND and NP (early exit)

    // L0: zero cnt
    k_zero<<<(3 * NP + 255) / 256, 256>>>(cnt, 3 * NP);
    // L1: count
    {
        dim3 gc(ebx, 3);
        k_count3<<<gc, 256>>>(dstA[0], dstA[1], dstA[2], E[0], E[1], E[2], cnt);
    }
    // L2: weight split
    {
        dim3 gw(256, 11);
        k_splitW_all<<<gw, 256>>>(linW_d, linW_p, W_hid, W_out, whi, wlo);
    }
    // L3: input projections (batched z=2) — ncu capture target
    {
        GemmCfg3 P{};
        P.c[0] = {x_drug, whi + o_lind, wlo + o_lind, linb_d, nullptr, nullptr,
                  xd[0], nullptr, nullptr, ND, 128};
        P.c[1] = {x_prot, whi + o_linp, wlo + o_linp, linb_p, nullptr, nullptr,
                  xp[0], nullptr, nullptr, NP, 256};
        P.c[2] = P.c[1];
        dim3 gg(gx128, 2, 2);
        k_mma<128, true, true, 0><<<gg, 256, SM128>>>(P);
    }
    // L4: scan (+re-zero cnt)
    k_scan3<<<3, 1024>>>(cnt, rp, NP, ND, NP);
    // L5: scatter
    {
        dim3 gs(ebx, 3);
        k_scatter3<<<gs, 256>>>(srcA[0], srcA[1], srcA[2], dstA[0], dstA[1], dstA[2], E[0],
                                E[1], E[2], rp, cnt, sp);
    }
    // L6: V vectors
    k_makeV_all<<<9, 256>>>(W_hid, ad_hid, W_out, ad_out, V);

    int cur = 0, nxt = 1;
    int naggb = (NP + ND + 7) / 8;

    // ---- hidden layers ----
    for (int l = 0; l < 2; l++) {
        int i0 = l * 3 + 0, i1 = l * 3 + 1, i2 = l * 3 + 2;
        // batched GEMM (3 edge types)
        {
            GemmCfg3 P{};
            P.c[0] = {xd[cur], whi + o_hid0 + (size_t)i0 * 65536,
                      wlo + o_hid0 + (size_t)i0 * 65536, nullptr,
                      as_hid + (size_t)i0 * 256, nullptr, h0, als0, nullptr, ND, 256};
            P.c[1] = {xp[cur], whi + o_hid0 + (size_t)i1 * 65536,
                      wlo + o_hid0 + (size_t)i1 * 65536, nullptr,
                      as_hid + (size_t)i1 * 256, nullptr, h1, als1, nullptr, NP, 256};
            P.c[2] = {xp[cur], whi + o_hid0 + (size_t)i2 * 65536,
                      wlo + o_hid0 + (size_t)i2 * 65536, nullptr,
                      as_hid + (size_t)i2 * 256, ad_hid + (size_t)i2 * 256, h2, als2, ald,
                      NP, 256};
            dim3 gg(gx128, 2, 3);
            k_mma<128, false, false, 4><<<gg, 256, SM128>>>(P);
        }
        // mega aggregation
        k_lagg4<<<naggb, 256>>>(rowptr[0], srcp[0], rowptr[1], srcp[1], rowptr[2], srcp[2],
                                h0, h1, h2, als0, als1, als2, ald, V + (size_t)i0 * 1024,
                                V + (size_t)i1 * 1024, xp[cur], xd[cur],
                                b_hid + (size_t)i0 * 256, b_hid + (size_t)i1 * 256,
                                b_hid + (size_t)i2 * 256, alpha0, alpha1, alpha2, xp[nxt],
                                xd[nxt], 1);
        cur = nxt;
        nxt = 1 - nxt;
    }

    // ---- output layer ----
    float* od = outp;
    float* op = outp + (size_t)ND * OUTC;
    {
        GemmCfg3 P{};
        P.c[0] = {xd[cur], whi + o_out0, wlo + o_out0, nullptr, as_out, nullptr,
                  h0, als0, nullptr, ND, 256};
        P.c[1] = {xp[cur], whi + o_out0 + 16384, wlo + o_out0 + 16384, nullptr,
                  as_out + OUTC, nullptr, h1, als1, nullptr, NP, 256};
        P.c[2] = {xp[cur], whi + o_out0 + 2 * 16384, wlo + o_out0 + 2 * 16384, nullptr,
                  as_out + 2 * OUTC, ad_out + 2 * OUTC, h2, als2, ald, NP, 256};
        dim3 gg(gx128, 1, 3);
        k_mma<64, false, false, 1><<<gg, 256, SM64>>>(P);
    }
    k_lagg1<<<naggb, 256>>>(rowptr[0], srcp[0], rowptr[1], srcp[1], rowptr[2], srcp[2], h0,
                            h1, h2, als0, als1, als2, ald, V + 6 * 1024, V + 7 * 1024,
                            xp[cur], xd[cur], b_out + 0 * OUTC, b_out + 1 * OUTC,
                            b_out + 2 * OUTC, alpha0, alpha1, alpha2, op, od);

    (void)n_in;
    (void)out_size;
}

// round 12
// speedup vs baseline: 3.0760x; 1.0854x over previous
#include <cuda_runtime.h>
#include <cuda_bf16.h>
#include <cstdint>

// Problem constants (fixed shapes)
#define ND 20000
#define NP 40000
#define EMAX 300000
#define HIDW 256
#define OUTC 64
#define NEG 0.2f

// ---------------- static device scratch (allocation-free rule) ----------------
__device__ float g_xd[2][ND * HIDW];
__device__ float g_xp[2][NP * HIDW];
__device__ float g_h[3][NP * HIDW];            // per-edge-type h_src
__device__ float g_alpha[3 * EMAX * 4];        // per-edge-type softmax fallback
__device__ float g_als[3 * NP * 4];            // per-edge-type src logits
__device__ float g_ald[NP * 4];                // dual (et2) dst logits
__device__ float g_V[9 * 1024];
__device__ int   g_rowptr[3 * (NP + 1)];
__device__ int   g_srcp[3 * EMAX];
__device__ int   g_cnt[3 * NP];
#define WTOT 540672
__device__ __nv_bfloat16 g_whi[WTOT];
__device__ __nv_bfloat16 g_wlo[WTOT];

// ======================= helpers =======================
__device__ __forceinline__ uint32_t smem_u32(const void* p) {
    uint32_t a;
    asm("{ .reg .u64 t; cvta.to.shared.u64 t, %1; cvt.u32.u64 %0, t; }" : "=r"(a) : "l"(p));
    return a;
}
__device__ __forceinline__ void cp_async8(uint32_t dst, const void* src) {
    asm volatile("cp.async.ca.shared.global [%0], [%1], 8;" :: "r"(dst), "l"(src));
}
#define CP_COMMIT() asm volatile("cp.async.commit_group;" ::: "memory")
#define CP_WAIT0()  asm volatile("cp.async.wait_group 0;" ::: "memory")

__device__ __forceinline__ void mma16816(float* c, const uint32_t* a, const uint32_t* b) {
    asm volatile(
        "mma.sync.aligned.m16n8k16.row.col.f32.bf16.bf16.f32 "
        "{%0,%1,%2,%3}, {%4,%5,%6,%7}, {%8,%9}, {%0,%1,%2,%3};"
        : "+f"(c[0]), "+f"(c[1]), "+f"(c[2]), "+f"(c[3])
        : "r"(a[0]), "r"(a[1]), "r"(a[2]), "r"(a[3]), "r"(b[0]), "r"(b[1]));
}

__device__ __forceinline__ uint32_t pack_bf2(float x, float y) {
    __nv_bfloat162 t = __floats2bfloat162_rn(x, y);
    return *reinterpret_cast<uint32_t*>(&t);
}
__device__ __forceinline__ float eluf(float v) { return v > 0.f ? v : expm1f(v); }

// ---------------- all-weights pre-transpose + bf16 split in ONE launch ----------------
__global__ void k_splitW_all(const float* __restrict__ linW_d, const float* __restrict__ linW_p,
                             const float* __restrict__ W_hid, const float* __restrict__ W_out,
                             __nv_bfloat16* __restrict__ hi, __nv_bfloat16* __restrict__ lo) {
    int id = blockIdx.y;
    int i = blockIdx.x * 256 + threadIdx.x;
    const float* W;
    size_t off;
    int K, N;
    if (id == 0) { W = linW_d; off = 0; K = 128; N = 256; }
    else if (id == 1) { W = linW_p; off = 32768; K = 256; N = 256; }
    else if (id < 8) {
        W = W_hid + (size_t)(id - 2) * 65536; off = 98304 + (size_t)(id - 2) * 65536;
        K = 256; N = 256;
    } else {
        W = W_out + (size_t)(id - 8) * 16384; off = 491520 + (size_t)(id - 8) * 16384;
        K = 256; N = 64;
    }
    if (i >= N * K) return;
    int n = i / K, k = i % K;
    float v = W[(size_t)k * N + n];
    __nv_bfloat16 h = __float2bfloat16(v);
    hi[off + i] = h;
    lo[off + i] = __float2bfloat16(v - __bfloat162float(h));
}

// ============ batched mma.sync GEMM (cfg selected by blockIdx.z) ============
struct GemmCfg {
    const float* A;
    const __nv_bfloat16* Bhi;
    const __nv_bfloat16* Blo;
    const float* bias;
    const float* asrc;
    const float* adst;
    float* C;
    float* als;
    float* ald;
    int M;
    int K;
};
struct GemmCfg3 { GemmCfg c[3]; };

template <int BN, bool BIAS, bool RELU, int HALS>
__global__ void __launch_bounds__(256, 2) k_mma(GemmCfg3 P) {
    GemmCfg cfg = P.c[blockIdx.z];
    const int M = cfg.M, K = cfg.K;
    if ((int)blockIdx.x * 128 >= M) return;

    extern __shared__ char smem[];
    constexpr int WN = BN / 2;
    constexpr int NTILES = WN / 8;
    constexpr int ABUF = 128 * 40 * 2;
    constexpr int BBUF = BN * 40 * 2;
    constexpr int S_A = 2048;
    constexpr int S_B = S_A + 4 * ABUF;
    float* sBias = (float*)(smem);
    float* sAsrc = (float*)(smem + 512);
    float* sAdst = (float*)(smem + 1024);
    __shared__ float sr1[128];
    __shared__ float sr2[128];

    const bool dual = (HALS != 0) && (cfg.adst != nullptr);

    int tid = threadIdx.x;
    int wid = tid >> 5, lane = tid & 31;
    int g = lane >> 2, tg = lane & 3;
    int warp_m = wid & 3, warp_n = wid >> 2;
    int bm = blockIdx.x * 128, bn = blockIdx.y * BN;

    if (BIAS)
        for (int i = tid; i < BN; i += 256) sBias[i] = cfg.bias[bn + i];
    if (HALS) {
        for (int i = tid; i < BN; i += 256) sAsrc[i] = cfg.asrc[bn + i];
        if (dual)
            for (int i = tid; i < BN; i += 256) sAdst[i] = cfg.adst[bn + i];
    }

    int arow = tid >> 1;
    int akq = (tid & 1) * 16;
    bool aval_base = (bm + arow) < M;
    constexpr int CH = BN * 8 / 256;

    float acc[2][NTILES][4];
#pragma unroll
    for (int mi = 0; mi < 2; mi++)
#pragma unroll
        for (int nt = 0; nt < NTILES; nt++)
#pragma unroll
            for (int q = 0; q < 4; q++) acc[mi][nt][q] = 0.f;

    uint32_t sbase = smem_u32(smem);
    const float* A = cfg.A;
    const __nv_bfloat16* Bthi = cfg.Bhi;
    const __nv_bfloat16* Btlo = cfg.Blo;

    auto loadA = [&](int k0, float4* ar) {
        const float* src = A + (size_t)(bm + arow) * K + k0 + akq;
#pragma unroll
        for (int i = 0; i < 4; i++)
            ar[i] = aval_base ? ((const float4*)src)[i] : make_float4(0.f, 0.f, 0.f, 0.f);
    };
    auto storeA = [&](const float4* ar, int buf) {
        char* dh = smem + S_A + buf * 2 * ABUF;
        char* dl = dh + ABUF;
#pragma unroll
        for (int i = 0; i < 4; i++) {
            float4 f = ar[i];
            __nv_bfloat16 hx = __float2bfloat16(f.x), hy = __float2bfloat16(f.y);
            __nv_bfloat16 hz = __float2bfloat16(f.z), hw = __float2bfloat16(f.w);
            __nv_bfloat162 H01(hx, hy), H23(hz, hw);
            uint32_t h01 = *(uint32_t*)&H01, h23 = *(uint32_t*)&H23;
            uint32_t l01 = pack_bf2(f.x - __bfloat162float(hx), f.y - __bfloat162float(hy));
            uint32_t l23 = pack_bf2(f.z - __bfloat162float(hz), f.w - __bfloat162float(hw));
            int off = (arow * 40 + akq + i * 4) * 2;
            *(uint2*)(dh + off) = make_uint2(h01, h23);
            *(uint2*)(dl + off) = make_uint2(l01, l23);
        }
    };
    auto loadB = [&](int k0, int buf) {
        uint32_t dh = sbase + S_B + buf * 2 * BBUF;
        uint32_t dl = dh + BBUF;
#pragma unroll
        for (int i = 0; i < CH; i++) {
            int c = tid + i * 256;
            int row = c >> 3, kc = c & 7;
            size_t go = (size_t)(bn + row) * K + k0 + kc * 4;
            uint32_t so = row * 80 + kc * 8;
            cp_async8(dh + so, Bthi + go);
            cp_async8(dl + so, Btlo + go);
        }
        CP_COMMIT();
    };
    auto compute = [&](int buf) {
        const char* Ah = smem + S_A + buf * 2 * ABUF;
        const char* Al = Ah + ABUF;
        const char* Bh = smem + S_B + buf * 2 * BBUF;
        const char* Bl = Bh + BBUF;
#pragma unroll
        for (int kk = 0; kk < 32; kk += 16) {
            uint32_t ah[2][4], al[2][4];
#pragma unroll
            for (int mi = 0; mi < 2; mi++) {
                int r0 = warp_m * 32 + mi * 16 + g;
                int kb = kk + tg * 2;
                ah[mi][0] = *(const uint32_t*)(Ah + (r0 * 40 + kb) * 2);
                ah[mi][1] = *(const uint32_t*)(Ah + ((r0 + 8) * 40 + kb) * 2);
                ah[mi][2] = *(const uint32_t*)(Ah + (r0 * 40 + kb + 8) * 2);
                ah[mi][3] = *(const uint32_t*)(Ah + ((r0 + 8) * 40 + kb + 8) * 2);
                al[mi][0] = *(const uint32_t*)(Al + (r0 * 40 + kb) * 2);
                al[mi][1] = *(const uint32_t*)(Al + ((r0 + 8) * 40 + kb) * 2);
                al[mi][2] = *(const uint32_t*)(Al + (r0 * 40 + kb + 8) * 2);
                al[mi][3] = *(const uint32_t*)(Al + ((r0 + 8) * 40 + kb + 8) * 2);
            }
#pragma unroll
            for (int nt = 0; nt < NTILES; nt++) {
                int nr = warp_n * WN + nt * 8 + g;
                int kb = kk + tg * 2;
                uint32_t bh[2], bl[2];
                bh[0] = *(const uint32_t*)(Bh + (nr * 40 + kb) * 2);
                bh[1] = *(const uint32_t*)(Bh + (nr * 40 + kb + 8) * 2);
                bl[0] = *(const uint32_t*)(Bl + (nr * 40 + kb) * 2);
                bl[1] = *(const uint32_t*)(Bl + (nr * 40 + kb + 8) * 2);
#pragma unroll
                for (int mi = 0; mi < 2; mi++) {
                    mma16816(acc[mi][nt], ah[mi], bh);
                    mma16816(acc[mi][nt], ah[mi], bl);
                    mma16816(acc[mi][nt], al[mi], bh);
                }
            }
        }
    };

    int nstages = K / 32;
    float4 ar[4];
    loadA(0, ar);
    loadB(0, 0);
    storeA(ar, 0);
    CP_WAIT0();
    __syncthreads();
    for (int s = 0; s < nstages; s++) {
        int cur = s & 1, nxt = cur ^ 1;
        bool more = (s + 1) < nstages;
        if (more) {
            loadA((s + 1) * 32, ar);
            loadB((s + 1) * 32, nxt);
        }
        compute(cur);
        if (more) storeA(ar, nxt);
        CP_WAIT0();
        __syncthreads();
    }

    // ---- epilogue ----
    const int NT = (BN == 128) ? 256 : 64;
    float sals[2][2], sald[2][2];
    sals[0][0] = sals[0][1] = sals[1][0] = sals[1][1] = 0.f;
    sald[0][0] = sald[0][1] = sald[1][0] = sald[1][1] = 0.f;
#pragma unroll
    for (int mi = 0; mi < 2; mi++) {
        int r0 = bm + warp_m * 32 + mi * 16 + g;
        int r1 = r0 + 8;
#pragma unroll
        for (int nt = 0; nt < NTILES; nt++) {
            int nloc = warp_n * WN + nt * 8 + tg * 2;
            int n0 = bn + nloc;
            float* cc = acc[mi][nt];
            float v00 = cc[0], v01 = cc[1], v10 = cc[2], v11 = cc[3];
            if (BIAS) {
                v00 += sBias[nloc]; v01 += sBias[nloc + 1];
                v10 += sBias[nloc]; v11 += sBias[nloc + 1];
            }
            if (RELU) {
                v00 = fmaxf(v00, 0.f); v01 = fmaxf(v01, 0.f);
                v10 = fmaxf(v10, 0.f); v11 = fmaxf(v11, 0.f);
            }
            if (r0 < M) *(float2*)(cfg.C + (size_t)r0 * NT + n0) = make_float2(v00, v01);
            if (r1 < M) *(float2*)(cfg.C + (size_t)r1 * NT + n0) = make_float2(v10, v11);
            if (HALS) {
                float a0 = sAsrc[nloc], a1 = sAsrc[nloc + 1];
                sals[mi][0] += v00 * a0 + v01 * a1;
                sals[mi][1] += v10 * a0 + v11 * a1;
                if (dual) {
                    float d0 = sAdst[nloc], d1 = sAdst[nloc + 1];
                    sald[mi][0] += v00 * d0 + v01 * d1;
                    sald[mi][1] += v10 * d0 + v11 * d1;
                }
            }
        }
    }
    if (HALS) {
        if (HALS == 1) {
            for (int i = tid; i < 128; i += 256) { sr1[i] = 0.f; sr2[i] = 0.f; }
            __syncthreads();
        }
#pragma unroll
        for (int mi = 0; mi < 2; mi++)
#pragma unroll
            for (int hf = 0; hf < 2; hf++) {
                float s = sals[mi][hf];
                s += __shfl_xor_sync(0xffffffffu, s, 1);
                s += __shfl_xor_sync(0xffffffffu, s, 2);
                float s2 = sald[mi][hf];
                s2 += __shfl_xor_sync(0xffffffffu, s2, 1);
                s2 += __shfl_xor_sync(0xffffffffu, s2, 2);
                if (tg == 0) {
                    int rloc = warp_m * 32 + mi * 16 + g + hf * 8;
                    int r = bm + rloc;
                    if (HALS == 4) {
                        if (r < M) {
                            int h = blockIdx.y * 2 + warp_n;
                            cfg.als[(size_t)r * 4 + h] = s;
                            if (dual) cfg.ald[(size_t)r * 4 + h] = s2;
                        }
                    } else {
                        atomicAdd(&sr1[rloc], s);
                        if (dual) atomicAdd(&sr2[rloc], s2);
                    }
                }
            }
        if (HALS == 1) {
            __syncthreads();
            for (int i = tid; i < 128; i += 256) {
                int r = bm + i;
                if (r < M) {
                    cfg.als[r] = sr1[i];
                    if (dual) cfg.ald[r] = sr2[i];
                }
            }
        }
    }
}

// ---------------- CSR build (batched over 3 edge types) ----------------
__global__ void k_zero(int* __restrict__ p, int n) {
    int i = blockIdx.x * blockDim.x + threadIdx.x;
    if (i < n) p[i] = 0;
}
__global__ void k_count3(const int* __restrict__ d0, const int* __restrict__ d1,
                         const int* __restrict__ d2, int E0, int E1, int E2,
                         int* __restrict__ cnt) {
    int t = blockIdx.y;
    const int* dst = (t == 0) ? d0 : (t == 1) ? d1 : d2;
    int E = (t == 0) ? E0 : (t == 1) ? E1 : E2;
    int i = blockIdx.x * 256 + threadIdx.x;
    if (i < E) atomicAdd(&cnt[t * NP + dst[i]], 1);
}
// 3 blocks, 1024 threads, 4 elems/thread; also re-zeroes cnt for the scatter pass
__global__ void __launch_bounds__(1024) k_scan3(int* __restrict__ cnt,
                                                int* __restrict__ rp, int n0, int n1, int n2) {
    int t = blockIdx.x;
    int n = (t == 0) ? n0 : (t == 1) ? n1 : n2;
    int* c = cnt + t * NP;
    int* rowptr = rp + t * (NP + 1);
    __shared__ int wsum[32];
    __shared__ int carry_s;
    int tid = threadIdx.x, lane = tid & 31, wid = tid >> 5;
    if (tid == 0) { carry_s = 0; rowptr[0] = 0; }
    __syncthreads();
    for (int base = 0; base < n; base += 4096) {
        int c0 = carry_s;
        int i0 = base + tid * 4;
        int v[4];
#pragma unroll
        for (int k = 0; k < 4; k++) {
            v[k] = (i0 + k < n) ? c[i0 + k] : 0;
            if (i0 + k < n) c[i0 + k] = 0;
        }
        int incl[4];
        incl[0] = v[0];
        incl[1] = incl[0] + v[1];
        incl[2] = incl[1] + v[2];
        incl[3] = incl[2] + v[3];
        int tot = incl[3];
        int x = tot;
#pragma unroll
        for (int o = 1; o < 32; o <<= 1) {
            int y = __shfl_up_sync(0xffffffffu, x, o);
            if (lane >= o) x += y;
        }
        if (lane == 31) wsum[wid] = x;
        __syncthreads();
        if (wid == 0) {
            int s = wsum[lane];
#pragma unroll
            for (int o = 1; o < 32; o <<= 1) {
                int y = __shfl_up_sync(0xffffffffu, s, o);
                if (lane >= o) s += y;
            }
            wsum[lane] = s;
        }
        __syncthreads();
        int excl = (x - tot) + (wid ? wsum[wid - 1] : 0) + c0;
#pragma unroll
        for (int k = 0; k < 4; k++) {
            int i = i0 + k;
            if (i < n) rowptr[i + 1] = excl + incl[k];
        }
        __syncthreads();
        if (tid == 0) carry_s = c0 + wsum[31];
        __syncthreads();
    }
}
__global__ void k_scatter3(const int* __restrict__ s0p, const int* __restrict__ s1p,
                           const int* __restrict__ s2p, const int* __restrict__ d0,
                           const int* __restrict__ d1, const int* __restrict__ d2,
                           int E0, int E1, int E2, const int* __restrict__ rp,
                           int* __restrict__ off, int* __restrict__ srcp) {
    int t = blockIdx.y;
    const int* src = (t == 0) ? s0p : (t == 1) ? s1p : s2p;
    const int* dst = (t == 0) ? d0 : (t == 1) ? d1 : d2;
    int E = (t == 0) ? E0 : (t == 1) ? E1 : E2;
    int i = blockIdx.x * 256 + threadIdx.x;
    if (i < E) {
        int d = dst[i];
        int p = rp[t * (NP + 1) + d] + atomicAdd(&off[t * NP + d], 1);
        srcp[t * EMAX + p] = src[i];
    }
}

// ---------------- all 9 Vd vectors in one launch ----------------
__global__ void k_makeV_all(const float* __restrict__ W_hid, const float* __restrict__ ad_hid,
                            const float* __restrict__ W_out, const float* __restrict__ ad_out,
                            float* __restrict__ V) {
    int b = blockIdx.x;
    int k = threadIdx.x;
    if (b < 6) {
        const float* W = W_hid + (size_t)b * 65536;
        const float* a = ad_hid + (size_t)b * 256;
        for (int h = 0; h < 4; h++) {
            float s = 0.f;
            for (int c = 0; c < 64; c++) s = fmaf(W[k * 256 + h * 64 + c], a[h * 64 + c], s);
            V[b * 1024 + k * 4 + h] = s;
        }
    } else {
        const float* W = W_out + (size_t)(b - 6) * 16384;
        const float* a = ad_out + (size_t)(b - 6) * 64;
        float s = 0.f;
        for (int c = 0; c < 64; c++) s = fmaf(W[k * 64 + c], a[c], s);
        V[b * 1024 + k] = s;
    }
}

// ---------------- per-segment softmax+gather accumulate, H=4 ----------------
__device__ __forceinline__ void edge4(const int* __restrict__ rowptr,
                                      const int* __restrict__ srcp,
                                      const float* __restrict__ als, const float* ad,
                                      const float* __restrict__ hsrc,
                                      float* __restrict__ alpha, int w, int lane, int c0,
                                      int c1, int hsel, float4& a0, float4& a1) {
    int s0 = rowptr[w], s1 = rowptr[w + 1];
    int deg = s1 - s0;
    if (deg <= 0) return;
    const float NINF = __int_as_float(0xff800000u);
    if (deg <= 32) {
        int sreg = (lane < deg) ? srcp[s0 + lane] : 0;
        float ex[4];
#pragma unroll
        for (int h = 0; h < 4; h++) {
            float e = NINF;
            if (lane < deg) {
                e = als[(size_t)sreg * 4 + h] + ad[h];
                e = e > 0.f ? e : NEG * e;
            }
            ex[h] = e;
        }
        float inv[4];
#pragma unroll
        for (int h = 0; h < 4; h++) {
            float m = ex[h];
#pragma unroll
            for (int o = 16; o; o >>= 1) m = fmaxf(m, __shfl_xor_sync(0xffffffffu, m, o));
            float v = (lane < deg) ? __expf(ex[h] - m) : 0.f;
            ex[h] = v;
#pragma unroll
            for (int o = 16; o; o >>= 1) v += __shfl_xor_sync(0xffffffffu, v, o);
            inv[h] = 1.f / (v + 1e-16f);
        }
        float inv0 = hsel ? inv[1] : inv[0];
        float inv1 = hsel ? inv[3] : inv[2];
        for (int i = 0; i < deg; i++) {
            int s = __shfl_sync(0xffffffffu, sreg, i);
            float e0 = __shfl_sync(0xffffffffu, ex[0], i);
            float e1 = __shfl_sync(0xffffffffu, ex[1], i);
            float e2 = __shfl_sync(0xffffffffu, ex[2], i);
            float e3 = __shfl_sync(0xffffffffu, ex[3], i);
            float w0 = (hsel ? e1 : e0) * inv0;
            float w1 = (hsel ? e3 : e2) * inv1;
            const float4* hr = (const float4*)(hsrc + (size_t)s * 256);
            float4 v0 = hr[c0], v1 = hr[c1];
            a0.x = fmaf(v0.x, w0, a0.x); a0.y = fmaf(v0.y, w0, a0.y);
            a0.z = fmaf(v0.z, w0, a0.z); a0.w = fmaf(v0.w, w0, a0.w);
            a1.x = fmaf(v1.x, w1, a1.x); a1.y = fmaf(v1.y, w1, a1.y);
            a1.z = fmaf(v1.z, w1, a1.z); a1.w = fmaf(v1.w, w1, a1.w);
        }
    } else {
        float mx[4], sm[4], inv[4];
#pragma unroll
        for (int h = 0; h < 4; h++) { mx[h] = NINF; sm[h] = 0.f; }
        for (int j = s0 + lane; j < s1; j += 32) {
            int s = srcp[j];
#pragma unroll
            for (int h = 0; h < 4; h++) {
                float e = als[(size_t)s * 4 + h] + ad[h];
                e = e > 0.f ? e : NEG * e;
                alpha[(size_t)j * 4 + h] = e;
                mx[h] = fmaxf(mx[h], e);
            }
        }
#pragma unroll
        for (int h = 0; h < 4; h++)
#pragma unroll
            for (int o = 16; o; o >>= 1)
                mx[h] = fmaxf(mx[h], __shfl_xor_sync(0xffffffffu, mx[h], o));
        for (int j = s0 + lane; j < s1; j += 32) {
#pragma unroll
            for (int h = 0; h < 4; h++) {
                float e2 = __expf(alpha[(size_t)j * 4 + h] - mx[h]);
                alpha[(size_t)j * 4 + h] = e2;
                sm[h] += e2;
            }
        }
#pragma unroll
        for (int h = 0; h < 4; h++) {
#pragma unroll
            for (int o = 16; o; o >>= 1) sm[h] += __shfl_xor_sync(0xffffffffu, sm[h], o);
            inv[h] = 1.f / (sm[h] + 1e-16f);
        }
        float inv0 = inv[hsel], inv1 = inv[hsel + 2];
        for (int j = s0; j < s1; j++) {
            int s = srcp[j];
            float4 al = *(const float4*)(alpha + (size_t)j * 4);
            const float4* hr = (const float4*)(hsrc + (size_t)s * 256);
            float4 v0 = hr[c0], v1 = hr[c1];
            float w0 = (hsel ? al.y : al.x) * inv0;
            float w1 = (hsel ? al.w : al.z) * inv1;
            a0.x = fmaf(v0.x, w0, a0.x); a0.y = fmaf(v0.y, w0, a0.y);
            a0.z = fmaf(v0.z, w0, a0.z); a0.w = fmaf(v0.w, w0, a0.w);
            a1.x = fmaf(v1.x, w1, a1.x); a1.y = fmaf(v1.y, w1, a1.y);
            a1.z = fmaf(v1.z, w1, a1.z); a1.w = fmaf(v1.w, w1, a1.w);
        }
    }
}

// ---------------- mega aggregation: one launch per hidden layer ----------------
__global__ void __launch_bounds__(256) k_lagg4(
    const int* __restrict__ rp0, const int* __restrict__ sp0, const int* __restrict__ rp1,
    const int* __restrict__ sp1, const int* __restrict__ rp2, const int* __restrict__ sp2,
    const float* __restrict__ h0, const float* __restrict__ h1, const float* __restrict__ h2,
    const float* __restrict__ als0, const float* __restrict__ als1,
    const float* __restrict__ als2, const float* __restrict__ ald2,
    const float* __restrict__ V0, const float* __restrict__ V1,
    const float* __restrict__ xp_in, const float* __restrict__ xd_in,
    const float* __restrict__ b0, const float* __restrict__ b1, const float* __restrict__ b2,
    float* __restrict__ alpha0, float* __restrict__ alpha1, float* __restrict__ alpha2,
    float* __restrict__ xp_out, float* __restrict__ xd_out, int act) {
    __shared__ float Vs0[1024];
    __shared__ float Vs1[1024];
    for (int i = threadIdx.x; i < 1024; i += 256) {
        Vs0[i] = V0[i];
        Vs1[i] = V1[i];
    }
    __syncthreads();
    int n = (blockIdx.x * 256 + threadIdx.x) >> 5;
    int lane = threadIdx.x & 31;
    if (n >= NP + ND) return;
    int c0 = lane, c1 = lane + 32, hsel = lane >> 4;
    float4 a0 = make_float4(0.f, 0.f, 0.f, 0.f), a1 = a0;
    float4 o0, o1;
    float4* orow;
    if (n < NP) {
        int w = n;
        const float* xr = xp_in + (size_t)w * 256;
        float p[4] = {0.f, 0.f, 0.f, 0.f};
#pragma unroll
        for (int tt = 0; tt < 8; tt++) {
            int k = lane + tt * 32;
            float x = xr[k];
#pragma unroll
            for (int h = 0; h < 4; h++) p[h] = fmaf(x, Vs0[k * 4 + h], p[h]);
        }
        float ad0[4];
#pragma unroll
        for (int h = 0; h < 4; h++) {
#pragma unroll
            for (int o = 16; o; o >>= 1) p[h] += __shfl_xor_sync(0xffffffffu, p[h], o);
            ad0[h] = p[h];
        }
        float ad2[4];
#pragma unroll
        for (int h = 0; h < 4; h++) ad2[h] = ald2[(size_t)w * 4 + h];
        edge4(rp0, sp0, als0, ad0, h0, alpha0, w, lane, c0, c1, hsel, a0, a1);
        edge4(rp2, sp2, als2, ad2, h2, alpha2, w, lane, c0, c1, hsel, a0, a1);
        const float4* B0 = (const float4*)b0;
        const float4* B2 = (const float4*)b2;
        float4 bb0 = B0[c0], bb1 = B0[c1];
        float4 t0 = B2[c0], t1 = B2[c1];
        bb0.x += t0.x; bb0.y += t0.y; bb0.z += t0.z; bb0.w += t0.w;
        bb1.x += t1.x; bb1.y += t1.y; bb1.z += t1.z; bb1.w += t1.w;
        o0 = make_float4(a0.x + bb0.x, a0.y + bb0.y, a0.z + bb0.z, a0.w + bb0.w);
        o1 = make_float4(a1.x + bb1.x, a1.y + bb1.y, a1.z + bb1.z, a1.w + bb1.w);
        orow = (float4*)(xp_out + (size_t)w * 256);
    } else {
        int w = n - NP;
        const float* xr = xd_in + (size_t)w * 256;
        float p[4] = {0.f, 0.f, 0.f, 0.f};
#pragma unroll
        for (int tt = 0; tt < 8; tt++) {
            int k = lane + tt * 32;
            float x = xr[k];
#pragma unroll
            for (int h = 0; h < 4; h++) p[h] = fmaf(x, Vs1[k * 4 + h], p[h]);
        }
        float ad1[4];
#pragma unroll
        for (int h = 0; h < 4; h++) {
#pragma unroll
            for (int o = 16; o; o >>= 1) p[h] += __shfl_xor_sync(0xffffffffu, p[h], o);
            ad1[h] = p[h];
        }
        edge4(rp1, sp1, als1, ad1, h1, alpha1, w, lane, c0, c1, hsel, a0, a1);
        const float4* B1 = (const float4*)b1;
        float4 bb0 = B1[c0], bb1 = B1[c1];
        o0 = make_float4(a0.x + bb0.x, a0.y + bb0.y, a0.z + bb0.z, a0.w + bb0.w);
        o1 = make_float4(a1.x + bb1.x, a1.y + bb1.y, a1.z + bb1.z, a1.w + bb1.w);
        orow = (float4*)(xd_out + (size_t)w * 256);
    }
    if (act) {
        o0.x = eluf(o0.x); o0.y = eluf(o0.y); o0.z = eluf(o0.z); o0.w = eluf(o0.w);
        o1.x = eluf(o1.x); o1.y = eluf(o1.y); o1.z = eluf(o1.z); o1.w = eluf(o1.w);
    }
    orow[c0] = o0;
    orow[c1] = o1;
}

// ---------------- per-segment softmax+gather, H=1, 64 cols ----------------
__device__ __forceinline__ void edge1(const int* __restrict__ rowptr,
                                      const int* __restrict__ srcp,
                                      const float* __restrict__ als, float ad,
                                      const float* __restrict__ hsrc,
                                      float* __restrict__ alpha, int w, int lane, float& a0,
                                      float& a1) {
    int s0 = rowptr[w], s1 = rowptr[w + 1];
    int deg = s1 - s0;
    if (deg <= 0) return;
    const float NINF = __int_as_float(0xff800000u);
    if (deg <= 32) {
        int sreg = (lane < deg) ? srcp[s0 + lane] : 0;
        float e = NINF;
        if (lane < deg) {
            e = als[sreg] + ad;
            e = e > 0.f ? e : NEG * e;
        }
        float m = e;
#pragma unroll
        for (int o = 16; o; o >>= 1) m = fmaxf(m, __shfl_xor_sync(0xffffffffu, m, o));
        float ex = (lane < deg) ? __expf(e - m) : 0.f;
        float sm = ex;
#pragma unroll
        for (int o = 16; o; o >>= 1) sm += __shfl_xor_sync(0xffffffffu, sm, o);
        float inv = 1.f / (sm + 1e-16f);
        for (int i = 0; i < deg; i++) {
            int s = __shfl_sync(0xffffffffu, sreg, i);
            float al = __shfl_sync(0xffffffffu, ex, i) * inv;
            const float* hr = hsrc + (size_t)s * 64;
            a0 = fmaf(hr[lane], al, a0);
            a1 = fmaf(hr[lane + 32], al, a1);
        }
    } else {
        float mx = NINF, sm = 0.f;
        for (int j = s0 + lane; j < s1; j += 32) {
            int s = srcp[j];
            float e = als[s] + ad;
            e = e > 0.f ? e : NEG * e;
            alpha[j] = e;
            mx = fmaxf(mx, e);
        }
#pragma unroll
        for (int o = 16; o; o >>= 1) mx = fmaxf(mx, __shfl_xor_sync(0xffffffffu, mx, o));
        for (int j = s0 + lane; j < s1; j += 32) {
            float ex = __expf(alpha[j] - mx);
            alpha[j] = ex;
            sm += ex;
        }
#pragma unroll
        for (int o = 16; o; o >>= 1) sm += __shfl_xor_sync(0xffffffffu, sm, o);
        float inv = 1.f / (sm + 1e-16f);
        for (int j = s0; j < s1; j++) {
            int s = srcp[j];
            float al = alpha[j] * inv;
            const float* hr = hsrc + (size_t)s * 64;
            a0 = fmaf(hr[lane], al, a0);
            a1 = fmaf(hr[lane + 32], al, a1);
        }
    }
}

// ---------------- mega aggregation for output layer ----------------
__global__ void __launch_bounds__(256) k_lagg1(
    const int* __restrict__ rp0, const int* __restrict__ sp0, const int* __restrict__ rp1,
    const int* __restrict__ sp1, const int* __restrict__ rp2, const int* __restrict__ sp2,
    const float* __restrict__ h0, const float* __restrict__ h1, const float* __restrict__ h2,
    const float* __restrict__ als0, const float* __restrict__ als1,
    const float* __restrict__ als2, const float* __restrict__ ald2,
    const float* __restrict__ V0, const float* __restrict__ V1,
    const float* __restrict__ xp_in, const float* __restrict__ xd_in,
    const float* __restrict__ b0, const float* __restrict__ b1, const float* __restrict__ b2,
    float* __restrict__ alpha0, float* __restrict__ alpha1, float* __restrict__ alpha2,
    float* __restrict__ op, float* __restrict__ od) {
    __shared__ float Vs0[256];
    __shared__ float Vs1[256];
    for (int i = threadIdx.x; i < 256; i += 256) {
        Vs0[i] = V0[i];
        Vs1[i] = V1[i];
    }
    __syncthreads();
    int n = (blockIdx.x * 256 + threadIdx.x) >> 5;
    int lane = threadIdx.x & 31;
    if (n >= NP + ND) return;
    float a0 = 0.f, a1 = 0.f;
    float* orow;
    float bb0, bb1;
    if (n < NP) {
        int w = n;
        const float* xr = xp_in + (size_t)w * 256;
        float p = 0.f;
#pragma unroll
        for (int tt = 0; tt < 8; tt++) {
            int k = lane + tt * 32;
            p = fmaf(xr[k], Vs0[k], p);
        }
#pragma unroll
        for (int o = 16; o; o >>= 1) p += __shfl_xor_sync(0xffffffffu, p, o);
        edge1(rp0, sp0, als0, p, h0, alpha0, w, lane, a0, a1);
        edge1(rp2, sp2, als2, ald2[w], h2, alpha2, w, lane, a0, a1);
        bb0 = b0[lane] + b2[lane];
        bb1 = b0[lane + 32] + b2[lane + 32];
        orow = op + (size_t)w * 64;
    } else {
        int w = n - NP;
        const float* xr = xd_in + (size_t)w * 256;
        float p = 0.f;
#pragma unroll
        for (int tt = 0; tt < 8; tt++) {
            int k = lane + tt * 32;
            p = fmaf(xr[k], Vs1[k], p);
        }
#pragma unroll
        for (int o = 16; o; o >>= 1) p += __shfl_xor_sync(0xffffffffu, p, o);
        edge1(rp1, sp1, als1, p, h1, alpha1, w, lane, a0, a1);
        bb0 = b1[lane];
        bb1 = b1[lane + 32];
        orow = od + (size_t)w * 64;
    }
    orow[lane] = a0 + bb0;
    orow[lane + 32] = a1 + bb1;
}

// =====================================================================
extern "C" void kernel_launch(void* const* d_in, const int* in_sizes, int n_in,
                              void* d_out, int out_size) {
    const float* x_drug = (const float*)d_in[0];
    const float* x_prot = (const float*)d_in[1];
    const int* srcA[3] = {(const int*)d_in[2], (const int*)d_in[4], (const int*)d_in[6]};
    const int* dstA[3] = {(const int*)d_in[3], (const int*)d_in[5], (const int*)d_in[7]};
    const float* linW_d = (const float*)d_in[8];
    const float* linb_d = (const float*)d_in[9];
    const float* linW_p = (const float*)d_in[10];
    const float* linb_p = (const float*)d_in[11];
    const float* W_hid = (const float*)d_in[12];
    const float* as_hid = (const float*)d_in[13];
    const float* ad_hid = (const float*)d_in[14];
    const float* b_hid = (const float*)d_in[15];
    const float* W_out = (const float*)d_in[16];
    const float* as_out = (const float*)d_in[17];
    const float* ad_out = (const float*)d_in[18];
    const float* b_out = (const float*)d_in[19];
    float* outp = (float*)d_out;

    int E[3] = {in_sizes[2], in_sizes[4], in_sizes[6]};
    int maxE = E[0] > E[1] ? E[0] : E[1];
    if (E[2] > maxE) maxE = E[2];

    float *xdb, *xpb, *hb, *alpha, *als, *ald, *V;
    int *rp, *sp, *cnt;
    __nv_bfloat16 *whi, *wlo;
    cudaGetSymbolAddress((void**)&xdb, g_xd);
    cudaGetSymbolAddress((void**)&xpb, g_xp);
    cudaGetSymbolAddress((void**)&hb, g_h);
    cudaGetSymbolAddress((void**)&alpha, g_alpha);
    cudaGetSymbolAddress((void**)&als, g_als);
    cudaGetSymbolAddress((void**)&ald, g_ald);
    cudaGetSymbolAddress((void**)&V, g_V);
    cudaGetSymbolAddress((void**)&rp, g_rowptr);
    cudaGetSymbolAddress((void**)&sp, g_srcp);
    cudaGetSymbolAddress((void**)&cnt, g_cnt);
    cudaGetSymbolAddress((void**)&whi, g_whi);
    cudaGetSymbolAddress((void**)&wlo, g_wlo);

    float* xd[2] = {xdb, xdb + (size_t)ND * HIDW};
    float* xp[2] = {xpb, xpb + (size_t)NP * HIDW};
    float* h0 = hb;
    float* h1 = hb + (size_t)NP * HIDW;
    float* h2 = hb + 2 * (size_t)NP * HIDW;
    int* rowptr[3] = {rp, rp + (NP + 1), rp + 2 * (NP + 1)};
    int* srcp[3] = {sp, sp + EMAX, sp + 2 * EMAX};
    float* als0 = als;
    float* als1 = als + (size_t)NP * 4;
    float* als2 = als + 2 * (size_t)NP * 4;
    float* alpha0 = alpha;
    float* alpha1 = alpha + (size_t)EMAX * 4;
    float* alpha2 = alpha + 2 * (size_t)EMAX * 4;

    const int SM128 = 2048 + 4 * (128 * 40 * 2) + 4 * (128 * 40 * 2);  // 83968
    const int SM64 = 2048 + 4 * (128 * 40 * 2) + 4 * (64 * 40 * 2);    // 63488
    cudaFuncSetAttribute(k_mma<128, true, true, 0>,
                         cudaFuncAttributeMaxDynamicSharedMemorySize, SM128);
    cudaFuncSetAttribute(k_mma<128, false, false, 4>,
                         cudaFuncAttributeMaxDynamicSharedMemorySize, SM128);
    cudaFuncSetAttribute(k_mma<64, false, false, 1>,
                         cudaFuncAttributeMaxDynamicSharedMemorySize, SM64);

    size_t o_lind = 0;
    size_t o_linp = 32768;
    size_t o_hid0 = 98304;
    size_t o_out0 = 491520;

    int ebx = (maxE + 255) / 256;
    int gx128 = (NP + 127) / 128;  // 313, covers both ND and NP (early exit)

    // L0: zero cnt
    k_zero<<<(3 * NP + 255) / 256, 256>>>(cnt, 3 * NP);
    // L1: count
    {
        dim3 gc(ebx, 3);
        k_count3<<<gc, 256>>>(dstA[0], dstA[1], dstA[2], E[0], E[1], E[2], cnt);
    }
    // L2: weight split
    {
        dim3 gw(256, 11);
        k_splitW_all<<<gw, 256>>>(linW_d, linW_p, W_hid, W_out, whi, wlo);
    }
    // L3: input projections (batched z=2) — ncu capture target
    {
        GemmCfg3 P{};
        P.c[0] = {x_drug, whi + o_lind, wlo + o_lind, linb_d, nullptr, nullptr,
                  xd[0], nullptr, nullptr, ND, 128};
        P.c[1] = {x_prot, whi + o_linp, wlo + o_linp, linb_p, nullptr, nullptr,
                  xp[0], nullptr, nullptr, NP, 256};
        P.c[2] = P.c[1];
        dim3 gg(gx128, 2, 2);
        k_mma<128, true, true, 0><<<gg, 256, SM128>>>(P);
    }
    // L4: scan (+re-zero cnt)
    k_scan3<<<3, 1024>>>(cnt, rp, NP, ND, NP);
    // L5: scatter
    {
        dim3 gs(ebx, 3);
        k_scatter3<<<gs, 256>>>(srcA[0], srcA[1], srcA[2], dstA[0], dstA[1], dstA[2], E[0],
                                E[1], E[2], rp, cnt, sp);
    }
    // L6: V vectors
    k_makeV_all<<<9, 256>>>(W_hid, ad_hid, W_out, ad_out, V);

    int cur = 0, nxt = 1;
    int naggb = (NP + ND + 7) / 8;

    // ---- hidden layers ----
    for (int l = 0; l < 2; l++) {
        int i0 = l * 3 + 0, i1 = l * 3 + 1, i2 = l * 3 + 2;
        // batched GEMM (3 edge types)
        {
            GemmCfg3 P{};
            P.c[0] = {xd[cur], whi + o_hid0 + (size_t)i0 * 65536,
                      wlo + o_hid0 + (size_t)i0 * 65536, nullptr,
                      as_hid + (size_t)i0 * 256, nullptr, h0, als0, nullptr, ND, 256};
            P.c[1] = {xp[cur], whi + o_hid0 + (size_t)i1 * 65536,
                      wlo + o_hid0 + (size_t)i1 * 65536, nullptr,
                      as_hid + (size_t)i1 * 256, nullptr, h1, als1, nullptr, NP, 256};
            P.c[2] = {xp[cur], whi + o_hid0 + (size_t)i2 * 65536,
                      wlo + o_hid0 + (size_t)i2 * 65536, nullptr,
                      as_hid + (size_t)i2 * 256, ad_hid + (size_t)i2 * 256, h2, als2, ald,
                      NP, 256};
            dim3 gg(gx128, 2, 3);
            k_mma<128, false, false, 4><<<gg, 256, SM128>>>(P);
        }
        // mega aggregation
        k_lagg4<<<naggb, 256>>>(rowptr[0], srcp[0], rowptr[1], srcp[1], rowptr[2], srcp[2],
                                h0, h1, h2, als0, als1, als2, ald, V + (size_t)i0 * 1024,
                                V + (size_t)i1 * 1024, xp[cur], xd[cur],
                                b_hid + (size_t)i0 * 256, b_hid + (size_t)i1 * 256,
                                b_hid + (size_t)i2 * 256, alpha0, alpha1, alpha2, xp[nxt],
                                xd[nxt], 1);
        cur = nxt;
        nxt = 1 - nxt;
    }

    // ---- output layer ----
    float* od = outp;
    float* op = outp + (size_t)ND * OUTC;
    {
        GemmCfg3 P{};
        P.c[0] = {xd[cur], whi + o_out0, wlo + o_out0, nullptr, as_out, nullptr,
                  h0, als0, nullptr, ND, 256};
        P.c[1] = {xp[cur], whi + o_out0 + 16384, wlo + o_out0 + 16384, nullptr,
                  as_out + OUTC, nullptr, h1, als1, nullptr, NP, 256};
        P.c[2] = {xp[cur], whi + o_out0 + 2 * 16384, wlo + o_out0 + 2 * 16384, nullptr,
                  as_out + 2 * OUTC, ad_out + 2 * OUTC, h2, als2, ald, NP, 256};
        dim3 gg(gx128, 1, 3);
        k_mma<64, false, false, 1><<<gg, 256, SM64>>>(P);
    }
    k_lagg1<<<naggb, 256>>>(rowptr[0], srcp[0], rowptr[1], srcp[1], rowptr[2], srcp[2], h0,
                            h1, h2, als0, als1, als2, ald, V + 6 * 1024, V + 7 * 1024,
                            xp[cur], xd[cur], b_out + 0 * OUTC, b_out + 1 * OUTC,
                            b_out + 2 * OUTC, alpha0, alpha1, alpha2, op, od);

    (void)n_in;
    (void)out_size;
}

// round 13
// speedup vs baseline: 3.3138x; 1.0773x over previous
#include <cuda_runtime.h>
#include <cuda_bf16.h>
#include <cstdint>

// Problem constants (fixed shapes)
#define ND 20000
#define NP 40000
#define EMAX 300000
#define HIDW 256
#define OUTC 64
#define NEG 0.2f

// ---------------- static device scratch (allocation-free rule) ----------------
__device__ float g_xd[2][ND * HIDW];
__device__ float g_xp[2][NP * HIDW];
__device__ float g_h[3][NP * HIDW];
__device__ float g_alpha[3 * EMAX * 4];
__device__ float g_als[3 * NP * 4];
__device__ float g_ald[NP * 4];
__device__ float g_V[9 * 1024];
__device__ int   g_rowptr[3 * (NP + 1)];
__device__ int   g_srcp[3 * EMAX];
__device__ int   g_cnt[3 * NP];
#define WTOT 540672
__device__ __nv_bfloat16 g_whi[WTOT];
__device__ __nv_bfloat16 g_wlo[WTOT];

// ======================= helpers =======================
__device__ __forceinline__ uint32_t smem_u32(const void* p) {
    uint32_t a;
    asm("{ .reg .u64 t; cvta.to.shared.u64 t, %1; cvt.u32.u64 %0, t; }" : "=r"(a) : "l"(p));
    return a;
}
__device__ __forceinline__ void cp_async8(uint32_t dst, const void* src) {
    asm volatile("cp.async.ca.shared.global [%0], [%1], 8;" :: "r"(dst), "l"(src));
}
#define CP_COMMIT() asm volatile("cp.async.commit_group;" ::: "memory")
#define CP_WAIT0()  asm volatile("cp.async.wait_group 0;" ::: "memory")

__device__ __forceinline__ void mma16816(float* c, const uint32_t* a, const uint32_t* b) {
    asm volatile(
        "mma.sync.aligned.m16n8k16.row.col.f32.bf16.bf16.f32 "
        "{%0,%1,%2,%3}, {%4,%5,%6,%7}, {%8,%9}, {%0,%1,%2,%3};"
        : "+f"(c[0]), "+f"(c[1]), "+f"(c[2]), "+f"(c[3])
        : "r"(a[0]), "r"(a[1]), "r"(a[2]), "r"(a[3]), "r"(b[0]), "r"(b[1]));
}
__device__ __forceinline__ void ldsm4(uint32_t* r, uint32_t addr) {
    asm volatile("ldmatrix.sync.aligned.m8n8.x4.shared.b16 {%0,%1,%2,%3}, [%4];"
                 : "=r"(r[0]), "=r"(r[1]), "=r"(r[2]), "=r"(r[3]) : "r"(addr));
}

__device__ __forceinline__ uint32_t pack_bf2(float x, float y) {
    __nv_bfloat162 t = __floats2bfloat162_rn(x, y);
    return *reinterpret_cast<uint32_t*>(&t);
}
__device__ __forceinline__ float eluf(float v) { return v > 0.f ? v : expm1f(v); }

// ---------------- all-weights pre-transpose + bf16 split in ONE launch ----------------
__global__ void k_splitW_all(const float* __restrict__ linW_d, const float* __restrict__ linW_p,
                             const float* __restrict__ W_hid, const float* __restrict__ W_out,
                             __nv_bfloat16* __restrict__ hi, __nv_bfloat16* __restrict__ lo) {
    int id = blockIdx.y;
    int i = blockIdx.x * 256 + threadIdx.x;
    const float* W;
    size_t off;
    int K, N;
    if (id == 0) { W = linW_d; off = 0; K = 128; N = 256; }
    else if (id == 1) { W = linW_p; off = 32768; K = 256; N = 256; }
    else if (id < 8) {
        W = W_hid + (size_t)(id - 2) * 65536; off = 98304 + (size_t)(id - 2) * 65536;
        K = 256; N = 256;
    } else {
        W = W_out + (size_t)(id - 8) * 16384; off = 491520 + (size_t)(id - 8) * 16384;
        K = 256; N = 64;
    }
    if (i >= N * K) return;
    int n = i / K, k = i % K;
    float v = W[(size_t)k * N + n];
    __nv_bfloat16 h = __float2bfloat16(v);
    hi[off + i] = h;
    lo[off + i] = __float2bfloat16(v - __bfloat162float(h));
}

// ============ batched mma.sync GEMM (cfg selected by blockIdx.z) ============
struct GemmCfg {
    const float* A;
    const __nv_bfloat16* Bhi;
    const __nv_bfloat16* Blo;
    const float* bias;
    const float* asrc;
    const float* adst;
    float* C;
    float* als;
    float* ald;
    int M;
    int K;
};
struct GemmCfg3 { GemmCfg c[3]; };

template <int BN, bool BIAS, bool RELU, int HALS>
__global__ void __launch_bounds__(256, 2) k_mma(GemmCfg3 P) {
    GemmCfg cfg = P.c[blockIdx.z];
    const int M = cfg.M, K = cfg.K;
    if ((int)blockIdx.x * 128 >= M) return;

    extern __shared__ char smem[];
    constexpr int WN = BN / 2;
    constexpr int NTILES = WN / 8;
    constexpr int ABUF = 128 * 40 * 2;
    constexpr int BBUF = BN * 40 * 2;
    constexpr int S_A = 2048;
    constexpr int S_B = S_A + 4 * ABUF;
    float* sBias = (float*)(smem);
    float* sAsrc = (float*)(smem + 512);
    float* sAdst = (float*)(smem + 1024);
    __shared__ float sr1[128];
    __shared__ float sr2[128];

    const bool dual = (HALS != 0) && (cfg.adst != nullptr);

    int tid = threadIdx.x;
    int wid = tid >> 5, lane = tid & 31;
    int g = lane >> 2, tg = lane & 3;
    int warp_m = wid & 3, warp_n = wid >> 2;
    int bm = blockIdx.x * 128, bn = blockIdx.y * BN;

    if (BIAS)
        for (int i = tid; i < BN; i += 256) sBias[i] = cfg.bias[bn + i];
    if (HALS) {
        for (int i = tid; i < BN; i += 256) sAsrc[i] = cfg.asrc[bn + i];
        if (dual)
            for (int i = tid; i < BN; i += 256) sAdst[i] = cfg.adst[bn + i];
    }

    int arow = tid >> 1;
    int akq = (tid & 1) * 16;
    bool aval_base = (bm + arow) < M;
    constexpr int CH = BN * 8 / 256;

    float acc[2][NTILES][4];
#pragma unroll
    for (int mi = 0; mi < 2; mi++)
#pragma unroll
        for (int nt = 0; nt < NTILES; nt++)
#pragma unroll
            for (int q = 0; q < 4; q++) acc[mi][nt][q] = 0.f;

    uint32_t sbase = smem_u32(smem);
    const float* A = cfg.A;
    const __nv_bfloat16* Bthi = cfg.Bhi;
    const __nv_bfloat16* Btlo = cfg.Blo;

    // ---- ldmatrix per-lane address offsets (bytes, relative to tile base) ----
    // A: matrices {rows r0..r0+7 @kk, rows r0+8.. @kk, same @kk+8} -> lane row r0+(lane&15), col +8 if lane>=16
    uint32_t aoff = (uint32_t)((warp_m * 32 + (lane & 15)) * 40 + ((lane >> 4) << 3)) * 2;
    // B: per ntile-pair tp: rows n(tp*2 + bit4) + (lane&7), col +8 if bit3
    uint32_t boff[NTILES / 2];
#pragma unroll
    for (int tp = 0; tp < NTILES / 2; tp++)
        boff[tp] = (uint32_t)((warp_n * WN + (tp * 2 + ((lane >> 4) & 1)) * 8 + (lane & 7)) * 40 +
                              (((lane >> 3) & 1) << 3)) * 2;

    auto loadA = [&](int k0, float4* ar) {
        const float* src = A + (size_t)(bm + arow) * K + k0 + akq;
#pragma unroll
        for (int i = 0; i < 4; i++)
            ar[i] = aval_base ? ((const float4*)src)[i] : make_float4(0.f, 0.f, 0.f, 0.f);
    };
    auto storeA = [&](const float4* ar, int buf) {
        char* dh = smem + S_A + buf * 2 * ABUF;
        char* dl = dh + ABUF;
#pragma unroll
        for (int i = 0; i < 4; i++) {
            float4 f = ar[i];
            __nv_bfloat16 hx = __float2bfloat16(f.x), hy = __float2bfloat16(f.y);
            __nv_bfloat16 hz = __float2bfloat16(f.z), hw = __float2bfloat16(f.w);
            __nv_bfloat162 H01(hx, hy), H23(hz, hw);
            uint32_t h01 = *(uint32_t*)&H01, h23 = *(uint32_t*)&H23;
            uint32_t l01 = pack_bf2(f.x - __bfloat162float(hx), f.y - __bfloat162float(hy));
            uint32_t l23 = pack_bf2(f.z - __bfloat162float(hz), f.w - __bfloat162float(hw));
            int off = (arow * 40 + akq + i * 4) * 2;
            *(uint2*)(dh + off) = make_uint2(h01, h23);
            *(uint2*)(dl + off) = make_uint2(l01, l23);
        }
    };
    auto loadB = [&](int k0, int buf) {
        uint32_t dh = sbase + S_B + buf * 2 * BBUF;
        uint32_t dl = dh + BBUF;
#pragma unroll
        for (int i = 0; i < CH; i++) {
            int c = tid + i * 256;
            int row = c >> 3, kc = c & 7;
            size_t go = (size_t)(bn + row) * K + k0 + kc * 4;
            uint32_t so = row * 80 + kc * 8;
            cp_async8(dh + so, Bthi + go);
            cp_async8(dl + so, Btlo + go);
        }
        CP_COMMIT();
    };
    auto compute = [&](int buf) {
        uint32_t Ah = sbase + S_A + buf * 2 * ABUF;
        uint32_t Al = Ah + ABUF;
        uint32_t Bh = sbase + S_B + buf * 2 * BBUF;
        uint32_t Bl = Bh + BBUF;
#pragma unroll
        for (int kk = 0; kk < 32; kk += 16) {
            uint32_t ah[2][4], al[2][4];
#pragma unroll
            for (int mi = 0; mi < 2; mi++) {
                uint32_t o = aoff + mi * (16 * 80) + kk * 2;
                ldsm4(ah[mi], Ah + o);
                ldsm4(al[mi], Al + o);
            }
#pragma unroll
            for (int tp = 0; tp < NTILES / 2; tp++) {
                uint32_t o = boff[tp] + kk * 2;
                uint32_t bh4[4], bl4[4];
                ldsm4(bh4, Bh + o);
                ldsm4(bl4, Bl + o);
#pragma unroll
                for (int sub = 0; sub < 2; sub++) {
                    int nt = tp * 2 + sub;
                    const uint32_t* bh = bh4 + sub * 2;
                    const uint32_t* bl = bl4 + sub * 2;
#pragma unroll
                    for (int mi = 0; mi < 2; mi++) {
                        mma16816(acc[mi][nt], ah[mi], bh);
                        mma16816(acc[mi][nt], ah[mi], bl);
                        mma16816(acc[mi][nt], al[mi], bh);
                    }
                }
            }
        }
    };

    int nstages = K / 32;
    float4 ar[4];
    loadA(0, ar);
    loadB(0, 0);
    storeA(ar, 0);
    CP_WAIT0();
    __syncthreads();
    for (int s = 0; s < nstages; s++) {
        int cur = s & 1, nxt = cur ^ 1;
        bool more = (s + 1) < nstages;
        if (more) {
            loadA((s + 1) * 32, ar);
            loadB((s + 1) * 32, nxt);
        }
        compute(cur);
        if (more) storeA(ar, nxt);
        CP_WAIT0();
        __syncthreads();
    }

    // ---- epilogue ----
    const int NT = (BN == 128) ? 256 : 64;
    float sals[2][2], sald[2][2];
    sals[0][0] = sals[0][1] = sals[1][0] = sals[1][1] = 0.f;
    sald[0][0] = sald[0][1] = sald[1][0] = sald[1][1] = 0.f;
#pragma unroll
    for (int mi = 0; mi < 2; mi++) {
        int r0 = bm + warp_m * 32 + mi * 16 + g;
        int r1 = r0 + 8;
#pragma unroll
        for (int nt = 0; nt < NTILES; nt++) {
            int nloc = warp_n * WN + nt * 8 + tg * 2;
            int n0 = bn + nloc;
            float* cc = acc[mi][nt];
            float v00 = cc[0], v01 = cc[1], v10 = cc[2], v11 = cc[3];
            if (BIAS) {
                v00 += sBias[nloc]; v01 += sBias[nloc + 1];
                v10 += sBias[nloc]; v11 += sBias[nloc + 1];
            }
            if (RELU) {
                v00 = fmaxf(v00, 0.f); v01 = fmaxf(v01, 0.f);
                v10 = fmaxf(v10, 0.f); v11 = fmaxf(v11, 0.f);
            }
            if (r0 < M) *(float2*)(cfg.C + (size_t)r0 * NT + n0) = make_float2(v00, v01);
            if (r1 < M) *(float2*)(cfg.C + (size_t)r1 * NT + n0) = make_float2(v10, v11);
            if (HALS) {
                float a0 = sAsrc[nloc], a1 = sAsrc[nloc + 1];
                sals[mi][0] += v00 * a0 + v01 * a1;
                sals[mi][1] += v10 * a0 + v11 * a1;
                if (dual) {
                    float d0 = sAdst[nloc], d1 = sAdst[nloc + 1];
                    sald[mi][0] += v00 * d0 + v01 * d1;
                    sald[mi][1] += v10 * d0 + v11 * d1;
                }
            }
        }
    }
    if (HALS) {
        if (HALS == 1) {
            for (int i = tid; i < 128; i += 256) { sr1[i] = 0.f; sr2[i] = 0.f; }
            __syncthreads();
        }
#pragma unroll
        for (int mi = 0; mi < 2; mi++)
#pragma unroll
            for (int hf = 0; hf < 2; hf++) {
                float s = sals[mi][hf];
                s += __shfl_xor_sync(0xffffffffu, s, 1);
                s += __shfl_xor_sync(0xffffffffu, s, 2);
                float s2 = sald[mi][hf];
                s2 += __shfl_xor_sync(0xffffffffu, s2, 1);
                s2 += __shfl_xor_sync(0xffffffffu, s2, 2);
                if (tg == 0) {
                    int rloc = warp_m * 32 + mi * 16 + g + hf * 8;
                    int r = bm + rloc;
                    if (HALS == 4) {
                        if (r < M) {
                            int h = blockIdx.y * 2 + warp_n;
                            cfg.als[(size_t)r * 4 + h] = s;
                            if (dual) cfg.ald[(size_t)r * 4 + h] = s2;
                        }
                    } else {
                        atomicAdd(&sr1[rloc], s);
                        if (dual) atomicAdd(&sr2[rloc], s2);
                    }
                }
            }
        if (HALS == 1) {
            __syncthreads();
            for (int i = tid; i < 128; i += 256) {
                int r = bm + i;
                if (r < M) {
                    cfg.als[r] = sr1[i];
                    if (dual) cfg.ald[r] = sr2[i];
                }
            }
        }
    }
}

// ---------------- CSR build (batched over 3 edge types) ----------------
__global__ void k_zero(int* __restrict__ p, int n) {
    int i = blockIdx.x * blockDim.x + threadIdx.x;
    if (i < n) p[i] = 0;
}
__global__ void k_count3(const int* __restrict__ d0, const int* __restrict__ d1,
                         const int* __restrict__ d2, int E0, int E1, int E2,
                         int* __restrict__ cnt) {
    int t = blockIdx.y;
    const int* dst = (t == 0) ? d0 : (t == 1) ? d1 : d2;
    int E = (t == 0) ? E0 : (t == 1) ? E1 : E2;
    int i = blockIdx.x * 256 + threadIdx.x;
    if (i < E) atomicAdd(&cnt[t * NP + dst[i]], 1);
}
__global__ void __launch_bounds__(1024) k_scan3(int* __restrict__ cnt,
                                                int* __restrict__ rp, int n0, int n1, int n2) {
    int t = blockIdx.x;
    int n = (t == 0) ? n0 : (t == 1) ? n1 : n2;
    int* c = cnt + t * NP;
    int* rowptr = rp + t * (NP + 1);
    __shared__ int wsum[32];
    __shared__ int carry_s;
    int tid = threadIdx.x, lane = tid & 31, wid = tid >> 5;
    if (tid == 0) { carry_s = 0; rowptr[0] = 0; }
    __syncthreads();
    for (int base = 0; base < n; base += 4096) {
        int c0 = carry_s;
        int i0 = base + tid * 4;
        int v[4];
#pragma unroll
        for (int k = 0; k < 4; k++) {
            v[k] = (i0 + k < n) ? c[i0 + k] : 0;
            if (i0 + k < n) c[i0 + k] = 0;
        }
        int incl[4];
        incl[0] = v[0];
        incl[1] = incl[0] + v[1];
        incl[2] = incl[1] + v[2];
        incl[3] = incl[2] + v[3];
        int tot = incl[3];
        int x = tot;
#pragma unroll
        for (int o = 1; o < 32; o <<= 1) {
            int y = __shfl_up_sync(0xffffffffu, x, o);
            if (lane >= o) x += y;
        }
        if (lane == 31) wsum[wid] = x;
        __syncthreads();
        if (wid == 0) {
            int s = wsum[lane];
#pragma unroll
            for (int o = 1; o < 32; o <<= 1) {
                int y = __shfl_up_sync(0xffffffffu, s, o);
                if (lane >= o) s += y;
            }
            wsum[lane] = s;
        }
        __syncthreads();
        int excl = (x - tot) + (wid ? wsum[wid - 1] : 0) + c0;
#pragma unroll
        for (int k = 0; k < 4; k++) {
            int i = i0 + k;
            if (i < n) rowptr[i + 1] = excl + incl[k];
        }
        __syncthreads();
        if (tid == 0) carry_s = c0 + wsum[31];
        __syncthreads();
    }
}
__global__ void k_scatter3(const int* __restrict__ s0p, const int* __restrict__ s1p,
                           const int* __restrict__ s2p, const int* __restrict__ d0,
                           const int* __restrict__ d1, const int* __restrict__ d2,
                           int E0, int E1, int E2, const int* __restrict__ rp,
                           int* __restrict__ off, int* __restrict__ srcp) {
    int t = blockIdx.y;
    const int* src = (t == 0) ? s0p : (t == 1) ? s1p : s2p;
    const int* dst = (t == 0) ? d0 : (t == 1) ? d1 : d2;
    int E = (t == 0) ? E0 : (t == 1) ? E1 : E2;
    int i = blockIdx.x * 256 + threadIdx.x;
    if (i < E) {
        int d = dst[i];
        int p = rp[t * (NP + 1) + d] + atomicAdd(&off[t * NP + d], 1);
        srcp[t * EMAX + p] = src[i];
    }
}

// ---------------- all 9 Vd vectors in one launch ----------------
__global__ void k_makeV_all(const float* __restrict__ W_hid, const float* __restrict__ ad_hid,
                            const float* __restrict__ W_out, const float* __restrict__ ad_out,
                            float* __restrict__ V) {
    int b = blockIdx.x;
    int k = threadIdx.x;
    if (b < 6) {
        const float* W = W_hid + (size_t)b * 65536;
        const float* a = ad_hid + (size_t)b * 256;
        for (int h = 0; h < 4; h++) {
            float s = 0.f;
            for (int c = 0; c < 64; c++) s = fmaf(W[k * 256 + h * 64 + c], a[h * 64 + c], s);
            V[b * 1024 + k * 4 + h] = s;
        }
    } else {
        const float* W = W_out + (size_t)(b - 6) * 16384;
        const float* a = ad_out + (size_t)(b - 6) * 64;
        float s = 0.f;
        for (int c = 0; c < 64; c++) s = fmaf(W[k * 64 + c], a[c], s);
        V[b * 1024 + k] = s;
    }
}

// ---------------- per-segment softmax+gather accumulate, H=4 ----------------
__device__ __forceinline__ void edge4(const int* __restrict__ rowptr,
                                      const int* __restrict__ srcp,
                                      const float* __restrict__ als, const float* ad,
                                      const float* __restrict__ hsrc,
                                      float* __restrict__ alpha, int w, int lane, int c0,
                                      int c1, int hsel, float4& a0, float4& a1) {
    int s0 = rowptr[w], s1 = rowptr[w + 1];
    int deg = s1 - s0;
    if (deg <= 0) return;
    const float NINF = __int_as_float(0xff800000u);
    if (deg <= 32) {
        int sreg = (lane < deg) ? srcp[s0 + lane] : 0;
        float ex[4];
#pragma unroll
        for (int h = 0; h < 4; h++) {
            float e = NINF;
            if (lane < deg) {
                e = als[(size_t)sreg * 4 + h] + ad[h];
                e = e > 0.f ? e : NEG * e;
            }
            ex[h] = e;
        }
        float inv[4];
#pragma unroll
        for (int h = 0; h < 4; h++) {
            float m = ex[h];
#pragma unroll
            for (int o = 16; o; o >>= 1) m = fmaxf(m, __shfl_xor_sync(0xffffffffu, m, o));
            float v = (lane < deg) ? __expf(ex[h] - m) : 0.f;
            ex[h] = v;
#pragma unroll
            for (int o = 16; o; o >>= 1) v += __shfl_xor_sync(0xffffffffu, v, o);
            inv[h] = 1.f / (v + 1e-16f);
        }
        float inv0 = hsel ? inv[1] : inv[0];
        float inv1 = hsel ? inv[3] : inv[2];
        for (int i = 0; i < deg; i++) {
            int s = __shfl_sync(0xffffffffu, sreg, i);
            float e0 = __shfl_sync(0xffffffffu, ex[0], i);
            float e1 = __shfl_sync(0xffffffffu, ex[1], i);
            float e2 = __shfl_sync(0xffffffffu, ex[2], i);
            float e3 = __shfl_sync(0xffffffffu, ex[3], i);
            float w0 = (hsel ? e1 : e0) * inv0;
            float w1 = (hsel ? e3 : e2) * inv1;
            const float4* hr = (const float4*)(hsrc + (size_t)s * 256);
            float4 v0 = hr[c0], v1 = hr[c1];
            a0.x = fmaf(v0.x, w0, a0.x); a0.y = fmaf(v0.y, w0, a0.y);
            a0.z = fmaf(v0.z, w0, a0.z); a0.w = fmaf(v0.w, w0, a0.w);
            a1.x = fmaf(v1.x, w1, a1.x); a1.y = fmaf(v1.y, w1, a1.y);
            a1.z = fmaf(v1.z, w1, a1.z); a1.w = fmaf(v1.w, w1, a1.w);
        }
    } else {
        float mx[4], sm[4], inv[4];
#pragma unroll
        for (int h = 0; h < 4; h++) { mx[h] = NINF; sm[h] = 0.f; }
        for (int j = s0 + lane; j < s1; j += 32) {
            int s = srcp[j];
#pragma unroll
            for (int h = 0; h < 4; h++) {
                float e = als[(size_t)s * 4 + h] + ad[h];
                e = e > 0.f ? e : NEG * e;
                alpha[(size_t)j * 4 + h] = e;
                mx[h] = fmaxf(mx[h], e);
            }
        }
#pragma unroll
        for (int h = 0; h < 4; h++)
#pragma unroll
            for (int o = 16; o; o >>= 1)
                mx[h] = fmaxf(mx[h], __shfl_xor_sync(0xffffffffu, mx[h], o));
        for (int j = s0 + lane; j < s1; j += 32) {
#pragma unroll
            for (int h = 0; h < 4; h++) {
                float e2 = __expf(alpha[(size_t)j * 4 + h] - mx[h]);
                alpha[(size_t)j * 4 + h] = e2;
                sm[h] += e2;
            }
        }
#pragma unroll
        for (int h = 0; h < 4; h++) {
#pragma unroll
            for (int o = 16; o; o >>= 1) sm[h] += __shfl_xor_sync(0xffffffffu, sm[h], o);
            inv[h] = 1.f / (sm[h] + 1e-16f);
        }
        float inv0 = inv[hsel], inv1 = inv[hsel + 2];
        for (int j = s0; j < s1; j++) {
            int s = srcp[j];
            float4 al = *(const float4*)(alpha + (size_t)j * 4);
            const float4* hr = (const float4*)(hsrc + (size_t)s * 256);
            float4 v0 = hr[c0], v1 = hr[c1];
            float w0 = (hsel ? al.y : al.x) * inv0;
            float w1 = (hsel ? al.w : al.z) * inv1;
            a0.x = fmaf(v0.x, w0, a0.x); a0.y = fmaf(v0.y, w0, a0.y);
            a0.z = fmaf(v0.z, w0, a0.z); a0.w = fmaf(v0.w, w0, a0.w);
            a1.x = fmaf(v1.x, w1, a1.x); a1.y = fmaf(v1.y, w1, a1.y);
            a1.z = fmaf(v1.z, w1, a1.z); a1.w = fmaf(v1.w, w1, a1.w);
        }
    }
}

// ---------------- mega aggregation: one launch per hidden layer ----------------
__global__ void __launch_bounds__(256) k_lagg4(
    const int* __restrict__ rp0, const int* __restrict__ sp0, const int* __restrict__ rp1,
    const int* __restrict__ sp1, const int* __restrict__ rp2, const int* __restrict__ sp2,
    const float* __restrict__ h0, const float* __restrict__ h1, const float* __restrict__ h2,
    const float* __restrict__ als0, const float* __restrict__ als1,
    const float* __restrict__ als2, const float* __restrict__ ald2,
    const float* __restrict__ V0, const float* __restrict__ V1,
    const float* __restrict__ xp_in, const float* __restrict__ xd_in,
    const float* __restrict__ b0, const float* __restrict__ b1, const float* __restrict__ b2,
    float* __restrict__ alpha0, float* __restrict__ alpha1, float* __restrict__ alpha2,
    float* __restrict__ xp_out, float* __restrict__ xd_out, int act) {
    __shared__ float Vs0[1024];
    __shared__ float Vs1[1024];
    for (int i = threadIdx.x; i < 1024; i += 256) {
        Vs0[i] = V0[i];
        Vs1[i] = V1[i];
    }
    __syncthreads();
    int n = (blockIdx.x * 256 + threadIdx.x) >> 5;
    int lane = threadIdx.x & 31;
    if (n >= NP + ND) return;
    int c0 = lane, c1 = lane + 32, hsel = lane >> 4;
    float4 a0 = make_float4(0.f, 0.f, 0.f, 0.f), a1 = a0;
    float4 o0, o1;
    float4* orow;
    if (n < NP) {
        int w = n;
        const float* xr = xp_in + (size_t)w * 256;
        float p[4] = {0.f, 0.f, 0.f, 0.f};
#pragma unroll
        for (int tt = 0; tt < 8; tt++) {
            int k = lane + tt * 32;
            float x = xr[k];
#pragma unroll
            for (int h = 0; h < 4; h++) p[h] = fmaf(x, Vs0[k * 4 + h], p[h]);
        }
        float ad0[4];
#pragma unroll
        for (int h = 0; h < 4; h++) {
#pragma unroll
            for (int o = 16; o; o >>= 1) p[h] += __shfl_xor_sync(0xffffffffu, p[h], o);
            ad0[h] = p[h];
        }
        float ad2[4];
#pragma unroll
        for (int h = 0; h < 4; h++) ad2[h] = ald2[(size_t)w * 4 + h];
        edge4(rp0, sp0, als0, ad0, h0, alpha0, w, lane, c0, c1, hsel, a0, a1);
        edge4(rp2, sp2, als2, ad2, h2, alpha2, w, lane, c0, c1, hsel, a0, a1);
        const float4* B0 = (const float4*)b0;
        const float4* B2 = (const float4*)b2;
        float4 bb0 = B0[c0], bb1 = B0[c1];
        float4 t0 = B2[c0], t1 = B2[c1];
        bb0.x += t0.x; bb0.y += t0.y; bb0.z += t0.z; bb0.w += t0.w;
        bb1.x += t1.x; bb1.y += t1.y; bb1.z += t1.z; bb1.w += t1.w;
        o0 = make_float4(a0.x + bb0.x, a0.y + bb0.y, a0.z + bb0.z, a0.w + bb0.w);
        o1 = make_float4(a1.x + bb1.x, a1.y + bb1.y, a1.z + bb1.z, a1.w + bb1.w);
        orow = (float4*)(xp_out + (size_t)w * 256);
    } else {
        int w = n - NP;
        const float* xr = xd_in + (size_t)w * 256;
        float p[4] = {0.f, 0.f, 0.f, 0.f};
#pragma unroll
        for (int tt = 0; tt < 8; tt++) {
            int k = lane + tt * 32;
            float x = xr[k];
#pragma unroll
            for (int h = 0; h < 4; h++) p[h] = fmaf(x, Vs1[k * 4 + h], p[h]);
        }
        float ad1[4];
#pragma unroll
        for (int h = 0; h < 4; h++) {
#pragma unroll
            for (int o = 16; o; o >>= 1) p[h] += __shfl_xor_sync(0xffffffffu, p[h], o);
            ad1[h] = p[h];
        }
        edge4(rp1, sp1, als1, ad1, h1, alpha1, w, lane, c0, c1, hsel, a0, a1);
        const float4* B1 = (const float4*)b1;
        float4 bb0 = B1[c0], bb1 = B1[c1];
        o0 = make_float4(a0.x + bb0.x, a0.y + bb0.y, a0.z + bb0.z, a0.w + bb0.w);
        o1 = make_float4(a1.x + bb1.x, a1.y + bb1.y, a1.z + bb1.z, a1.w + bb1.w);
        orow = (float4*)(xd_out + (size_t)w * 256);
    }
    if (act) {
        o0.x = eluf(o0.x); o0.y = eluf(o0.y); o0.z = eluf(o0.z); o0.w = eluf(o0.w);
        o1.x = eluf(o1.x); o1.y = eluf(o1.y); o1.z = eluf(o1.z); o1.w = eluf(o1.w);
    }
    orow[c0] = o0;
    orow[c1] = o1;
}

// ---------------- per-segment softmax+gather, H=1, 64 cols ----------------
__device__ __forceinline__ void edge1(const int* __restrict__ rowptr,
                                      const int* __restrict__ srcp,
                                      const float* __restrict__ als, float ad,
                                      const float* __restrict__ hsrc,
                                      float* __restrict__ alpha, int w, int lane, float& a0,
                                      float& a1) {
    int s0 = rowptr[w], s1 = rowptr[w + 1];
    int deg = s1 - s0;
    if (deg <= 0) return;
    const float NINF = __int_as_float(0xff800000u);
    if (deg <= 32) {
        int sreg = (lane < deg) ? srcp[s0 + lane] : 0;
        float e = NINF;
        if (lane < deg) {
            e = als[sreg] + ad;
            e = e > 0.f ? e : NEG * e;
        }
        float m = e;
#pragma unroll
        for (int o = 16; o; o >>= 1) m = fmaxf(m, __shfl_xor_sync(0xffffffffu, m, o));
        float ex = (lane < deg) ? __expf(e - m) : 0.f;
        float sm = ex;
#pragma unroll
        for (int o = 16; o; o >>= 1) sm += __shfl_xor_sync(0xffffffffu, sm, o);
        float inv = 1.f / (sm + 1e-16f);
        for (int i = 0; i < deg; i++) {
            int s = __shfl_sync(0xffffffffu, sreg, i);
            float al = __shfl_sync(0xffffffffu, ex, i) * inv;
            const float* hr = hsrc + (size_t)s * 64;
            a0 = fmaf(hr[lane], al, a0);
            a1 = fmaf(hr[lane + 32], al, a1);
        }
    } else {
        float mx = NINF, sm = 0.f;
        for (int j = s0 + lane; j < s1; j += 32) {
            int s = srcp[j];
            float e = als[s] + ad;
            e = e > 0.f ? e : NEG * e;
            alpha[j] = e;
            mx = fmaxf(mx, e);
        }
#pragma unroll
        for (int o = 16; o; o >>= 1) mx = fmaxf(mx, __shfl_xor_sync(0xffffffffu, mx, o));
        for (int j = s0 + lane; j < s1; j += 32) {
            float ex = __expf(alpha[j] - mx);
            alpha[j] = ex;
            sm += ex;
        }
#pragma unroll
        for (int o = 16; o; o >>= 1) sm += __shfl_xor_sync(0xffffffffu, sm, o);
        float inv = 1.f / (sm + 1e-16f);
        for (int j = s0; j < s1; j++) {
            int s = srcp[j];
            float al = alpha[j] * inv;
            const float* hr = hsrc + (size_t)s * 64;
            a0 = fmaf(hr[lane], al, a0);
            a1 = fmaf(hr[lane + 32], al, a1);
        }
    }
}

// ---------------- mega aggregation for output layer ----------------
__global__ void __launch_bounds__(256) k_lagg1(
    const int* __restrict__ rp0, const int* __restrict__ sp0, const int* __restrict__ rp1,
    const int* __restrict__ sp1, const int* __restrict__ rp2, const int* __restrict__ sp2,
    const float* __restrict__ h0, const float* __restrict__ h1, const float* __restrict__ h2,
    const float* __restrict__ als0, const float* __restrict__ als1,
    const float* __restrict__ als2, const float* __restrict__ ald2,
    const float* __restrict__ V0, const float* __restrict__ V1,
    const float* __restrict__ xp_in, const float* __restrict__ xd_in,
    const float* __restrict__ b0, const float* __restrict__ b1, const float* __restrict__ b2,
    float* __restrict__ alpha0, float* __restrict__ alpha1, float* __restrict__ alpha2,
    float* __restrict__ op, float* __restrict__ od) {
    __shared__ float Vs0[256];
    __shared__ float Vs1[256];
    for (int i = threadIdx.x; i < 256; i += 256) {
        Vs0[i] = V0[i];
        Vs1[i] = V1[i];
    }
    __syncthreads();
    int n = (blockIdx.x * 256 + threadIdx.x) >> 5;
    int lane = threadIdx.x & 31;
    if (n >= NP + ND) return;
    float a0 = 0.f, a1 = 0.f;
    float* orow;
    float bb0, bb1;
    if (n < NP) {
        int w = n;
        const float* xr = xp_in + (size_t)w * 256;
        float p = 0.f;
#pragma unroll
        for (int tt = 0; tt < 8; tt++) {
            int k = lane + tt * 32;
            p = fmaf(xr[k], Vs0[k], p);
        }
#pragma unroll
        for (int o = 16; o; o >>= 1) p += __shfl_xor_sync(0xffffffffu, p, o);
        edge1(rp0, sp0, als0, p, h0, alpha0, w, lane, a0, a1);
        edge1(rp2, sp2, als2, ald2[w], h2, alpha2, w, lane, a0, a1);
        bb0 = b0[lane] + b2[lane];
        bb1 = b0[lane + 32] + b2[lane + 32];
        orow = op + (size_t)w * 64;
    } else {
        int w = n - NP;
        const float* xr = xd_in + (size_t)w * 256;
        float p = 0.f;
#pragma unroll
        for (int tt = 0; tt < 8; tt++) {
            int k = lane + tt * 32;
            p = fmaf(xr[k], Vs1[k], p);
        }
#pragma unroll
        for (int o = 16; o; o >>= 1) p += __shfl_xor_sync(0xffffffffu, p, o);
        edge1(rp1, sp1, als1, p, h1, alpha1, w, lane, a0, a1);
        bb0 = b1[lane];
        bb1 = b1[lane + 32];
        orow = od + (size_t)w * 64;
    }
    orow[lane] = a0 + bb0;
    orow[lane + 32] = a1 + bb1;
}

// =====================================================================
extern "C" void kernel_launch(void* const* d_in, const int* in_sizes, int n_in,
                              void* d_out, int out_size) {
    const float* x_drug = (const float*)d_in[0];
    const float* x_prot = (const float*)d_in[1];
    const int* srcA[3] = {(const int*)d_in[2], (const int*)d_in[4], (const int*)d_in[6]};
    const int* dstA[3] = {(const int*)d_in[3], (const int*)d_in[5], (const int*)d_in[7]};
    const float* linW_d = (const float*)d_in[8];
    const float* linb_d = (const float*)d_in[9];
    const float* linW_p = (const float*)d_in[10];
    const float* linb_p = (const float*)d_in[11];
    const float* W_hid = (const float*)d_in[12];
    const float* as_hid = (const float*)d_in[13];
    const float* ad_hid = (const float*)d_in[14];
    const float* b_hid = (const float*)d_in[15];
    const float* W_out = (const float*)d_in[16];
    const float* as_out = (const float*)d_in[17];
    const float* ad_out = (const float*)d_in[18];
    const float* b_out = (const float*)d_in[19];
    float* outp = (float*)d_out;

    int E[3] = {in_sizes[2], in_sizes[4], in_sizes[6]};
    int maxE = E[0] > E[1] ? E[0] : E[1];
    if (E[2] > maxE) maxE = E[2];

    float *xdb, *xpb, *hb, *alpha, *als, *ald, *V;
    int *rp, *sp, *cnt;
    __nv_bfloat16 *whi, *wlo;
    cudaGetSymbolAddress((void**)&xdb, g_xd);
    cudaGetSymbolAddress((void**)&xpb, g_xp);
    cudaGetSymbolAddress((void**)&hb, g_h);
    cudaGetSymbolAddress((void**)&alpha, g_alpha);
    cudaGetSymbolAddress((void**)&als, g_als);
    cudaGetSymbolAddress((void**)&ald, g_ald);
    cudaGetSymbolAddress((void**)&V, g_V);
    cudaGetSymbolAddress((void**)&rp, g_rowptr);
    cudaGetSymbolAddress((void**)&sp, g_srcp);
    cudaGetSymbolAddress((void**)&cnt, g_cnt);
    cudaGetSymbolAddress((void**)&whi, g_whi);
    cudaGetSymbolAddress((void**)&wlo, g_wlo);

    float* xd[2] = {xdb, xdb + (size_t)ND * HIDW};
    float* xp[2] = {xpb, xpb + (size_t)NP * HIDW};
    float* h0 = hb;
    float* h1 = hb + (size_t)NP * HIDW;
    float* h2 = hb + 2 * (size_t)NP * HIDW;
    int* rowptr[3] = {rp, rp + (NP + 1), rp + 2 * (NP + 1)};
    int* srcp[3] = {sp, sp + EMAX, sp + 2 * EMAX};
    float* als0 = als;
    float* als1 = als + (size_t)NP * 4;
    float* als2 = als + 2 * (size_t)NP * 4;
    float* alpha0 = alpha;
    float* alpha1 = alpha + (size_t)EMAX * 4;
    float* alpha2 = alpha + 2 * (size_t)EMAX * 4;

    const int SM128 = 2048 + 4 * (128 * 40 * 2) + 4 * (128 * 40 * 2);  // 83968
    const int SM64 = 2048 + 4 * (128 * 40 * 2) + 4 * (64 * 40 * 2);    // 63488
    cudaFuncSetAttribute(k_mma<128, true, true, 0>,
                         cudaFuncAttributeMaxDynamicSharedMemorySize, SM128);
    cudaFuncSetAttribute(k_mma<128, false, false, 4>,
                         cudaFuncAttributeMaxDynamicSharedMemorySize, SM128);
    cudaFuncSetAttribute(k_mma<64, false, false, 1>,
                         cudaFuncAttributeMaxDynamicSharedMemorySize, SM64);

    size_t o_lind = 0;
    size_t o_linp = 32768;
    size_t o_hid0 = 98304;
    size_t o_out0 = 491520;

    int ebx = (maxE + 255) / 256;
    int gx128 = (NP + 127) / 128;

    // L0: zero cnt
    k_zero<<<(3 * NP + 255) / 256, 256>>>(cnt, 3 * NP);
    // L1: count
    {
        dim3 gc(ebx, 3);
        k_count3<<<gc, 256>>>(dstA[0], dstA[1], dstA[2], E[0], E[1], E[2], cnt);
    }
    // L2: weight split
    {
        dim3 gw(256, 11);
        k_splitW_all<<<gw, 256>>>(linW_d, linW_p, W_hid, W_out, whi, wlo);
    }
    // L3: input projections (batched z=2) — ncu capture target
    {
        GemmCfg3 P{};
        P.c[0] = {x_drug, whi + o_lind, wlo + o_lind, linb_d, nullptr, nullptr,
                  xd[0], nullptr, nullptr, ND, 128};
        P.c[1] = {x_prot, whi + o_linp, wlo + o_linp, linb_p, nullptr, nullptr,
                  xp[0], nullptr, nullptr, NP, 256};
        P.c[2] = P.c[1];
        dim3 gg(gx128, 2, 2);
        k_mma<128, true, true, 0><<<gg, 256, SM128>>>(P);
    }
    // L4: scan (+re-zero cnt)
    k_scan3<<<3, 1024>>>(cnt, rp, NP, ND, NP);
    // L5: scatter
    {
        dim3 gs(ebx, 3);
        k_scatter3<<<gs, 256>>>(srcA[0], srcA[1], srcA[2], dstA[0], dstA[1], dstA[2], E[0],
                                E[1], E[2], rp, cnt, sp);
    }
    // L6: V vectors
    k_makeV_all<<<9, 256>>>(W_hid, ad_hid, W_out, ad_out, V);

    int cur = 0, nxt = 1;
    int naggb = (NP + ND + 7) / 8;

    // ---- hidden layers ----
    for (int l = 0; l < 2; l++) {
        int i0 = l * 3 + 0, i1 = l * 3 + 1, i2 = l * 3 + 2;
        {
            GemmCfg3 P{};
            P.c[0] = {xd[cur], whi + o_hid0 + (size_t)i0 * 65536,
                      wlo + o_hid0 + (size_t)i0 * 65536, nullptr,
                      as_hid + (size_t)i0 * 256, nullptr, h0, als0, nullptr, ND, 256};
            P.c[1] = {xp[cur], whi + o_hid0 + (size_t)i1 * 65536,
                      wlo + o_hid0 + (size_t)i1 * 65536, nullptr,
                      as_hid + (size_t)i1 * 256, nullptr, h1, als1, nullptr, NP, 256};
            P.c[2] = {xp[cur], whi + o_hid0 + (size_t)i2 * 65536,
                      wlo + o_hid0 + (size_t)i2 * 65536, nullptr,
                      as_hid + (size_t)i2 * 256, ad_hid + (size_t)i2 * 256, h2, als2, ald,
                      NP, 256};
            dim3 gg(gx128, 2, 3);
            k_mma<128, false, false, 4><<<gg, 256, SM128>>>(P);
        }
        k_lagg4<<<naggb, 256>>>(rowptr[0], srcp[0], rowptr[1], srcp[1], rowptr[2], srcp[2],
                                h0, h1, h2, als0, als1, als2, ald, V + (size_t)i0 * 1024,
                                V + (size_t)i1 * 1024, xp[cur], xd[cur],
                                b_hid + (size_t)i0 * 256, b_hid + (size_t)i1 * 256,
                                b_hid + (size_t)i2 * 256, alpha0, alpha1, alpha2, xp[nxt],
                                xd[nxt], 1);
        cur = nxt;
        nxt = 1 - nxt;
    }

    // ---- output layer ----
    float* od = outp;
    float* op = outp + (size_t)ND * OUTC;
    {
        GemmCfg3 P{};
        P.c[0] = {xd[cur], whi + o_out0, wlo + o_out0, nullptr, as_out, nullptr,
                  h0, als0, nullptr, ND, 256};
        P.c[1] = {xp[cur], whi + o_out0 + 16384, wlo + o_out0 + 16384, nullptr,
                  as_out + OUTC, nullptr, h1, als1, nullptr, NP, 256};
        P.c[2] = {xp[cur], whi + o_out0 + 2 * 16384, wlo + o_out0 + 2 * 16384, nullptr,
                  as_out + 2 * OUTC, ad_out + 2 * OUTC, h2, als2, ald, NP, 256};
        dim3 gg(gx128, 1, 3);
        k_mma<64, false, false, 1><<<gg, 256, SM64>>>(P);
    }
    k_lagg1<<<naggb, 256>>>(rowptr[0], srcp[0], rowptr[1], srcp[1], rowptr[2], srcp[2], h0,
                            h1, h2, als0, als1, als2, ald, V + 6 * 1024, V + 7 * 1024,
                            xp[cur], xd[cur], b_out + 0 * OUTC, b_out + 1 * OUTC,
                            b_out + 2 * OUTC, alpha0, alpha1, alpha2, op, od);

    (void)n_in;
    (void)out_size;
}